// round 1
// baseline (speedup 1.0000x reference)
#include <cuda_runtime.h>
#include <math.h>

#define HW 4096     // 64*64
#define BATCH 8

// ---------------- scratch (static device globals; no allocation) ----------------
__device__ float g_Si  [BATCH*3*HW];
__device__ float g_h1  [BATCH*64*HW];
__device__ float g_h2  [BATCH*64*HW];
__device__ float g_h3  [BATCH*64*HW];
__device__ float g_feat[BATCH*64*HW];
__device__ float g_off [BATCH*36*HW];   // channels 0..17 = offset, 18..35 = dc_off
__device__ float g_mask[BATCH*9*HW];

__device__ float g_Wt1 [3*9*64];
__device__ float g_Wt2 [64*9*64];
__device__ float g_Wt3 [64*9*64];
__device__ float g_Wt36[64*9*36];
__device__ float g_Wtdc[64*9*64];
__device__ float g_WtF [256*9*256];
__device__ float g_b36 [36];

// ---------------- weight transpose: src[O][CIN][9] -> dst[(c*9+k)*Otot + oOff + o] ----
__global__ void transpose_weight(const float* __restrict__ src, float* __restrict__ dst,
                                 int O, int CIN, int oOff, int Otot) {
    int i = blockIdx.x * blockDim.x + threadIdx.x;
    int total = O * CIN * 9;
    if (i >= total) return;
    int k = i % 9;
    int c = (i / 9) % CIN;
    int o = i / (9 * CIN);
    dst[(c * 9 + k) * Otot + oOff + o] = src[i];
}

__global__ void concat_bias36(const float* __restrict__ a, const float* __restrict__ b,
                              float* __restrict__ dst) {
    int i = threadIdx.x;
    if (i < 18) dst[i] = a[i];
    else if (i < 36) dst[i] = b[i - 18];
}

// ---------------- bilinear resize 128x128 -> 64x64, align_corners=True --------------
__global__ void resize_kernel(const float* __restrict__ S, float* __restrict__ Si) {
    int i = blockIdx.x * blockDim.x + threadIdx.x;
    if (i >= BATCH * 3 * HW) return;
    int x = i & 63;
    int y = (i >> 6) & 63;
    int bc = i >> 12;
    const float scale = 127.0f / 63.0f;
    float ys = y * scale, xs = x * scale;
    float fy = floorf(ys), fx = floorf(xs);
    int y0 = (int)fy, x0 = (int)fx;
    int y1 = min(y0 + 1, 127), x1 = min(x0 + 1, 127);
    float wy = ys - fy, wx = xs - fx;
    const float* p = S + (size_t)bc * 128 * 128;
    float v = p[y0 * 128 + x0] * (1.0f - wy) * (1.0f - wx)
            + p[y0 * 128 + x1] * (1.0f - wy) * wx
            + p[y1 * 128 + x0] * wy * (1.0f - wx)
            + p[y1 * 128 + x1] * wy * wx;
    Si[i] = v;
}

// ---------------- 1x1 conv + sigmoid: feat[b,64,hw] -> mask[b,9,hw] -----------------
__global__ void mask_kernel(const float* __restrict__ feat, const float* __restrict__ mw,
                            const float* __restrict__ mb, float* __restrict__ mask) {
    int i = blockIdx.x * blockDim.x + threadIdx.x;
    if (i >= BATCH * HW) return;
    int b = i >> 12;
    int pix = i & (HW - 1);
    float acc[9];
#pragma unroll
    for (int o = 0; o < 9; o++) acc[o] = __ldg(mb + o);
    const float* fp = feat + (size_t)b * 64 * HW + pix;
    for (int c = 0; c < 64; c++) {
        float v = __ldg(fp + c * HW);
#pragma unroll
        for (int o = 0; o < 9; o++) acc[o] += v * __ldg(mw + o * 64 + c);
    }
#pragma unroll
    for (int o = 0; o < 9; o++)
        mask[((size_t)b * 9 + o) * HW + pix] = 1.0f / (1.0f + expf(-acc[o]));
}

// ---------------- generic fused (deform-)conv3x3 as implicit GEMM -------------------
// inp: [B][CIN][4096]; Wt: [(c*9+k)][O]; out: [B][O][4096]
// offs (nullable): per-batch stride offBS; channel 2k=dy, 2k+1=dx
// mask (nullable): per-batch stride maskBS; channel k
// EPI: 0=none, 1=relu((acc+b)*s+o), 2=acc+b
template <int CIN, int O, int PG, int EPI>
__global__ void __launch_bounds__(O * PG)
dconv_gemm(const float* __restrict__ inp, const float* __restrict__ Wt,
           const float* __restrict__ offs, int offBS,
           const float* __restrict__ msk, int maskBS,
           const float* __restrict__ e_b, const float* __restrict__ e_s,
           const float* __restrict__ e_o, float* __restrict__ out) {
    constexpr int PT = 64;                 // pixels per block
    constexpr int PPT = PT / PG;           // pixels per thread
    constexpr int THREADS = O * PG;

    __shared__ int   s_i[9 * PT][4];
    __shared__ float s_w[9 * PT][4];
    __shared__ __align__(16) float s_t[9 * PT];

    const int b = blockIdx.y;
    const int tile = blockIdx.x;
    const int tid = threadIdx.x;
    const int o = tid % O;
    const int pg = tid / O;
    const int pbase = pg * PPT;

    // ---- precompute bilinear corner indices & weights per (k, pixel) ----
    for (int e = tid; e < 9 * PT; e += THREADS) {
        int k = e / PT;
        int p = e % PT;
        int pix = tile * PT + p;
        int y = pix >> 6, xx = pix & 63;
        float py = (float)(y - 1 + k / 3);
        float px = (float)(xx - 1 + k % 3);
        if (offs) {
            py += offs[(size_t)b * offBS + (2 * k) * HW + pix];
            px += offs[(size_t)b * offBS + (2 * k + 1) * HW + pix];
        }
        float m = 1.0f;
        if (msk) m = msk[(size_t)b * maskBS + k * HW + pix];
        float fy = floorf(py), fx = floorf(px);
        int iy = (int)fy, ix = (int)fx;
        float ay = py - fy, ax = px - fx;
        bool vy0 = (iy >= 0) && (iy < 64);
        bool vy1 = (iy + 1 >= 0) && (iy + 1 < 64);
        bool vx0 = (ix >= 0) && (ix < 64);
        bool vx1 = (ix + 1 >= 0) && (ix + 1 < 64);
        int cy0 = min(max(iy, 0), 63), cy1 = min(max(iy + 1, 0), 63);
        int cx0 = min(max(ix, 0), 63), cx1 = min(max(ix + 1, 0), 63);
        s_i[e][0] = cy0 * 64 + cx0;
        s_i[e][1] = cy0 * 64 + cx1;
        s_i[e][2] = cy1 * 64 + cx0;
        s_i[e][3] = cy1 * 64 + cx1;
        s_w[e][0] = (vy0 && vx0) ? (1.0f - ay) * (1.0f - ax) * m : 0.0f;
        s_w[e][1] = (vy0 && vx1) ? (1.0f - ay) * ax * m : 0.0f;
        s_w[e][2] = (vy1 && vx0) ? ay * (1.0f - ax) * m : 0.0f;
        s_w[e][3] = (vy1 && vx1) ? ay * ax * m : 0.0f;
    }

    float acc[PPT];
#pragma unroll
    for (int j = 0; j < PPT; j++) acc[j] = 0.0f;

    __syncthreads();

    for (int c = 0; c < CIN; c++) {
        const float* xc = inp + ((size_t)b * CIN + c) * HW;
        // gather s-slice for this input channel
        for (int e = tid; e < 9 * PT; e += THREADS) {
            float v = s_w[e][0] * __ldg(xc + s_i[e][0])
                    + s_w[e][1] * __ldg(xc + s_i[e][1])
                    + s_w[e][2] * __ldg(xc + s_i[e][2])
                    + s_w[e][3] * __ldg(xc + s_i[e][3]);
            s_t[e] = v;
        }
        __syncthreads();

        float wv[9];
#pragma unroll
        for (int k = 0; k < 9; k++) wv[k] = __ldg(Wt + (c * 9 + k) * O + o);

#pragma unroll
        for (int k = 0; k < 9; k++) {
            const float4* sp = reinterpret_cast<const float4*>(s_t + k * PT + pbase);
#pragma unroll
            for (int j4 = 0; j4 < PPT / 4; j4++) {
                float4 sv = sp[j4];
                acc[j4 * 4 + 0] += wv[k] * sv.x;
                acc[j4 * 4 + 1] += wv[k] * sv.y;
                acc[j4 * 4 + 2] += wv[k] * sv.z;
                acc[j4 * 4 + 3] += wv[k] * sv.w;
            }
        }
        __syncthreads();
    }

    // epilogue
    float bb = 0.0f, ssc = 1.0f, oof = 0.0f;
    if (EPI == 1) { bb = __ldg(e_b + o); ssc = __ldg(e_s + o); oof = __ldg(e_o + o); }
    if (EPI == 2) { bb = __ldg(e_b + o); }
    float* op = out + ((size_t)b * O + o) * HW + tile * PT + pbase;
#pragma unroll
    for (int j = 0; j < PPT; j++) {
        float v = acc[j];
        if (EPI == 1) v = fmaxf((v + bb) * ssc + oof, 0.0f);
        else if (EPI == 2) v = v + bb;
        op[j] = v;
    }
}

// ---------------- host launcher ------------------------------------------------------
extern "C" void kernel_launch(void* const* d_in, const int* in_sizes, int n_in,
                              void* d_out, int out_size) {
    const float* x       = (const float*)d_in[0];   // [8,256,64,64]
    const float* S       = (const float*)d_in[1];   // [8,3,128,128]
    const float* sp_w1   = (const float*)d_in[2];
    const float* sp_b1   = (const float*)d_in[3];
    const float* sp_s1   = (const float*)d_in[4];
    const float* sp_o1   = (const float*)d_in[5];
    const float* sp_w2   = (const float*)d_in[6];
    const float* sp_b2   = (const float*)d_in[7];
    const float* sp_s2   = (const float*)d_in[8];
    const float* sp_o2   = (const float*)d_in[9];
    const float* sp_w3   = (const float*)d_in[10];
    const float* sp_b3   = (const float*)d_in[11];
    const float* sp_s3   = (const float*)d_in[12];
    const float* sp_o3   = (const float*)d_in[13];
    const float* off_w   = (const float*)d_in[14];
    const float* off_b   = (const float*)d_in[15];
    const float* dcoff_w = (const float*)d_in[16];
    const float* dcoff_b = (const float*)d_in[17];
    const float* dc_w    = (const float*)d_in[18];
    const float* m_w     = (const float*)d_in[19];
    const float* m_b     = (const float*)d_in[20];
    const float* weight  = (const float*)d_in[21];
    const float* bias    = (const float*)d_in[22];

    float *Si, *h1, *h2, *h3, *feat, *off, *mask;
    float *Wt1, *Wt2, *Wt3, *Wt36, *Wtdc, *WtF, *b36;
    cudaGetSymbolAddress((void**)&Si,   g_Si);
    cudaGetSymbolAddress((void**)&h1,   g_h1);
    cudaGetSymbolAddress((void**)&h2,   g_h2);
    cudaGetSymbolAddress((void**)&h3,   g_h3);
    cudaGetSymbolAddress((void**)&feat, g_feat);
    cudaGetSymbolAddress((void**)&off,  g_off);
    cudaGetSymbolAddress((void**)&mask, g_mask);
    cudaGetSymbolAddress((void**)&Wt1,  g_Wt1);
    cudaGetSymbolAddress((void**)&Wt2,  g_Wt2);
    cudaGetSymbolAddress((void**)&Wt3,  g_Wt3);
    cudaGetSymbolAddress((void**)&Wt36, g_Wt36);
    cudaGetSymbolAddress((void**)&Wtdc, g_Wtdc);
    cudaGetSymbolAddress((void**)&WtF,  g_WtF);
    cudaGetSymbolAddress((void**)&b36,  g_b36);

    // weight prep (layout [c][k][o])
    auto tgrid = [](int n) { return (n + 255) / 256; };
    transpose_weight<<<tgrid(64 * 3 * 9), 256>>>(sp_w1, Wt1, 64, 3, 0, 64);
    transpose_weight<<<tgrid(64 * 64 * 9), 256>>>(sp_w2, Wt2, 64, 64, 0, 64);
    transpose_weight<<<tgrid(64 * 64 * 9), 256>>>(sp_w3, Wt3, 64, 64, 0, 64);
    transpose_weight<<<tgrid(18 * 64 * 9), 256>>>(off_w, Wt36, 18, 64, 0, 36);
    transpose_weight<<<tgrid(18 * 64 * 9), 256>>>(dcoff_w, Wt36, 18, 64, 18, 36);
    transpose_weight<<<tgrid(64 * 64 * 9), 256>>>(dc_w, Wtdc, 64, 64, 0, 64);
    transpose_weight<<<tgrid(256 * 256 * 9), 256>>>(weight, WtF, 256, 256, 0, 256);
    concat_bias36<<<1, 36>>>(off_b, dcoff_b, b36);

    // stage 0: resize
    resize_kernel<<<(BATCH * 3 * HW + 255) / 256, 256>>>(S, Si);

    dim3 grid(HW / 64, BATCH);

    // spatial projector (3 convs, BN-fold + ReLU)
    dconv_gemm<3, 64, 4, 1><<<grid, 256>>>(Si, Wt1, nullptr, 0, nullptr, 0,
                                           sp_b1, sp_s1, sp_o1, h1);
    dconv_gemm<64, 64, 4, 1><<<grid, 256>>>(h1, Wt2, nullptr, 0, nullptr, 0,
                                            sp_b2, sp_s2, sp_o2, h2);
    dconv_gemm<64, 64, 4, 1><<<grid, 256>>>(h2, Wt3, nullptr, 0, nullptr, 0,
                                            sp_b3, sp_s3, sp_o3, h3);

    // both offset convs fused (36 output channels)
    dconv_gemm<64, 36, 8, 2><<<grid, 288>>>(h3, Wt36, nullptr, 0, nullptr, 0,
                                            b36, nullptr, nullptr, off);

    // DCNv1: feat = deform_conv(h3, dc_off, dc_w) (no bias, no mask)
    dconv_gemm<64, 64, 4, 0><<<grid, 256>>>(h3, Wtdc, off + 18 * HW, 36 * HW,
                                            nullptr, 0, nullptr, nullptr, nullptr, feat);

    // mask = sigmoid(conv1x1(feat))
    mask_kernel<<<(BATCH * HW + 255) / 256, 256>>>(feat, m_w, m_b, mask);

    // final modulated DCNv2: 256 -> 256
    dconv_gemm<256, 256, 1, 2><<<grid, 256>>>(x, WtF, off, 36 * HW,
                                              mask, 9 * HW, bias, nullptr, nullptr,
                                              (float*)d_out);
}

// round 2
// speedup vs baseline: 2.0144x; 2.0144x over previous
#include <cuda_runtime.h>
#include <math.h>

#define HW 4096     // 64*64
#define BATCH 8

// ---------------- scratch (static device globals; no allocation) ----------------
__device__ float g_Si  [BATCH*3*HW];
__device__ float g_h1  [BATCH*64*HW];
__device__ float g_h2  [BATCH*64*HW];
__device__ float g_h3  [BATCH*64*HW];
__device__ float g_feat[BATCH*64*HW];
__device__ float g_off [BATCH*36*HW];   // channels 0..17 = offset, 18..35 = dc_off
__device__ float g_mask[BATCH*9*HW];

__device__ float g_Wt1 [3*9*64];
__device__ float g_Wt2 [64*9*64];
__device__ float g_Wt3 [64*9*64];
__device__ float g_Wt36[64*9*36];
__device__ float g_Wtdc[64*9*64];
__device__ float g_WtF [256*9*256];     // fragment-packed tf32 weights for final layer
__device__ float g_b36 [36];

// ---------------- helpers ------------------------------------------------------------
__device__ __forceinline__ unsigned f2tf32(float f) {
    unsigned u;
    asm("cvt.rna.tf32.f32 %0, %1;" : "=r"(u) : "f"(f));
    return u;
}

// ---------------- weight transpose: src[O][CIN][9] -> dst[(c*9+k)*Otot + oOff + o] ----
__global__ void transpose_weight(const float* __restrict__ src, float* __restrict__ dst,
                                 int O, int CIN, int oOff, int Otot) {
    int i = blockIdx.x * blockDim.x + threadIdx.x;
    int total = O * CIN * 9;
    if (i >= total) return;
    int k = i % 9;
    int c = (i / 9) % CIN;
    int o = i / (9 * CIN);
    dst[(c * 9 + k) * Otot + oOff + o] = src[i];
}

// ---- final-layer weight prep into mma fragment layout (tf32-rounded) ----------------
// src: weight[o][c][kk] (o<256, K=c*9+kk < 2304)
// dst float index: (((kc*16 + ot)*32 + lane)*4 + r)
//   a0: row=lane/4,   col=lane%4   (r=0)
//   a1: row=lane/4+8, col=lane%4   (r=1)
//   a2: row=lane/4,   col=lane%4+4 (r=2)
//   a3: row=lane/4+8, col=lane%4+4 (r=3)
__global__ void prep_final_w(const float* __restrict__ w, float* __restrict__ dst) {
    int i = blockIdx.x * blockDim.x + threadIdx.x;
    if (i >= 256 * 2304) return;
    int K = i % 2304;
    int o = i / 2304;
    int kc = K >> 3, kp = K & 7;
    int ot = o >> 4, om = o & 15;
    int lane = (om & 7) * 4 + (kp & 3);
    int r = (om >> 3) + ((kp >> 2) << 1);
    dst[(((size_t)kc * 16 + ot) * 32 + lane) * 4 + r] = __uint_as_float(f2tf32(w[i]));
}

__global__ void concat_bias36(const float* __restrict__ a, const float* __restrict__ b,
                              float* __restrict__ dst) {
    int i = threadIdx.x;
    if (i < 18) dst[i] = a[i];
    else if (i < 36) dst[i] = b[i - 18];
}

// ---------------- bilinear resize 128x128 -> 64x64, align_corners=True --------------
__global__ void resize_kernel(const float* __restrict__ S, float* __restrict__ Si) {
    int i = blockIdx.x * blockDim.x + threadIdx.x;
    if (i >= BATCH * 3 * HW) return;
    int x = i & 63;
    int y = (i >> 6) & 63;
    int bc = i >> 12;
    const float scale = 127.0f / 63.0f;
    float ys = y * scale, xs = x * scale;
    float fy = floorf(ys), fx = floorf(xs);
    int y0 = (int)fy, x0 = (int)fx;
    int y1 = min(y0 + 1, 127), x1 = min(x0 + 1, 127);
    float wy = ys - fy, wx = xs - fx;
    const float* p = S + (size_t)bc * 128 * 128;
    float v = p[y0 * 128 + x0] * (1.0f - wy) * (1.0f - wx)
            + p[y0 * 128 + x1] * (1.0f - wy) * wx
            + p[y1 * 128 + x0] * wy * (1.0f - wx)
            + p[y1 * 128 + x1] * wy * wx;
    Si[i] = v;
}

// ---------------- 1x1 conv + sigmoid: feat[b,64,hw] -> mask[b,9,hw] -----------------
__global__ void mask_kernel(const float* __restrict__ feat, const float* __restrict__ mw,
                            const float* __restrict__ mb, float* __restrict__ mask) {
    int i = blockIdx.x * blockDim.x + threadIdx.x;
    if (i >= BATCH * HW) return;
    int b = i >> 12;
    int pix = i & (HW - 1);
    float acc[9];
#pragma unroll
    for (int o = 0; o < 9; o++) acc[o] = __ldg(mb + o);
    const float* fp = feat + (size_t)b * 64 * HW + pix;
    for (int c = 0; c < 64; c++) {
        float v = __ldg(fp + c * HW);
#pragma unroll
        for (int o = 0; o < 9; o++) acc[o] += v * __ldg(mw + o * 64 + c);
    }
#pragma unroll
    for (int o = 0; o < 9; o++)
        mask[((size_t)b * 9 + o) * HW + pix] = 1.0f / (1.0f + expf(-acc[o]));
}

// ---------------- generic fused (deform-)conv3x3 as implicit GEMM (fp32) -------------
template <int CIN, int O, int PG, int EPI>
__global__ void __launch_bounds__(O * PG)
dconv_gemm(const float* __restrict__ inp, const float* __restrict__ Wt,
           const float* __restrict__ offs, int offBS,
           const float* __restrict__ msk, int maskBS,
           const float* __restrict__ e_b, const float* __restrict__ e_s,
           const float* __restrict__ e_o, float* __restrict__ out) {
    constexpr int PT = 64;
    constexpr int PPT = PT / PG;
    constexpr int THREADS = O * PG;

    __shared__ int   s_i[9 * PT][4];
    __shared__ float s_w[9 * PT][4];
    __shared__ __align__(16) float s_t[9 * PT];

    const int b = blockIdx.y;
    const int tile = blockIdx.x;
    const int tid = threadIdx.x;
    const int o = tid % O;
    const int pg = tid / O;
    const int pbase = pg * PPT;

    for (int e = tid; e < 9 * PT; e += THREADS) {
        int k = e / PT;
        int p = e % PT;
        int pix = tile * PT + p;
        int y = pix >> 6, xx = pix & 63;
        float py = (float)(y - 1 + k / 3);
        float px = (float)(xx - 1 + k % 3);
        if (offs) {
            py += offs[(size_t)b * offBS + (2 * k) * HW + pix];
            px += offs[(size_t)b * offBS + (2 * k + 1) * HW + pix];
        }
        float m = 1.0f;
        if (msk) m = msk[(size_t)b * maskBS + k * HW + pix];
        float fy = floorf(py), fx = floorf(px);
        int iy = (int)fy, ix = (int)fx;
        float ay = py - fy, ax = px - fx;
        bool vy0 = (iy >= 0) && (iy < 64);
        bool vy1 = (iy + 1 >= 0) && (iy + 1 < 64);
        bool vx0 = (ix >= 0) && (ix < 64);
        bool vx1 = (ix + 1 >= 0) && (ix + 1 < 64);
        int cy0 = min(max(iy, 0), 63), cy1 = min(max(iy + 1, 0), 63);
        int cx0 = min(max(ix, 0), 63), cx1 = min(max(ix + 1, 0), 63);
        s_i[e][0] = cy0 * 64 + cx0;
        s_i[e][1] = cy0 * 64 + cx1;
        s_i[e][2] = cy1 * 64 + cx0;
        s_i[e][3] = cy1 * 64 + cx1;
        s_w[e][0] = (vy0 && vx0) ? (1.0f - ay) * (1.0f - ax) * m : 0.0f;
        s_w[e][1] = (vy0 && vx1) ? (1.0f - ay) * ax * m : 0.0f;
        s_w[e][2] = (vy1 && vx0) ? ay * (1.0f - ax) * m : 0.0f;
        s_w[e][3] = (vy1 && vx1) ? ay * ax * m : 0.0f;
    }

    float acc[PPT];
#pragma unroll
    for (int j = 0; j < PPT; j++) acc[j] = 0.0f;

    __syncthreads();

    for (int c = 0; c < CIN; c++) {
        const float* xc = inp + ((size_t)b * CIN + c) * HW;
        for (int e = tid; e < 9 * PT; e += THREADS) {
            float v = s_w[e][0] * __ldg(xc + s_i[e][0])
                    + s_w[e][1] * __ldg(xc + s_i[e][1])
                    + s_w[e][2] * __ldg(xc + s_i[e][2])
                    + s_w[e][3] * __ldg(xc + s_i[e][3]);
            s_t[e] = v;
        }
        __syncthreads();

        float wv[9];
#pragma unroll
        for (int k = 0; k < 9; k++) wv[k] = __ldg(Wt + (c * 9 + k) * O + o);

#pragma unroll
        for (int k = 0; k < 9; k++) {
            const float4* sp = reinterpret_cast<const float4*>(s_t + k * PT + pbase);
#pragma unroll
            for (int j4 = 0; j4 < PPT / 4; j4++) {
                float4 sv = sp[j4];
                acc[j4 * 4 + 0] += wv[k] * sv.x;
                acc[j4 * 4 + 1] += wv[k] * sv.y;
                acc[j4 * 4 + 2] += wv[k] * sv.z;
                acc[j4 * 4 + 3] += wv[k] * sv.w;
            }
        }
        __syncthreads();
    }

    float bb = 0.0f, ssc = 1.0f, oof = 0.0f;
    if (EPI == 1) { bb = __ldg(e_b + o); ssc = __ldg(e_s + o); oof = __ldg(e_o + o); }
    if (EPI == 2) { bb = __ldg(e_b + o); }
    float* op = out + ((size_t)b * O + o) * HW + tile * PT + pbase;
#pragma unroll
    for (int j = 0; j < PPT; j++) {
        float v = acc[j];
        if (EPI == 1) v = fmaxf((v + bb) * ssc + oof, 0.0f);
        else if (EPI == 2) v = v + bb;
        op[j] = v;
    }
}

// ---------------- final layer: modulated DCNv2 (256->256) via tf32 mma.sync ----------
// GEMM per (batch, 64-pixel tile): M=256 (o), N=64 (pixels), K=2304 (c*9+k).
// K in slabs of 72 (8 input channels); s-tile in SMEM [72][pitch 72] (conflict-free).
// A-fragments pre-packed in g_WtF; one LDG.128 per m-tile per k-chunk per warp.
__global__ void __launch_bounds__(256, 2)
dcn_mma_final(const float* __restrict__ x, const float* __restrict__ Wfrag,
              const float* __restrict__ offs, const float* __restrict__ msk,
              const float* __restrict__ bias, float* __restrict__ out) {
    __shared__ int   s_i0[576], s_i1[576];
    __shared__ float s_wa[576], s_wb[576], s_wc[576], s_wd[576];
    __shared__ __align__(16) float s_t[72 * 72];

    const int b = blockIdx.y;
    const int tile = blockIdx.x;
    const int tid = threadIdx.x;
    const int warp = tid >> 5;
    const int lane = tid & 31;

    // ---- gather tables: separable bilinear (2 row bases + 4 weights), mask folded ----
    for (int e = tid; e < 576; e += 256) {
        int k = e >> 6, p = e & 63;
        int pix = tile * 64 + p;
        int y = pix >> 6, xx = pix & 63;
        float py = (float)(y - 1 + k / 3) + offs[(size_t)b * 36 * HW + (2 * k) * HW + pix];
        float px = (float)(xx - 1 + k % 3) + offs[(size_t)b * 36 * HW + (2 * k + 1) * HW + pix];
        float m = msk[(size_t)b * 9 * HW + k * HW + pix];
        float fy = floorf(py), fx = floorf(px);
        int iy = (int)fy, ix = (int)fx;
        float ay = py - fy, ax = px - fx;
        bool vy0 = (iy >= 0) && (iy < 64);
        bool vy1 = (iy >= -1) && (iy < 63);
        bool vx0 = (ix >= 0) && (ix < 64);
        bool vx1 = (ix >= -1) && (ix < 63);
        int cy0 = min(max(iy, 0), 63), cy1 = min(max(iy + 1, 0), 63);
        int cx0 = min(max(ix, 0), 63), cx1 = min(max(ix + 1, 0), 63);
        int xb = min(max(ix, 0), 62);
        float wAx = 0.0f, wBx = 0.0f;
        if (vx0) { if (cx0 == xb) wAx += 1.0f - ax; else wBx += 1.0f - ax; }
        if (vx1) { if (cx1 == xb) wAx += ax; else wBx += ax; }
        float w0 = vy0 ? (1.0f - ay) * m : 0.0f;
        float w1 = vy1 ? ay * m : 0.0f;
        s_i0[e] = cy0 * 64 + xb;
        s_i1[e] = cy1 * 64 + xb;
        s_wa[e] = w0 * wAx;
        s_wb[e] = w0 * wBx;
        s_wc[e] = w1 * wAx;
        s_wd[e] = w1 * wBx;
    }

    float acc[2][8][4];
#pragma unroll
    for (int mt = 0; mt < 2; mt++)
#pragma unroll
        for (int nt = 0; nt < 8; nt++)
#pragma unroll
            for (int r = 0; r < 4; r++) acc[mt][nt][r] = 0.0f;

    const float* xb_ptr = x + (size_t)b * 256 * HW;

    for (int slab = 0; slab < 32; slab++) {
        __syncthreads();
        // gather 8 channels (72 K-rows x 64 pixels), tf32-rounded into SMEM
        for (int e = tid; e < 4608; e += 256) {
            int cl = e / 576, r = e % 576;
            const float* xc = xb_ptr + (size_t)(slab * 8 + cl) * HW;
            int i0 = s_i0[r], i1 = s_i1[r];
            float v = s_wa[r] * __ldg(xc + i0) + s_wb[r] * __ldg(xc + i0 + 1)
                    + s_wc[r] * __ldg(xc + i1) + s_wd[r] * __ldg(xc + i1 + 1);
            int row = cl * 9 + (r >> 6);
            s_t[row * 72 + (r & 63)] = __uint_as_float(f2tf32(v));
        }
        __syncthreads();

#pragma unroll
        for (int kc = 0; kc < 9; kc++) {
            int kcg = slab * 9 + kc;
            const float4* ap = reinterpret_cast<const float4*>(
                Wfrag + (((size_t)kcg * 16 + warp * 2) * 32 + lane) * 4);
            float4 A0 = __ldg(ap);
            float4 A1 = __ldg(ap + 32);
            unsigned a00 = __float_as_uint(A0.x), a01 = __float_as_uint(A0.y);
            unsigned a02 = __float_as_uint(A0.z), a03 = __float_as_uint(A0.w);
            unsigned a10 = __float_as_uint(A1.x), a11 = __float_as_uint(A1.y);
            unsigned a12 = __float_as_uint(A1.z), a13 = __float_as_uint(A1.w);

            const float* sb = s_t + (kc * 8 + (lane & 3)) * 72 + (lane >> 2);
#pragma unroll
            for (int nt = 0; nt < 8; nt++) {
                unsigned b0 = __float_as_uint(sb[nt * 8]);
                unsigned b1 = __float_as_uint(sb[nt * 8 + 4 * 72]);
                asm volatile(
                    "mma.sync.aligned.m16n8k8.row.col.f32.tf32.tf32.f32 "
                    "{%0,%1,%2,%3}, {%4,%5,%6,%7}, {%8,%9}, {%0,%1,%2,%3};"
                    : "+f"(acc[0][nt][0]), "+f"(acc[0][nt][1]),
                      "+f"(acc[0][nt][2]), "+f"(acc[0][nt][3])
                    : "r"(a00), "r"(a01), "r"(a02), "r"(a03), "r"(b0), "r"(b1));
                asm volatile(
                    "mma.sync.aligned.m16n8k8.row.col.f32.tf32.tf32.f32 "
                    "{%0,%1,%2,%3}, {%4,%5,%6,%7}, {%8,%9}, {%0,%1,%2,%3};"
                    : "+f"(acc[1][nt][0]), "+f"(acc[1][nt][1]),
                      "+f"(acc[1][nt][2]), "+f"(acc[1][nt][3])
                    : "r"(a10), "r"(a11), "r"(a12), "r"(a13), "r"(b0), "r"(b1));
            }
        }
    }

    // ---- epilogue: bias add, float2 stores ----
#pragma unroll
    for (int mt = 0; mt < 2; mt++) {
        int o = warp * 32 + mt * 16 + (lane >> 2);
        float b_lo = __ldg(bias + o);
        float b_hi = __ldg(bias + o + 8);
        float* o0 = out + ((size_t)b * 256 + o) * HW + tile * 64 + (lane & 3) * 2;
        float* o1 = o0 + 8 * HW;
#pragma unroll
        for (int nt = 0; nt < 8; nt++) {
            float2 v0 = make_float2(acc[mt][nt][0] + b_lo, acc[mt][nt][1] + b_lo);
            float2 v1 = make_float2(acc[mt][nt][2] + b_hi, acc[mt][nt][3] + b_hi);
            *reinterpret_cast<float2*>(o0 + nt * 8) = v0;
            *reinterpret_cast<float2*>(o1 + nt * 8) = v1;
        }
    }
}

// ---------------- host launcher ------------------------------------------------------
extern "C" void kernel_launch(void* const* d_in, const int* in_sizes, int n_in,
                              void* d_out, int out_size) {
    const float* x       = (const float*)d_in[0];
    const float* S       = (const float*)d_in[1];
    const float* sp_w1   = (const float*)d_in[2];
    const float* sp_b1   = (const float*)d_in[3];
    const float* sp_s1   = (const float*)d_in[4];
    const float* sp_o1   = (const float*)d_in[5];
    const float* sp_w2   = (const float*)d_in[6];
    const float* sp_b2   = (const float*)d_in[7];
    const float* sp_s2   = (const float*)d_in[8];
    const float* sp_o2   = (const float*)d_in[9];
    const float* sp_w3   = (const float*)d_in[10];
    const float* sp_b3   = (const float*)d_in[11];
    const float* sp_s3   = (const float*)d_in[12];
    const float* sp_o3   = (const float*)d_in[13];
    const float* off_w   = (const float*)d_in[14];
    const float* off_b   = (const float*)d_in[15];
    const float* dcoff_w = (const float*)d_in[16];
    const float* dcoff_b = (const float*)d_in[17];
    const float* dc_w    = (const float*)d_in[18];
    const float* m_w     = (const float*)d_in[19];
    const float* m_b     = (const float*)d_in[20];
    const float* weight  = (const float*)d_in[21];
    const float* bias    = (const float*)d_in[22];

    float *Si, *h1, *h2, *h3, *feat, *off, *mask;
    float *Wt1, *Wt2, *Wt3, *Wt36, *Wtdc, *WtF, *b36;
    cudaGetSymbolAddress((void**)&Si,   g_Si);
    cudaGetSymbolAddress((void**)&h1,   g_h1);
    cudaGetSymbolAddress((void**)&h2,   g_h2);
    cudaGetSymbolAddress((void**)&h3,   g_h3);
    cudaGetSymbolAddress((void**)&feat, g_feat);
    cudaGetSymbolAddress((void**)&off,  g_off);
    cudaGetSymbolAddress((void**)&mask, g_mask);
    cudaGetSymbolAddress((void**)&Wt1,  g_Wt1);
    cudaGetSymbolAddress((void**)&Wt2,  g_Wt2);
    cudaGetSymbolAddress((void**)&Wt3,  g_Wt3);
    cudaGetSymbolAddress((void**)&Wt36, g_Wt36);
    cudaGetSymbolAddress((void**)&Wtdc, g_Wtdc);
    cudaGetSymbolAddress((void**)&WtF,  g_WtF);
    cudaGetSymbolAddress((void**)&b36,  g_b36);

    auto tgrid = [](int n) { return (n + 255) / 256; };
    transpose_weight<<<tgrid(64 * 3 * 9), 256>>>(sp_w1, Wt1, 64, 3, 0, 64);
    transpose_weight<<<tgrid(64 * 64 * 9), 256>>>(sp_w2, Wt2, 64, 64, 0, 64);
    transpose_weight<<<tgrid(64 * 64 * 9), 256>>>(sp_w3, Wt3, 64, 64, 0, 64);
    transpose_weight<<<tgrid(18 * 64 * 9), 256>>>(off_w, Wt36, 18, 64, 0, 36);
    transpose_weight<<<tgrid(18 * 64 * 9), 256>>>(dcoff_w, Wt36, 18, 64, 18, 36);
    transpose_weight<<<tgrid(64 * 64 * 9), 256>>>(dc_w, Wtdc, 64, 64, 0, 64);
    prep_final_w<<<tgrid(256 * 2304), 256>>>(weight, WtF);
    concat_bias36<<<1, 36>>>(off_b, dcoff_b, b36);

    resize_kernel<<<(BATCH * 3 * HW + 255) / 256, 256>>>(S, Si);

    dim3 grid(HW / 64, BATCH);

    dconv_gemm<3, 64, 4, 1><<<grid, 256>>>(Si, Wt1, nullptr, 0, nullptr, 0,
                                           sp_b1, sp_s1, sp_o1, h1);
    dconv_gemm<64, 64, 4, 1><<<grid, 256>>>(h1, Wt2, nullptr, 0, nullptr, 0,
                                            sp_b2, sp_s2, sp_o2, h2);
    dconv_gemm<64, 64, 4, 1><<<grid, 256>>>(h2, Wt3, nullptr, 0, nullptr, 0,
                                            sp_b3, sp_s3, sp_o3, h3);

    dconv_gemm<64, 36, 8, 2><<<grid, 288>>>(h3, Wt36, nullptr, 0, nullptr, 0,
                                            b36, nullptr, nullptr, off);

    dconv_gemm<64, 64, 4, 0><<<grid, 256>>>(h3, Wtdc, off + 18 * HW, 36 * HW,
                                            nullptr, 0, nullptr, nullptr, nullptr, feat);

    mask_kernel<<<(BATCH * HW + 255) / 256, 256>>>(feat, m_w, m_b, mask);

    // final modulated DCNv2 on tensor cores (tf32)
    dcn_mma_final<<<grid, 256>>>(x, WtF, off, mask, bias, (float*)d_out);
}

// round 3
// speedup vs baseline: 2.5972x; 1.2893x over previous
#include <cuda_runtime.h>
#include <math.h>

#define HW 4096     // 64*64
#define BATCH 8

// ---------------- scratch (static device globals; no allocation) ----------------
__device__ float g_Si  [BATCH*3*HW];
__device__ float g_h1  [BATCH*64*HW];
__device__ float g_h2  [BATCH*64*HW];
__device__ float g_h3  [BATCH*64*HW];
__device__ float g_feat[BATCH*64*HW];
__device__ float g_off [BATCH*36*HW];   // ch 0..17 = offset, 18..35 = dc_off
__device__ float g_mask[BATCH*9*HW];

__device__ float g_Wt1 [3*9*64];
__device__ float g_WtF [256*9*256];     // fragment-packed tf32 weights, final layer
__device__ float g_b36 [36];

// 3xTF32 fragment-packed mid-layer weights: [72 kchunk][4 mtile][32 lane][4 reg]
#define MIDW (72*4*32*4)
__device__ float g_Whi2 [MIDW], g_Wlo2 [MIDW];
__device__ float g_Whi3 [MIDW], g_Wlo3 [MIDW];
__device__ float g_Whidc[MIDW], g_Wlodc[MIDW];
__device__ float g_Whi36[MIDW], g_Wlo36[MIDW];

// ---------------- helpers ------------------------------------------------------------
__device__ __forceinline__ unsigned f2tf32(float f) {
    unsigned u;
    asm("cvt.rna.tf32.f32 %0, %1;" : "=r"(u) : "f"(f));
    return u;
}

__device__ __forceinline__ void mma_tf32(float* acc, unsigned a0, unsigned a1,
                                         unsigned a2, unsigned a3,
                                         unsigned b0, unsigned b1) {
    asm volatile(
        "mma.sync.aligned.m16n8k8.row.col.f32.tf32.tf32.f32 "
        "{%0,%1,%2,%3}, {%4,%5,%6,%7}, {%8,%9}, {%0,%1,%2,%3};"
        : "+f"(acc[0]), "+f"(acc[1]), "+f"(acc[2]), "+f"(acc[3])
        : "r"(a0), "r"(a1), "r"(a2), "r"(a3), "r"(b0), "r"(b1));
}

// ---------------- weight transpose (kept for sp1 fp32 path) --------------------------
__global__ void transpose_weight(const float* __restrict__ src, float* __restrict__ dst,
                                 int O, int CIN, int oOff, int Otot) {
    int i = blockIdx.x * blockDim.x + threadIdx.x;
    int total = O * CIN * 9;
    if (i >= total) return;
    int k = i % 9;
    int c = (i / 9) % CIN;
    int o = i / (9 * CIN);
    dst[(c * 9 + k) * Otot + oOff + o] = src[i];
}

// ---- mid-layer weight prep: src[O][64][9] -> hi/lo fragments, padded to 64 rows -----
__global__ void prep_mid_w(const float* __restrict__ w, float* __restrict__ hi,
                           float* __restrict__ lo, int O) {
    int i = blockIdx.x * blockDim.x + threadIdx.x;
    if (i >= 64 * 576) return;
    int K = i % 576;
    int o = i / 576;
    float v = (o < O) ? w[o * 576 + K] : 0.0f;
    float vh = __uint_as_float(f2tf32(v));
    float vl = __uint_as_float(f2tf32(v - vh));
    int kc = K >> 3, kp = K & 7;
    int mt = o >> 4, om = o & 15;
    int lane = (om & 7) * 4 + (kp & 3);
    int r = (om >> 3) + ((kp >> 2) << 1);
    size_t d = (((size_t)kc * 4 + mt) * 32 + lane) * 4 + r;
    hi[d] = vh;
    lo[d] = vl;
}

// fused 36-ch weight prep (off_w rows 0..17, dcoff_w rows 18..35, zero pad to 64)
__global__ void prep_w36(const float* __restrict__ wa, const float* __restrict__ wb,
                         float* __restrict__ hi, float* __restrict__ lo) {
    int i = blockIdx.x * blockDim.x + threadIdx.x;
    if (i >= 64 * 576) return;
    int K = i % 576;
    int o = i / 576;
    float v = 0.0f;
    if (o < 18) v = wa[o * 576 + K];
    else if (o < 36) v = wb[(o - 18) * 576 + K];
    float vh = __uint_as_float(f2tf32(v));
    float vl = __uint_as_float(f2tf32(v - vh));
    int kc = K >> 3, kp = K & 7;
    int mt = o >> 4, om = o & 15;
    int lane = (om & 7) * 4 + (kp & 3);
    int r = (om >> 3) + ((kp >> 2) << 1);
    size_t d = (((size_t)kc * 4 + mt) * 32 + lane) * 4 + r;
    hi[d] = vh;
    lo[d] = vl;
}

// ---- final-layer weight prep (single tf32), layout [kc(288)][ot(16)][lane][4] -------
__global__ void prep_final_w(const float* __restrict__ w, float* __restrict__ dst) {
    int i = blockIdx.x * blockDim.x + threadIdx.x;
    if (i >= 256 * 2304) return;
    int K = i % 2304;
    int o = i / 2304;
    int kc = K >> 3, kp = K & 7;
    int ot = o >> 4, om = o & 15;
    int lane = (om & 7) * 4 + (kp & 3);
    int r = (om >> 3) + ((kp >> 2) << 1);
    dst[(((size_t)kc * 16 + ot) * 32 + lane) * 4 + r] = __uint_as_float(f2tf32(w[i]));
}

__global__ void concat_bias36(const float* __restrict__ a, const float* __restrict__ b,
                              float* __restrict__ dst) {
    int i = threadIdx.x;
    if (i < 18) dst[i] = a[i];
    else if (i < 36) dst[i] = b[i - 18];
}

// ---------------- bilinear resize 128x128 -> 64x64, align_corners=True --------------
__global__ void resize_kernel(const float* __restrict__ S, float* __restrict__ Si) {
    int i = blockIdx.x * blockDim.x + threadIdx.x;
    if (i >= BATCH * 3 * HW) return;
    int x = i & 63;
    int y = (i >> 6) & 63;
    int bc = i >> 12;
    const float scale = 127.0f / 63.0f;
    float ys = y * scale, xs = x * scale;
    float fy = floorf(ys), fx = floorf(xs);
    int y0 = (int)fy, x0 = (int)fx;
    int y1 = min(y0 + 1, 127), x1 = min(x0 + 1, 127);
    float wy = ys - fy, wx = xs - fx;
    const float* p = S + (size_t)bc * 128 * 128;
    float v = p[y0 * 128 + x0] * (1.0f - wy) * (1.0f - wx)
            + p[y0 * 128 + x1] * (1.0f - wy) * wx
            + p[y1 * 128 + x0] * wy * (1.0f - wx)
            + p[y1 * 128 + x1] * wy * wx;
    Si[i] = v;
}

// ---------------- 1x1 conv + sigmoid: feat[b,64,hw] -> mask[b,9,hw] -----------------
__global__ void mask_kernel(const float* __restrict__ feat, const float* __restrict__ mw,
                            const float* __restrict__ mb, float* __restrict__ mask) {
    int i = blockIdx.x * blockDim.x + threadIdx.x;
    if (i >= BATCH * HW) return;
    int b = i >> 12;
    int pix = i & (HW - 1);
    float acc[9];
#pragma unroll
    for (int o = 0; o < 9; o++) acc[o] = __ldg(mb + o);
    const float* fp = feat + (size_t)b * 64 * HW + pix;
    for (int c = 0; c < 64; c++) {
        float v = __ldg(fp + c * HW);
#pragma unroll
        for (int o = 0; o < 9; o++) acc[o] += v * __ldg(mw + o * 64 + c);
    }
#pragma unroll
    for (int o = 0; o < 9; o++)
        mask[((size_t)b * 9 + o) * HW + pix] = 1.0f / (1.0f + expf(-acc[o]));
}

// ---------------- fp32 implicit-GEMM conv (only sp1: CIN=3) --------------------------
template <int CIN, int O, int PG, int EPI>
__global__ void __launch_bounds__(O * PG)
dconv_gemm(const float* __restrict__ inp, const float* __restrict__ Wt,
           const float* __restrict__ e_b, const float* __restrict__ e_s,
           const float* __restrict__ e_o, float* __restrict__ out) {
    constexpr int PT = 64;
    constexpr int PPT = PT / PG;
    constexpr int THREADS = O * PG;

    __shared__ __align__(16) float s_t[9 * PT];

    const int b = blockIdx.y;
    const int tile = blockIdx.x;
    const int tid = threadIdx.x;
    const int o = tid % O;
    const int pg = tid / O;
    const int pbase = pg * PPT;

    float acc[PPT];
#pragma unroll
    for (int j = 0; j < PPT; j++) acc[j] = 0.0f;

    for (int c = 0; c < CIN; c++) {
        const float* xc = inp + ((size_t)b * CIN + c) * HW;
        for (int e = tid; e < 9 * PT; e += THREADS) {
            int k = e >> 6, p = e & 63;
            int yy = tile + k / 3 - 1;
            int xx = p + k % 3 - 1;
            float v = ((unsigned)yy < 64u && (unsigned)xx < 64u)
                          ? __ldg(xc + yy * 64 + xx) : 0.0f;
            s_t[e] = v;
        }
        __syncthreads();

        float wv[9];
#pragma unroll
        for (int k = 0; k < 9; k++) wv[k] = __ldg(Wt + (c * 9 + k) * O + o);

#pragma unroll
        for (int k = 0; k < 9; k++) {
            const float4* sp = reinterpret_cast<const float4*>(s_t + k * PT + pbase);
#pragma unroll
            for (int j4 = 0; j4 < PPT / 4; j4++) {
                float4 sv = sp[j4];
                acc[j4 * 4 + 0] += wv[k] * sv.x;
                acc[j4 * 4 + 1] += wv[k] * sv.y;
                acc[j4 * 4 + 2] += wv[k] * sv.z;
                acc[j4 * 4 + 3] += wv[k] * sv.w;
            }
        }
        __syncthreads();
    }

    float bb = __ldg(e_b + o), ssc = __ldg(e_s + o), oof = __ldg(e_o + o);
    float* op = out + ((size_t)b * O + o) * HW + tile * PT + pbase;
#pragma unroll
    for (int j = 0; j < PPT; j++)
        op[j] = fmaxf((acc[j] + bb) * ssc + oof, 0.0f);
}

// ---------------- mid-layer 3xTF32 mma conv: CIN=64, M=64(pad), N=64 px --------------
// DEFORM: gather via offset tables (DCNv1). EPI: 0=none, 1=relu((acc+b)*s+o), 2=acc+b
template <bool DEFORM, int EPI>
__global__ void __launch_bounds__(256)
conv_mma(const float* __restrict__ inp,
         const float* __restrict__ Whi, const float* __restrict__ Wlo,
         const float* __restrict__ offs, int offBS,
         const float* __restrict__ e_b, const float* __restrict__ e_s,
         const float* __restrict__ e_o, float* __restrict__ out, int Oact) {
    extern __shared__ float dsm[];
    float* s_hi = dsm;              // 72*72
    float* s_lo = dsm + 72 * 72;    // 72*72
    int*   s_i0 = (int*)(dsm + 2 * 72 * 72);       // 576 (deform only)
    int*   s_i1 = s_i0 + 576;
    float* s_wa = (float*)(s_i1 + 576);
    float* s_wb = s_wa + 576;
    float* s_wc = s_wb + 576;
    float* s_wd = s_wc + 576;

    const int b = blockIdx.y;
    const int tile = blockIdx.x;     // = image row y
    const int tid = threadIdx.x;
    const int warp = tid >> 5;
    const int lane = tid & 31;
    const int mt = warp >> 1;        // m-tile 0..3
    const int nh = warp & 1;         // n-half: nt in [nh*4, nh*4+4)

    if (DEFORM) {
        for (int e = tid; e < 576; e += 256) {
            int k = e >> 6, p = e & 63;
            int pix = tile * 64 + p;
            float py = (float)(tile - 1 + k / 3)
                     + offs[(size_t)b * offBS + (2 * k) * HW + pix];
            float px = (float)(p - 1 + k % 3)
                     + offs[(size_t)b * offBS + (2 * k + 1) * HW + pix];
            float fy = floorf(py), fx = floorf(px);
            int iy = (int)fy, ix = (int)fx;
            float ay = py - fy, ax = px - fx;
            bool vy0 = (iy >= 0) && (iy < 64);
            bool vy1 = (iy >= -1) && (iy < 63);
            bool vx0 = (ix >= 0) && (ix < 64);
            bool vx1 = (ix >= -1) && (ix < 63);
            int cy0 = min(max(iy, 0), 63), cy1 = min(max(iy + 1, 0), 63);
            int cx0 = min(max(ix, 0), 63), cx1 = min(max(ix + 1, 0), 63);
            int xb = min(max(ix, 0), 62);
            float wAx = 0.0f, wBx = 0.0f;
            if (vx0) { if (cx0 == xb) wAx += 1.0f - ax; else wBx += 1.0f - ax; }
            if (vx1) { if (cx1 == xb) wAx += ax; else wBx += ax; }
            float w0 = vy0 ? (1.0f - ay) : 0.0f;
            float w1 = vy1 ? ay : 0.0f;
            s_i0[e] = cy0 * 64 + xb;
            s_i1[e] = cy1 * 64 + xb;
            s_wa[e] = w0 * wAx;
            s_wb[e] = w0 * wBx;
            s_wc[e] = w1 * wAx;
            s_wd[e] = w1 * wBx;
        }
        __syncthreads();
    }

    float acc[4][4];
#pragma unroll
    for (int nt = 0; nt < 4; nt++)
#pragma unroll
        for (int r = 0; r < 4; r++) acc[nt][r] = 0.0f;

    const float* xb_ptr = inp + (size_t)b * 64 * HW;

    for (int slab = 0; slab < 8; slab++) {
        // ---- gather 8 channels (72 rows x 64 px) with hi/lo tf32 split ----
        for (int e = tid; e < 4608; e += 256) {
            int cl = e / 576, r = e % 576;
            const float* xc = xb_ptr + (size_t)(slab * 8 + cl) * HW;
            float v;
            if (DEFORM) {
                int i0 = s_i0[r], i1 = s_i1[r];
                v = s_wa[r] * __ldg(xc + i0) + s_wb[r] * __ldg(xc + i0 + 1)
                  + s_wc[r] * __ldg(xc + i1) + s_wd[r] * __ldg(xc + i1 + 1);
            } else {
                int k = r >> 6, p = r & 63;
                int yy = tile + k / 3 - 1;
                int xx = p + k % 3 - 1;
                v = ((unsigned)yy < 64u && (unsigned)xx < 64u)
                        ? __ldg(xc + yy * 64 + xx) : 0.0f;
            }
            float vh = __uint_as_float(f2tf32(v));
            float vl = __uint_as_float(f2tf32(v - vh));
            int row = cl * 9 + (r >> 6);
            int col = r & 63;
            s_hi[row * 72 + col] = vh;
            s_lo[row * 72 + col] = vl;
        }
        __syncthreads();

#pragma unroll
        for (int kc = 0; kc < 9; kc++) {
            int kcg = slab * 9 + kc;
            const float4* ah = reinterpret_cast<const float4*>(
                Whi + (((size_t)kcg * 4 + mt) * 32 + lane) * 4);
            const float4* al = reinterpret_cast<const float4*>(
                Wlo + (((size_t)kcg * 4 + mt) * 32 + lane) * 4);
            float4 Ah = __ldg(ah);
            float4 Al = __ldg(al);
            unsigned ah0 = __float_as_uint(Ah.x), ah1 = __float_as_uint(Ah.y);
            unsigned ah2 = __float_as_uint(Ah.z), ah3 = __float_as_uint(Ah.w);
            unsigned al0 = __float_as_uint(Al.x), al1 = __float_as_uint(Al.y);
            unsigned al2 = __float_as_uint(Al.z), al3 = __float_as_uint(Al.w);

            int boff = (kc * 8 + (lane & 3)) * 72 + (lane >> 2) + nh * 32;
            const float* sbh = s_hi + boff;
            const float* sbl = s_lo + boff;
#pragma unroll
            for (int nt = 0; nt < 4; nt++) {
                unsigned bh0 = __float_as_uint(sbh[nt * 8]);
                unsigned bh1 = __float_as_uint(sbh[nt * 8 + 4 * 72]);
                unsigned bl0 = __float_as_uint(sbl[nt * 8]);
                unsigned bl1 = __float_as_uint(sbl[nt * 8 + 4 * 72]);
                mma_tf32(acc[nt], ah0, ah1, ah2, ah3, bh0, bh1);
                mma_tf32(acc[nt], ah0, ah1, ah2, ah3, bl0, bl1);
                mma_tf32(acc[nt], al0, al1, al2, al3, bh0, bh1);
            }
        }
        __syncthreads();
    }

    // ---- epilogue ----
    int o = mt * 16 + (lane >> 2);
    float b0 = 0, s0 = 1, f0 = 0, b1 = 0, s1 = 1, f1 = 0;
    if (EPI == 1) {
        if (o < Oact)     { b0 = __ldg(e_b + o);     s0 = __ldg(e_s + o);     f0 = __ldg(e_o + o); }
        if (o + 8 < Oact) { b1 = __ldg(e_b + o + 8); s1 = __ldg(e_s + o + 8); f1 = __ldg(e_o + o + 8); }
    } else if (EPI == 2) {
        if (o < Oact)     b0 = __ldg(e_b + o);
        if (o + 8 < Oact) b1 = __ldg(e_b + o + 8);
    }
    int colb = tile * 64 + nh * 32 + (lane & 3) * 2;
    float* o0 = out + ((size_t)b * Oact + o) * HW + colb;
    float* o1 = o0 + 8 * HW;
#pragma unroll
    for (int nt = 0; nt < 4; nt++) {
        float v0a = acc[nt][0], v0b = acc[nt][1];
        float v1a = acc[nt][2], v1b = acc[nt][3];
        if (EPI == 1) {
            v0a = fmaxf((v0a + b0) * s0 + f0, 0.0f);
            v0b = fmaxf((v0b + b0) * s0 + f0, 0.0f);
            v1a = fmaxf((v1a + b1) * s1 + f1, 0.0f);
            v1b = fmaxf((v1b + b1) * s1 + f1, 0.0f);
        } else if (EPI == 2) {
            v0a += b0; v0b += b0; v1a += b1; v1b += b1;
        }
        if (o < Oact)
            *reinterpret_cast<float2*>(o0 + nt * 8) = make_float2(v0a, v0b);
        if (o + 8 < Oact)
            *reinterpret_cast<float2*>(o1 + nt * 8) = make_float2(v1a, v1b);
    }
}

// ---------------- final layer: modulated DCNv2 (256->256) via tf32 mma ---------------
__global__ void __launch_bounds__(256, 2)
dcn_mma_final(const float* __restrict__ x, const float* __restrict__ Wfrag,
              const float* __restrict__ offs, const float* __restrict__ msk,
              const float* __restrict__ bias, float* __restrict__ out) {
    __shared__ int   s_i0[576], s_i1[576];
    __shared__ float s_wa[576], s_wb[576], s_wc[576], s_wd[576];
    __shared__ __align__(16) float s_t[72 * 72];

    const int b = blockIdx.y;
    const int tile = blockIdx.x;
    const int tid = threadIdx.x;
    const int warp = tid >> 5;
    const int lane = tid & 31;

    for (int e = tid; e < 576; e += 256) {
        int k = e >> 6, p = e & 63;
        int pix = tile * 64 + p;
        int y = pix >> 6, xx = pix & 63;
        float py = (float)(y - 1 + k / 3) + offs[(size_t)b * 36 * HW + (2 * k) * HW + pix];
        float px = (float)(xx - 1 + k % 3) + offs[(size_t)b * 36 * HW + (2 * k + 1) * HW + pix];
        float m = msk[(size_t)b * 9 * HW + k * HW + pix];
        float fy = floorf(py), fx = floorf(px);
        int iy = (int)fy, ix = (int)fx;
        float ay = py - fy, ax = px - fx;
        bool vy0 = (iy >= 0) && (iy < 64);
        bool vy1 = (iy >= -1) && (iy < 63);
        bool vx0 = (ix >= 0) && (ix < 64);
        bool vx1 = (ix >= -1) && (ix < 63);
        int cy0 = min(max(iy, 0), 63), cy1 = min(max(iy + 1, 0), 63);
        int cx0 = min(max(ix, 0), 63), cx1 = min(max(ix + 1, 0), 63);
        int xb = min(max(ix, 0), 62);
        float wAx = 0.0f, wBx = 0.0f;
        if (vx0) { if (cx0 == xb) wAx += 1.0f - ax; else wBx += 1.0f - ax; }
        if (vx1) { if (cx1 == xb) wAx += ax; else wBx += ax; }
        float w0 = vy0 ? (1.0f - ay) * m : 0.0f;
        float w1 = vy1 ? ay * m : 0.0f;
        s_i0[e] = cy0 * 64 + xb;
        s_i1[e] = cy1 * 64 + xb;
        s_wa[e] = w0 * wAx;
        s_wb[e] = w0 * wBx;
        s_wc[e] = w1 * wAx;
        s_wd[e] = w1 * wBx;
    }

    float acc[2][8][4];
#pragma unroll
    for (int mt = 0; mt < 2; mt++)
#pragma unroll
        for (int nt = 0; nt < 8; nt++)
#pragma unroll
            for (int r = 0; r < 4; r++) acc[mt][nt][r] = 0.0f;

    const float* xb_ptr = x + (size_t)b * 256 * HW;

    for (int slab = 0; slab < 32; slab++) {
        __syncthreads();
        for (int e = tid; e < 4608; e += 256) {
            int cl = e / 576, r = e % 576;
            const float* xc = xb_ptr + (size_t)(slab * 8 + cl) * HW;
            int i0 = s_i0[r], i1 = s_i1[r];
            float v = s_wa[r] * __ldg(xc + i0) + s_wb[r] * __ldg(xc + i0 + 1)
                    + s_wc[r] * __ldg(xc + i1) + s_wd[r] * __ldg(xc + i1 + 1);
            int row = cl * 9 + (r >> 6);
            s_t[row * 72 + (r & 63)] = __uint_as_float(f2tf32(v));
        }
        __syncthreads();

#pragma unroll
        for (int kc = 0; kc < 9; kc++) {
            int kcg = slab * 9 + kc;
            const float4* ap = reinterpret_cast<const float4*>(
                Wfrag + (((size_t)kcg * 16 + warp * 2) * 32 + lane) * 4);
            float4 A0 = __ldg(ap);
            float4 A1 = __ldg(ap + 32);
            unsigned a00 = __float_as_uint(A0.x), a01 = __float_as_uint(A0.y);
            unsigned a02 = __float_as_uint(A0.z), a03 = __float_as_uint(A0.w);
            unsigned a10 = __float_as_uint(A1.x), a11 = __float_as_uint(A1.y);
            unsigned a12 = __float_as_uint(A1.z), a13 = __float_as_uint(A1.w);

            const float* sb = s_t + (kc * 8 + (lane & 3)) * 72 + (lane >> 2);
#pragma unroll
            for (int nt = 0; nt < 8; nt++) {
                unsigned b0 = __float_as_uint(sb[nt * 8]);
                unsigned b1 = __float_as_uint(sb[nt * 8 + 4 * 72]);
                mma_tf32(acc[0][nt], a00, a01, a02, a03, b0, b1);
                mma_tf32(acc[1][nt], a10, a11, a12, a13, b0, b1);
            }
        }
    }

#pragma unroll
    for (int mt = 0; mt < 2; mt++) {
        int o = warp * 32 + mt * 16 + (lane >> 2);
        float b_lo = __ldg(bias + o);
        float b_hi = __ldg(bias + o + 8);
        float* o0 = out + ((size_t)b * 256 + o) * HW + tile * 64 + (lane & 3) * 2;
        float* o1 = o0 + 8 * HW;
#pragma unroll
        for (int nt = 0; nt < 8; nt++) {
            *reinterpret_cast<float2*>(o0 + nt * 8) =
                make_float2(acc[mt][nt][0] + b_lo, acc[mt][nt][1] + b_lo);
            *reinterpret_cast<float2*>(o1 + nt * 8) =
                make_float2(acc[mt][nt][2] + b_hi, acc[mt][nt][3] + b_hi);
        }
    }
}

// ---------------- host launcher ------------------------------------------------------
extern "C" void kernel_launch(void* const* d_in, const int* in_sizes, int n_in,
                              void* d_out, int out_size) {
    const float* x       = (const float*)d_in[0];
    const float* S       = (const float*)d_in[1];
    const float* sp_w1   = (const float*)d_in[2];
    const float* sp_b1   = (const float*)d_in[3];
    const float* sp_s1   = (const float*)d_in[4];
    const float* sp_o1   = (const float*)d_in[5];
    const float* sp_w2   = (const float*)d_in[6];
    const float* sp_s2   = (const float*)d_in[8];
    const float* sp_o2   = (const float*)d_in[9];
    const float* sp_w3   = (const float*)d_in[10];
    const float* sp_s3   = (const float*)d_in[12];
    const float* sp_o3   = (const float*)d_in[13];
    const float* off_w   = (const float*)d_in[14];
    const float* off_b   = (const float*)d_in[15];
    const float* dcoff_w = (const float*)d_in[16];
    const float* dcoff_b = (const float*)d_in[17];
    const float* dc_w    = (const float*)d_in[18];
    const float* m_w     = (const float*)d_in[19];
    const float* m_b     = (const float*)d_in[20];
    const float* weight  = (const float*)d_in[21];
    const float* bias    = (const float*)d_in[22];
    const float* sp_b2   = (const float*)d_in[7];
    const float* sp_b3   = (const float*)d_in[11];

    float *Si, *h1, *h2, *h3, *feat, *off, *mask;
    float *Wt1, *WtF, *b36;
    float *Whi2, *Wlo2, *Whi3, *Wlo3, *Whidc, *Wlodc, *Whi36, *Wlo36;
    cudaGetSymbolAddress((void**)&Si,    g_Si);
    cudaGetSymbolAddress((void**)&h1,    g_h1);
    cudaGetSymbolAddress((void**)&h2,    g_h2);
    cudaGetSymbolAddress((void**)&h3,    g_h3);
    cudaGetSymbolAddress((void**)&feat,  g_feat);
    cudaGetSymbolAddress((void**)&off,   g_off);
    cudaGetSymbolAddress((void**)&mask,  g_mask);
    cudaGetSymbolAddress((void**)&Wt1,   g_Wt1);
    cudaGetSymbolAddress((void**)&WtF,   g_WtF);
    cudaGetSymbolAddress((void**)&b36,   g_b36);
    cudaGetSymbolAddress((void**)&Whi2,  g_Whi2);
    cudaGetSymbolAddress((void**)&Wlo2,  g_Wlo2);
    cudaGetSymbolAddress((void**)&Whi3,  g_Whi3);
    cudaGetSymbolAddress((void**)&Wlo3,  g_Wlo3);
    cudaGetSymbolAddress((void**)&Whidc, g_Whidc);
    cudaGetSymbolAddress((void**)&Wlodc, g_Wlodc);
    cudaGetSymbolAddress((void**)&Whi36, g_Whi36);
    cudaGetSymbolAddress((void**)&Wlo36, g_Wlo36);

    // dynamic SMEM sizes
    const int SMEM_PLAIN  = 2 * 72 * 72 * 4;                 // 41472
    const int SMEM_DEFORM = SMEM_PLAIN + 2 * 576 * 4 + 4 * 576 * 4;  // 55296
    static bool attr_done = false;
    if (!attr_done) {
        cudaFuncSetAttribute(conv_mma<true, 0>,
                             cudaFuncAttributeMaxDynamicSharedMemorySize, SMEM_DEFORM);
        attr_done = true;
    }

    auto tgrid = [](int n) { return (n + 255) / 256; };
    dim3 grid(HW / 64, BATCH);

    // launch order chosen so ncu (-s 5 -c 1) captures conv_mma(sp2)
    transpose_weight<<<tgrid(64 * 3 * 9), 256>>>(sp_w1, Wt1, 64, 3, 0, 64);     // 0
    prep_mid_w<<<tgrid(64 * 576), 256>>>(sp_w2, Whi2, Wlo2, 64);                // 1
    prep_mid_w<<<tgrid(64 * 576), 256>>>(sp_w3, Whi3, Wlo3, 64);                // 2
    resize_kernel<<<(BATCH * 3 * HW + 255) / 256, 256>>>(S, Si);                // 3
    dconv_gemm<3, 64, 4, 1><<<grid, 256>>>(Si, Wt1, sp_b1, sp_s1, sp_o1, h1);   // 4
    conv_mma<false, 1><<<grid, 256, SMEM_PLAIN>>>(h1, Whi2, Wlo2, nullptr, 0,
                                                  sp_b2, sp_s2, sp_o2, h2, 64); // 5 <- ncu
    conv_mma<false, 1><<<grid, 256, SMEM_PLAIN>>>(h2, Whi3, Wlo3, nullptr, 0,
                                                  sp_b3, sp_s3, sp_o3, h3, 64); // 6
    prep_w36<<<tgrid(64 * 576), 256>>>(off_w, dcoff_w, Whi36, Wlo36);           // 7
    concat_bias36<<<1, 36>>>(off_b, dcoff_b, b36);                              // 8
    prep_mid_w<<<tgrid(64 * 576), 256>>>(dc_w, Whidc, Wlodc, 64);               // 9
    conv_mma<false, 2><<<grid, 256, SMEM_PLAIN>>>(h3, Whi36, Wlo36, nullptr, 0,
                                                  b36, nullptr, nullptr, off, 36); // 10
    conv_mma<true, 0><<<grid, 256, SMEM_DEFORM>>>(h3, Whidc, Wlodc,
                                                  off + 18 * HW, 36 * HW,
                                                  nullptr, nullptr, nullptr, feat, 64); // 11
    mask_kernel<<<(BATCH * HW + 255) / 256, 256>>>(feat, m_w, m_b, mask);       // 12
    prep_final_w<<<tgrid(256 * 2304), 256>>>(weight, WtF);                      // 13
    dcn_mma_final<<<grid, 256>>>(x, WtF, off, mask, bias, (float*)d_out);       // 14
}

// round 5
// speedup vs baseline: 3.3394x; 1.2858x over previous
#include <cuda_runtime.h>
#include <cuda_fp16.h>
#include <math.h>
#include <stdint.h>

#define HW 4096     // 64*64
#define BATCH 8

// ---------------- scratch (static device globals; no allocation) ----------------
__device__ float g_h1  [BATCH*64*HW];
__device__ float g_h2  [BATCH*64*HW];
__device__ float g_h3  [BATCH*64*HW];
__device__ float g_feat[BATCH*64*HW];
__device__ float g_off [BATCH*36*HW];   // ch 0..17 = offset, 18..35 = dc_off
__device__ float g_mask[BATCH*9*HW];
__device__ float g_b36 [36];

// f16 fragment-packed weights (each u32 = 2 f16 along K)
// final: [144 kc16][16 mt][32 lane][4 reg]
__device__ unsigned g_Af[144*16*32*4];
// mids:  [36 kc16][4 mt][32 lane][4 reg], hi + lo per layer
#define MIDA (36*4*32*4)
__device__ unsigned g_Ah2 [MIDA], g_Al2 [MIDA];
__device__ unsigned g_Ah3 [MIDA], g_Al3 [MIDA];
__device__ unsigned g_Ahdc[MIDA], g_Aldc[MIDA];
__device__ unsigned g_Ah36[MIDA], g_Al36[MIDA];

// ---------------- helpers ------------------------------------------------------------
__device__ __forceinline__ void mma_f16(float* acc, unsigned a0, unsigned a1,
                                        unsigned a2, unsigned a3,
                                        unsigned b0, unsigned b1) {
    asm volatile(
        "mma.sync.aligned.m16n8k16.row.col.f32.f16.f16.f32 "
        "{%0,%1,%2,%3}, {%4,%5,%6,%7}, {%8,%9}, {%0,%1,%2,%3};"
        : "+f"(acc[0]), "+f"(acc[1]), "+f"(acc[2]), "+f"(acc[3])
        : "r"(a0), "r"(a1), "r"(a2), "r"(a3), "r"(b0), "r"(b1));
}

// fragment coords for A of m16n8k16: element (om, kk) within a 16x16 chunk
__device__ __forceinline__ void frag_coords(int om, int kk, int& lane, int& reg, int& half) {
    int kpair = kk >> 1;
    half = kk & 1;
    lane = (om & 7) * 4 + (kpair & 3);
    reg = (om >> 3) + ((kpair >> 2) << 1);
}

// ---------------- weight prep kernels -------------------------------------------------
// mids: w[O][576] (O<=64, pad rows to 64) -> hi/lo f16 fragment arrays
__global__ void prep_mid_f16(const float* __restrict__ w, unsigned* __restrict__ hi,
                             unsigned* __restrict__ lo, int O) {
    int i = blockIdx.x * blockDim.x + threadIdx.x;
    if (i >= 64 * 576) return;
    int K = i % 576;
    int o = i / 576;
    float v = (o < O) ? w[o * 576 + K] : 0.0f;
    __half vh = __float2half(v);
    __half vl = __float2half(v - __half2float(vh));
    int kc = K >> 4, kk = K & 15;
    int mt = o >> 4, om = o & 15;
    int lane, reg, half;
    frag_coords(om, kk, lane, reg, half);
    size_t base = ((((size_t)kc * 4 + mt) * 32 + lane) * 4 + reg) * 2 + half;
    ((__half*)hi)[base] = vh;
    ((__half*)lo)[base] = vl;
}

// fused 36-ch (off rows 0..17, dc_off rows 18..35, zero pad)
__global__ void prep_w36_f16(const float* __restrict__ wa, const float* __restrict__ wb,
                             unsigned* __restrict__ hi, unsigned* __restrict__ lo) {
    int i = blockIdx.x * blockDim.x + threadIdx.x;
    if (i >= 64 * 576) return;
    int K = i % 576;
    int o = i / 576;
    float v = 0.0f;
    if (o < 18) v = wa[o * 576 + K];
    else if (o < 36) v = wb[(o - 18) * 576 + K];
    __half vh = __float2half(v);
    __half vl = __float2half(v - __half2float(vh));
    int kc = K >> 4, kk = K & 15;
    int mt = o >> 4, om = o & 15;
    int lane, reg, half;
    frag_coords(om, kk, lane, reg, half);
    size_t base = ((((size_t)kc * 4 + mt) * 32 + lane) * 4 + reg) * 2 + half;
    ((__half*)hi)[base] = vh;
    ((__half*)lo)[base] = vl;
}

// final: w[256][2304] -> single f16 fragments
__global__ void prep_final_f16(const float* __restrict__ w, unsigned* __restrict__ dst) {
    int i = blockIdx.x * blockDim.x + threadIdx.x;
    if (i >= 256 * 2304) return;
    int K = i % 2304;
    int o = i / 2304;
    int kc = K >> 4, kk = K & 15;
    int mt = o >> 4, om = o & 15;
    int lane, reg, half;
    frag_coords(om, kk, lane, reg, half);
    size_t base = ((((size_t)kc * 16 + mt) * 32 + lane) * 4 + reg) * 2 + half;
    ((__half*)dst)[base] = __float2half(w[i]);
}

__global__ void concat_bias36(const float* __restrict__ a, const float* __restrict__ b,
                              float* __restrict__ dst) {
    int i = threadIdx.x;
    if (i < 18) dst[i] = a[i];
    else if (i < 36) dst[i] = b[i - 18];
}

// ---------------- 1x1 conv + sigmoid -------------------------------------------------
__global__ void mask_kernel(const float* __restrict__ feat, const float* __restrict__ mw,
                            const float* __restrict__ mb, float* __restrict__ mask) {
    int i = blockIdx.x * blockDim.x + threadIdx.x;
    if (i >= BATCH * HW) return;
    int b = i >> 12;
    int pix = i & (HW - 1);
    float acc[9];
#pragma unroll
    for (int o = 0; o < 9; o++) acc[o] = __ldg(mb + o);
    const float* fp = feat + (size_t)b * 64 * HW + pix;
    for (int c = 0; c < 64; c++) {
        float v = __ldg(fp + c * HW);
#pragma unroll
        for (int o = 0; o < 9; o++) acc[o] += v * __ldg(mw + o * 64 + c);
    }
#pragma unroll
    for (int o = 0; o < 9; o++)
        mask[((size_t)b * 9 + o) * HW + pix] = 1.0f / (1.0f + expf(-acc[o]));
}

// ---------------- sp1: fused resize + conv3x3 (CIN=3) + BN + ReLU, fp32 --------------
__device__ __forceinline__ float resize_at(const float* __restrict__ p, int y, int x) {
    const float scale = 127.0f / 63.0f;
    float ys = y * scale, xs = x * scale;
    float fy = floorf(ys), fx = floorf(xs);
    int y0 = (int)fy, x0 = (int)fx;
    int y1 = min(y0 + 1, 127), x1 = min(x0 + 1, 127);
    float wy = ys - fy, wx = xs - fx;
    return p[y0 * 128 + x0] * (1.0f - wy) * (1.0f - wx)
         + p[y0 * 128 + x1] * (1.0f - wy) * wx
         + p[y1 * 128 + x0] * wy * (1.0f - wx)
         + p[y1 * 128 + x1] * wy * wx;
}

__global__ void __launch_bounds__(256)
sp1_kernel(const float* __restrict__ S, const float* __restrict__ w1,
           const float* __restrict__ e_b, const float* __restrict__ e_s,
           const float* __restrict__ e_o, float* __restrict__ out) {
    __shared__ __align__(16) float s_t[576];
    const int b = blockIdx.y;
    const int tile = blockIdx.x;           // image row y
    const int tid = threadIdx.x;
    const int o = tid & 63;
    const int pbase = (tid >> 6) * 16;

    float acc[16];
#pragma unroll
    for (int j = 0; j < 16; j++) acc[j] = 0.0f;

    for (int c = 0; c < 3; c++) {
        const float* Sc = S + (size_t)(b * 3 + c) * 128 * 128;
        for (int e = tid; e < 576; e += 256) {
            int k = e >> 6, p = e & 63;
            int yy = tile + k / 3 - 1;
            int xx = p + k % 3 - 1;
            s_t[e] = ((unsigned)yy < 64u && (unsigned)xx < 64u)
                         ? resize_at(Sc, yy, xx) : 0.0f;
        }
        __syncthreads();

        float wv[9];
#pragma unroll
        for (int k = 0; k < 9; k++) wv[k] = __ldg(w1 + o * 27 + c * 9 + k);

#pragma unroll
        for (int k = 0; k < 9; k++) {
            const float4* sp = reinterpret_cast<const float4*>(s_t + k * 64 + pbase);
#pragma unroll
            for (int j4 = 0; j4 < 4; j4++) {
                float4 sv = sp[j4];
                acc[j4 * 4 + 0] += wv[k] * sv.x;
                acc[j4 * 4 + 1] += wv[k] * sv.y;
                acc[j4 * 4 + 2] += wv[k] * sv.z;
                acc[j4 * 4 + 3] += wv[k] * sv.w;
            }
        }
        __syncthreads();
    }

    float bb = __ldg(e_b + o), ssc = __ldg(e_s + o), oof = __ldg(e_o + o);
    float* op = out + ((size_t)b * 64 + o) * HW + tile * 64 + pbase;
#pragma unroll
    for (int j = 0; j < 16; j++)
        op[j] = fmaxf((acc[j] + bb) * ssc + oof, 0.0f);
}

// ---------------- mid-layer 3-term f16 mma conv (CIN=64, M=64 pad, N=64 px) ----------
// DEFORM: DCNv1 gather. EPI: 0=none, 1=relu((acc+b)*s+o), 2=acc+b
template <bool DEFORM, int EPI>
__global__ void __launch_bounds__(256)
conv_mma(const float* __restrict__ inp,
         const unsigned* __restrict__ Ahi, const unsigned* __restrict__ Alo,
         const float* __restrict__ offs, int offBS,
         const float* __restrict__ e_b, const float* __restrict__ e_s,
         const float* __restrict__ e_o, float* __restrict__ out, int Oact) {
    __shared__ unsigned s_bh[32 * 72], s_bl[32 * 72];
    __shared__ int s_i0[576], s_i1[576];
    __shared__ float s_wa[576], s_wb[576], s_wc[576], s_wd[576];

    const int b = blockIdx.y;
    const int tile = blockIdx.x;       // image row
    const int tid = threadIdx.x;
    const int warp = tid >> 5;
    const int lane = tid & 31;
    const int mt = warp >> 1;
    const int nh = warp & 1;

    if (DEFORM) {
        for (int e = tid; e < 576; e += 256) {
            int k = e >> 6, p = e & 63;
            int pix = tile * 64 + p;
            float py = (float)(tile - 1 + k / 3)
                     + offs[(size_t)b * offBS + (2 * k) * HW + pix];
            float px = (float)(p - 1 + k % 3)
                     + offs[(size_t)b * offBS + (2 * k + 1) * HW + pix];
            float fy = floorf(py), fx = floorf(px);
            int iy = (int)fy, ix = (int)fx;
            float ay = py - fy, ax = px - fx;
            bool vy0 = (iy >= 0) && (iy < 64);
            bool vy1 = (iy >= -1) && (iy < 63);
            bool vx0 = (ix >= 0) && (ix < 64);
            bool vx1 = (ix >= -1) && (ix < 63);
            int cy0 = min(max(iy, 0), 63), cy1 = min(max(iy + 1, 0), 63);
            int cx0 = min(max(ix, 0), 63), cx1 = min(max(ix + 1, 0), 63);
            int xb = min(max(ix, 0), 62);
            float wAx = 0.0f, wBx = 0.0f;
            if (vx0) { if (cx0 == xb) wAx += 1.0f - ax; else wBx += 1.0f - ax; }
            if (vx1) { if (cx1 == xb) wAx += ax; else wBx += ax; }
            float w0 = vy0 ? (1.0f - ay) : 0.0f;
            float w1 = vy1 ? ay : 0.0f;
            s_i0[e] = cy0 * 64 + xb;
            s_i1[e] = cy1 * 64 + xb;
            s_wa[e] = w0 * wAx;
            s_wb[e] = w0 * wBx;
            s_wc[e] = w1 * wAx;
            s_wd[e] = w1 * wBx;
        }
        __syncthreads();
    }

    float acc[4][4];
#pragma unroll
    for (int nt = 0; nt < 4; nt++)
#pragma unroll
        for (int r = 0; r < 4; r++) acc[nt][r] = 0.0f;

    const float* xb_ptr = inp + (size_t)b * 64 * HW;

    for (int slab = 0; slab < 9; slab++) {
        // gather 64 K-rows x 64 px, f16 hi/lo into paired-K u32 tiles
#pragma unroll 4
        for (int i = 0; i < 16; i++) {
            int e = i * 256 + tid;
            int p = e & 63, j = e >> 6;
            int K = slab * 64 + j;
            int c = K / 9;
            int kk = K - c * 9;
            const float* xc = xb_ptr + (size_t)c * HW;
            float v;
            if (DEFORM) {
                int r = kk * 64 + p;
                int i0 = s_i0[r], i1 = s_i1[r];
                v = s_wa[r] * __ldg(xc + i0) + s_wb[r] * __ldg(xc + i0 + 1)
                  + s_wc[r] * __ldg(xc + i1) + s_wd[r] * __ldg(xc + i1 + 1);
            } else {
                int yy = tile + kk / 3 - 1;
                int xx = p + kk % 3 - 1;
                v = ((unsigned)yy < 64u && (unsigned)xx < 64u)
                        ? __ldg(xc + yy * 64 + xx) : 0.0f;
            }
            __half vh = __float2half(v);
            __half vl = __float2half(v - __half2float(vh));
            int idx = ((j >> 1) * 72 + p) * 2 + (j & 1);
            ((__half*)s_bh)[idx] = vh;
            ((__half*)s_bl)[idx] = vl;
        }
        __syncthreads();

#pragma unroll
        for (int kc = 0; kc < 4; kc++) {
            int kcg = slab * 4 + kc;
            uint4 Ah = __ldg((const uint4*)(Ahi + (((size_t)kcg * 4 + mt) * 32 + lane) * 4));
            uint4 Al = __ldg((const uint4*)(Alo + (((size_t)kcg * 4 + mt) * 32 + lane) * 4));

            const unsigned* bhp = s_bh + (kc * 8 + (lane & 3)) * 72 + (lane >> 2) + nh * 32;
            const unsigned* blp = s_bl + (kc * 8 + (lane & 3)) * 72 + (lane >> 2) + nh * 32;
#pragma unroll
            for (int nt = 0; nt < 4; nt++) {
                unsigned b0h = bhp[nt * 8], b1h = bhp[nt * 8 + 4 * 72];
                unsigned b0l = blp[nt * 8], b1l = blp[nt * 8 + 4 * 72];
                mma_f16(acc[nt], Ah.x, Ah.y, Ah.z, Ah.w, b0h, b1h);
                mma_f16(acc[nt], Ah.x, Ah.y, Ah.z, Ah.w, b0l, b1l);
                mma_f16(acc[nt], Al.x, Al.y, Al.z, Al.w, b0h, b1h);
            }
        }
        __syncthreads();
    }

    // epilogue
    int o = mt * 16 + (lane >> 2);
    float b0 = 0, s0 = 1, f0 = 0, b1 = 0, s1 = 1, f1 = 0;
    if (EPI == 1) {
        if (o < Oact)     { b0 = __ldg(e_b + o);     s0 = __ldg(e_s + o);     f0 = __ldg(e_o + o); }
        if (o + 8 < Oact) { b1 = __ldg(e_b + o + 8); s1 = __ldg(e_s + o + 8); f1 = __ldg(e_o + o + 8); }
    } else if (EPI == 2) {
        if (o < Oact)     b0 = __ldg(e_b + o);
        if (o + 8 < Oact) b1 = __ldg(e_b + o + 8);
    }
    int colb = tile * 64 + nh * 32 + (lane & 3) * 2;
    float* o0 = out + ((size_t)b * Oact + o) * HW + colb;
    float* o1 = o0 + 8 * HW;
#pragma unroll
    for (int nt = 0; nt < 4; nt++) {
        float v0a = acc[nt][0], v0b = acc[nt][1];
        float v1a = acc[nt][2], v1b = acc[nt][3];
        if (EPI == 1) {
            v0a = fmaxf((v0a + b0) * s0 + f0, 0.0f);
            v0b = fmaxf((v0b + b0) * s0 + f0, 0.0f);
            v1a = fmaxf((v1a + b1) * s1 + f1, 0.0f);
            v1b = fmaxf((v1b + b1) * s1 + f1, 0.0f);
        } else if (EPI == 2) {
            v0a += b0; v0b += b0; v1a += b1; v1b += b1;
        }
        if (o < Oact)
            *reinterpret_cast<float2*>(o0 + nt * 8) = make_float2(v0a, v0b);
        if (o + 8 < Oact)
            *reinterpret_cast<float2*>(o1 + nt * 8) = make_float2(v1a, v1b);
    }
}

// ---------------- final modulated DCNv2 (256->256), single-pass f16 mma --------------
__global__ void __launch_bounds__(256)
dcn_final_f16(const float* __restrict__ x, const unsigned* __restrict__ Af,
              const float* __restrict__ offs, const float* __restrict__ msk,
              const float* __restrict__ bias, float* __restrict__ out) {
    __shared__ unsigned s_b[32 * 72];
    __shared__ int s_i0[576], s_i1[576];
    __shared__ float s_wa[576], s_wb[576], s_wc[576], s_wd[576];

    const int b = blockIdx.y;
    const int tile = blockIdx.x;
    const int tid = threadIdx.x;
    const int warp = tid >> 5;
    const int lane = tid & 31;

    // gather tables (mask folded)
    for (int e = tid; e < 576; e += 256) {
        int k = e >> 6, p = e & 63;
        int pix = tile * 64 + p;
        float py = (float)(tile - 1 + k / 3) + offs[(size_t)b * 36 * HW + (2 * k) * HW + pix];
        float px = (float)(p - 1 + k % 3) + offs[(size_t)b * 36 * HW + (2 * k + 1) * HW + pix];
        float m = msk[(size_t)b * 9 * HW + k * HW + pix];
        float fy = floorf(py), fx = floorf(px);
        int iy = (int)fy, ix = (int)fx;
        float ay = py - fy, ax = px - fx;
        bool vy0 = (iy >= 0) && (iy < 64);
        bool vy1 = (iy >= -1) && (iy < 63);
        bool vx0 = (ix >= 0) && (ix < 64);
        bool vx1 = (ix >= -1) && (ix < 63);
        int cy0 = min(max(iy, 0), 63), cy1 = min(max(iy + 1, 0), 63);
        int cx0 = min(max(ix, 0), 63), cx1 = min(max(ix + 1, 0), 63);
        int xb = min(max(ix, 0), 62);
        float wAx = 0.0f, wBx = 0.0f;
        if (vx0) { if (cx0 == xb) wAx += 1.0f - ax; else wBx += 1.0f - ax; }
        if (vx1) { if (cx1 == xb) wAx += ax; else wBx += ax; }
        float w0 = vy0 ? (1.0f - ay) * m : 0.0f;
        float w1 = vy1 ? ay * m : 0.0f;
        s_i0[e] = cy0 * 64 + xb;
        s_i1[e] = cy1 * 64 + xb;
        s_wa[e] = w0 * wAx;
        s_wb[e] = w0 * wBx;
        s_wc[e] = w1 * wAx;
        s_wd[e] = w1 * wBx;
    }
    __syncthreads();

    float acc[2][8][4];
#pragma unroll
    for (int mtl = 0; mtl < 2; mtl++)
#pragma unroll
        for (int nt = 0; nt < 8; nt++)
#pragma unroll
            for (int r = 0; r < 4; r++) acc[mtl][nt][r] = 0.0f;

    const float* xb_ptr = x + (size_t)b * 256 * HW;

    for (int slab = 0; slab < 36; slab++) {
        // gather 64 K-rows x 64 px into f16-pair tile
#pragma unroll 4
        for (int i = 0; i < 16; i++) {
            int e = i * 256 + tid;
            int p = e & 63, j = e >> 6;
            int K = slab * 64 + j;
            int c = K / 9;
            int kk = K - c * 9;
            int r = kk * 64 + p;
            const float* xc = xb_ptr + (size_t)c * HW;
            int i0 = s_i0[r], i1 = s_i1[r];
            float v = s_wa[r] * __ldg(xc + i0) + s_wb[r] * __ldg(xc + i0 + 1)
                    + s_wc[r] * __ldg(xc + i1) + s_wd[r] * __ldg(xc + i1 + 1);
            ((__half*)s_b)[((j >> 1) * 72 + p) * 2 + (j & 1)] = __float2half(v);
        }
        __syncthreads();

#pragma unroll
        for (int kc = 0; kc < 4; kc++) {
            int kcg = slab * 4 + kc;
            const unsigned* ap = Af + (((size_t)kcg * 16 + warp * 2) * 32 + lane) * 4;
            uint4 A0 = __ldg((const uint4*)ap);
            uint4 A1 = __ldg((const uint4*)(ap + 128));

            const unsigned* bp = s_b + (kc * 8 + (lane & 3)) * 72 + (lane >> 2);
#pragma unroll
            for (int nt = 0; nt < 8; nt++) {
                unsigned b0 = bp[nt * 8], b1 = bp[nt * 8 + 4 * 72];
                mma_f16(acc[0][nt], A0.x, A0.y, A0.z, A0.w, b0, b1);
                mma_f16(acc[1][nt], A1.x, A1.y, A1.z, A1.w, b0, b1);
            }
        }
        __syncthreads();
    }

    // epilogue: bias, float2 stores
#pragma unroll
    for (int mtl = 0; mtl < 2; mtl++) {
        int o = warp * 32 + mtl * 16 + (lane >> 2);
        float b_lo = __ldg(bias + o);
        float b_hi = __ldg(bias + o + 8);
        float* o0 = out + ((size_t)b * 256 + o) * HW + tile * 64 + (lane & 3) * 2;
        float* o1 = o0 + 8 * HW;
#pragma unroll
        for (int nt = 0; nt < 8; nt++) {
            *reinterpret_cast<float2*>(o0 + nt * 8) =
                make_float2(acc[mtl][nt][0] + b_lo, acc[mtl][nt][1] + b_lo);
            *reinterpret_cast<float2*>(o1 + nt * 8) =
                make_float2(acc[mtl][nt][2] + b_hi, acc[mtl][nt][3] + b_hi);
        }
    }
}

// ---------------- host launcher ------------------------------------------------------
extern "C" void kernel_launch(void* const* d_in, const int* in_sizes, int n_in,
                              void* d_out, int out_size) {
    const float* x       = (const float*)d_in[0];
    const float* S       = (const float*)d_in[1];
    const float* sp_w1   = (const float*)d_in[2];
    const float* sp_b1   = (const float*)d_in[3];
    const float* sp_s1   = (const float*)d_in[4];
    const float* sp_o1   = (const float*)d_in[5];
    const float* sp_w2   = (const float*)d_in[6];
    const float* sp_b2   = (const float*)d_in[7];
    const float* sp_s2   = (const float*)d_in[8];
    const float* sp_o2   = (const float*)d_in[9];
    const float* sp_w3   = (const float*)d_in[10];
    const float* sp_b3   = (const float*)d_in[11];
    const float* sp_s3   = (const float*)d_in[12];
    const float* sp_o3   = (const float*)d_in[13];
    const float* off_w   = (const float*)d_in[14];
    const float* off_b   = (const float*)d_in[15];
    const float* dcoff_w = (const float*)d_in[16];
    const float* dcoff_b = (const float*)d_in[17];
    const float* dc_w    = (const float*)d_in[18];
    const float* m_w     = (const float*)d_in[19];
    const float* m_b     = (const float*)d_in[20];
    const float* weight  = (const float*)d_in[21];
    const float* bias    = (const float*)d_in[22];

    float *h1, *h2, *h3, *feat, *off, *mask, *b36;
    unsigned *Af, *Ah2, *Al2, *Ah3, *Al3, *Ahdc, *Aldc, *Ah36, *Al36;
    cudaGetSymbolAddress((void**)&h1,   g_h1);
    cudaGetSymbolAddress((void**)&h2,   g_h2);
    cudaGetSymbolAddress((void**)&h3,   g_h3);
    cudaGetSymbolAddress((void**)&feat, g_feat);
    cudaGetSymbolAddress((void**)&off,  g_off);
    cudaGetSymbolAddress((void**)&mask, g_mask);
    cudaGetSymbolAddress((void**)&b36,  g_b36);
    cudaGetSymbolAddress((void**)&Af,   g_Af);
    cudaGetSymbolAddress((void**)&Ah2,  g_Ah2);
    cudaGetSymbolAddress((void**)&Al2,  g_Al2);
    cudaGetSymbolAddress((void**)&Ah3,  g_Ah3);
    cudaGetSymbolAddress((void**)&Al3,  g_Al3);
    cudaGetSymbolAddress((void**)&Ahdc, g_Ahdc);
    cudaGetSymbolAddress((void**)&Aldc, g_Aldc);
    cudaGetSymbolAddress((void**)&Ah36, g_Ah36);
    cudaGetSymbolAddress((void**)&Al36, g_Al36);

    auto tgrid = [](int n) { return (n + 255) / 256; };
    dim3 grid(64, BATCH);

    // order: conv_mma(sp2) at launch index 3 (where ncu has been sampling)
    prep_mid_f16<<<tgrid(64 * 576), 256>>>(sp_w2, Ah2, Al2, 64);                 // 0
    prep_mid_f16<<<tgrid(64 * 576), 256>>>(sp_w3, Ah3, Al3, 64);                 // 1
    sp1_kernel<<<grid, 256>>>(S, sp_w1, sp_b1, sp_s1, sp_o1, h1);                // 2
    conv_mma<false, 1><<<grid, 256>>>(h1, Ah2, Al2, nullptr, 0,
                                      sp_b2, sp_s2, sp_o2, h2, 64);              // 3 <- ncu
    conv_mma<false, 1><<<grid, 256>>>(h2, Ah3, Al3, nullptr, 0,
                                      sp_b3, sp_s3, sp_o3, h3, 64);              // 4
    prep_w36_f16<<<tgrid(64 * 576), 256>>>(off_w, dcoff_w, Ah36, Al36);          // 5
    concat_bias36<<<1, 36>>>(off_b, dcoff_b, b36);                               // 6
    prep_mid_f16<<<tgrid(64 * 576), 256>>>(dc_w, Ahdc, Aldc, 64);                // 7
    conv_mma<false, 2><<<grid, 256>>>(h3, Ah36, Al36, nullptr, 0,
                                      b36, nullptr, nullptr, off, 36);           // 8
    conv_mma<true, 0><<<grid, 256>>>(h3, Ahdc, Aldc, off + 18 * HW, 36 * HW,
                                     nullptr, nullptr, nullptr, feat, 64);       // 9
    mask_kernel<<<(BATCH * HW + 255) / 256, 256>>>(feat, m_w, m_b, mask);        // 10
    prep_final_f16<<<tgrid(256 * 2304), 256>>>(weight, Af);                      // 11
    dcn_final_f16<<<grid, 256>>>(x, Af, off, mask, bias, (float*)d_out);         // 12
}

// round 6
// speedup vs baseline: 3.7525x; 1.1237x over previous
#include <cuda_runtime.h>
#include <cuda_fp16.h>
#include <math.h>
#include <stdint.h>

#define HW 4096     // 64*64
#define BATCH 8

// ---------------- scratch (static device globals; no allocation) ----------------
__device__ float g_h1  [BATCH*64*HW];
__device__ float g_h2  [BATCH*64*HW];
__device__ float g_h3  [BATCH*64*HW];
__device__ float g_feat[BATCH*64*HW];
__device__ float g_off [BATCH*36*HW];   // ch 0..17 = offset, 18..35 = dc_off
__device__ float g_mask[BATCH*9*HW];
__device__ float g_b36 [36];

// f16 fragment-packed weights (each u32 = 2 f16 along K)
// final: [144 kc16][16 mt][32 lane][4 reg]
__device__ unsigned g_Af[144*16*32*4];
// mids: [36 kc16][4 mt][32 lane][4 reg], hi + lo per layer
#define MIDA (36*4*32*4)
__device__ unsigned g_Ah2 [MIDA], g_Al2 [MIDA];   // shift-order (tap-major)
__device__ unsigned g_Ah3 [MIDA], g_Al3 [MIDA];   // shift-order
__device__ unsigned g_Ah36[MIDA], g_Al36[MIDA];   // shift-order
__device__ unsigned g_Ahdc[MIDA], g_Aldc[MIDA];   // gather-order (K=c*9+kk)

// ---------------- helpers ------------------------------------------------------------
__device__ __forceinline__ void mma_f16(float* acc, unsigned a0, unsigned a1,
                                        unsigned a2, unsigned a3,
                                        unsigned b0, unsigned b1) {
    asm volatile(
        "mma.sync.aligned.m16n8k16.row.col.f32.f16.f16.f32 "
        "{%0,%1,%2,%3}, {%4,%5,%6,%7}, {%8,%9}, {%0,%1,%2,%3};"
        : "+f"(acc[0]), "+f"(acc[1]), "+f"(acc[2]), "+f"(acc[3])
        : "r"(a0), "r"(a1), "r"(a2), "r"(a3), "r"(b0), "r"(b1));
}

__device__ __forceinline__ void frag_coords(int om, int kk, int& lane, int& reg, int& half) {
    int kpair = kk >> 1;
    half = kk & 1;
    lane = (om & 7) * 4 + (kpair & 3);
    reg = (om >> 3) + ((kpair >> 2) << 1);
}

__device__ __forceinline__ unsigned pack_h2(__half lo, __half hi) {
    return (unsigned)__half_as_ushort(lo) | ((unsigned)__half_as_ushort(hi) << 16);
}

// ---------------- weight prep kernels -------------------------------------------------
// gather-order (for dcn_mid deform): K = c*9+kk
__global__ void prep_mid_f16(const float* __restrict__ w, unsigned* __restrict__ hi,
                             unsigned* __restrict__ lo, int O) {
    int i = blockIdx.x * blockDim.x + threadIdx.x;
    if (i >= 64 * 576) return;
    int K = i % 576;
    int o = i / 576;
    float v = (o < O) ? w[o * 576 + K] : 0.0f;
    __half vh = __float2half(v);
    __half vl = __float2half(v - __half2float(vh));
    int kc = K >> 4, kk = K & 15;
    int lane, reg, half;
    frag_coords(o & 15, kk, lane, reg, half);
    size_t base = ((((size_t)kc * 4 + (o >> 4)) * 32 + lane) * 4 + reg) * 2 + half;
    ((__half*)hi)[base] = vh;
    ((__half*)lo)[base] = vl;
}

// shift-order (for conv_shift): kcg = (slab*9 + tap)*2 + (c_local>>4), k-within = c_local&15
__global__ void prep_shift_f16(const float* __restrict__ w, unsigned* __restrict__ hi,
                               unsigned* __restrict__ lo, int O) {
    int i = blockIdx.x * blockDim.x + threadIdx.x;
    if (i >= 64 * 576) return;
    int K = i % 576;
    int o = i / 576;
    float v = (o < O) ? w[o * 576 + K] : 0.0f;
    __half vh = __float2half(v);
    __half vl = __float2half(v - __half2float(vh));
    int c = K / 9, kk = K % 9;
    int slab = c >> 5, cl = c & 31;
    int kcg = (slab * 9 + kk) * 2 + (cl >> 4);
    int lane, reg, half;
    frag_coords(o & 15, cl & 15, lane, reg, half);
    size_t base = ((((size_t)kcg * 4 + (o >> 4)) * 32 + lane) * 4 + reg) * 2 + half;
    ((__half*)hi)[base] = vh;
    ((__half*)lo)[base] = vl;
}

// fused 36-ch shift-order (off rows 0..17, dc_off rows 18..35, zero pad to 64)
__global__ void prep_shift_w36(const float* __restrict__ wa, const float* __restrict__ wb,
                               unsigned* __restrict__ hi, unsigned* __restrict__ lo) {
    int i = blockIdx.x * blockDim.x + threadIdx.x;
    if (i >= 64 * 576) return;
    int K = i % 576;
    int o = i / 576;
    float v = 0.0f;
    if (o < 18) v = wa[o * 576 + K];
    else if (o < 36) v = wb[(o - 18) * 576 + K];
    __half vh = __float2half(v);
    __half vl = __float2half(v - __half2float(vh));
    int c = K / 9, kk = K % 9;
    int slab = c >> 5, cl = c & 31;
    int kcg = (slab * 9 + kk) * 2 + (cl >> 4);
    int lane, reg, half;
    frag_coords(o & 15, cl & 15, lane, reg, half);
    size_t base = ((((size_t)kcg * 4 + (o >> 4)) * 32 + lane) * 4 + reg) * 2 + half;
    ((__half*)hi)[base] = vh;
    ((__half*)lo)[base] = vl;
}

// final: w[256][2304], gather-order single f16
__global__ void prep_final_f16(const float* __restrict__ w, unsigned* __restrict__ dst) {
    int i = blockIdx.x * blockDim.x + threadIdx.x;
    if (i >= 256 * 2304) return;
    int K = i % 2304;
    int o = i / 2304;
    int kc = K >> 4, kk = K & 15;
    int lane, reg, half;
    frag_coords(o & 15, kk, lane, reg, half);
    size_t base = ((((size_t)kc * 16 + (o >> 4)) * 32 + lane) * 4 + reg) * 2 + half;
    ((__half*)dst)[base] = __float2half(w[i]);
}

__global__ void concat_bias36(const float* __restrict__ a, const float* __restrict__ b,
                              float* __restrict__ dst) {
    int i = threadIdx.x;
    if (i < 18) dst[i] = a[i];
    else if (i < 36) dst[i] = b[i - 18];
}

// ---------------- 1x1 conv + sigmoid -------------------------------------------------
__global__ void mask_kernel(const float* __restrict__ feat, const float* __restrict__ mw,
                            const float* __restrict__ mb, float* __restrict__ mask) {
    int i = blockIdx.x * blockDim.x + threadIdx.x;
    if (i >= BATCH * HW) return;
    int b = i >> 12;
    int pix = i & (HW - 1);
    float acc[9];
#pragma unroll
    for (int o = 0; o < 9; o++) acc[o] = __ldg(mb + o);
    const float* fp = feat + (size_t)b * 64 * HW + pix;
    for (int c = 0; c < 64; c++) {
        float v = __ldg(fp + c * HW);
#pragma unroll
        for (int o = 0; o < 9; o++) acc[o] += v * __ldg(mw + o * 64 + c);
    }
#pragma unroll
    for (int o = 0; o < 9; o++)
        mask[((size_t)b * 9 + o) * HW + pix] = 1.0f / (1.0f + expf(-acc[o]));
}

// ---------------- sp1: fused resize + conv3x3 (CIN=3) + BN + ReLU, fp32 --------------
__device__ __forceinline__ float resize_at(const float* __restrict__ p, int y, int x) {
    const float scale = 127.0f / 63.0f;
    float ys = y * scale, xs = x * scale;
    float fy = floorf(ys), fx = floorf(xs);
    int y0 = (int)fy, x0 = (int)fx;
    int y1 = min(y0 + 1, 127), x1 = min(x0 + 1, 127);
    float wy = ys - fy, wx = xs - fx;
    return p[y0 * 128 + x0] * (1.0f - wy) * (1.0f - wx)
         + p[y0 * 128 + x1] * (1.0f - wy) * wx
         + p[y1 * 128 + x0] * wy * (1.0f - wx)
         + p[y1 * 128 + x1] * wy * wx;
}

__global__ void __launch_bounds__(256)
sp1_kernel(const float* __restrict__ S, const float* __restrict__ w1,
           const float* __restrict__ e_b, const float* __restrict__ e_s,
           const float* __restrict__ e_o, float* __restrict__ out) {
    __shared__ __align__(16) float s_t[576];
    const int b = blockIdx.y;
    const int tile = blockIdx.x;
    const int tid = threadIdx.x;
    const int o = tid & 63;
    const int pbase = (tid >> 6) * 16;

    float acc[16];
#pragma unroll
    for (int j = 0; j < 16; j++) acc[j] = 0.0f;

    for (int c = 0; c < 3; c++) {
        const float* Sc = S + (size_t)(b * 3 + c) * 128 * 128;
        for (int e = tid; e < 576; e += 256) {
            int k = e >> 6, p = e & 63;
            int yy = tile + k / 3 - 1;
            int xx = p + k % 3 - 1;
            s_t[e] = ((unsigned)yy < 64u && (unsigned)xx < 64u)
                         ? resize_at(Sc, yy, xx) : 0.0f;
        }
        __syncthreads();

        float wv[9];
#pragma unroll
        for (int k = 0; k < 9; k++) wv[k] = __ldg(w1 + o * 27 + c * 9 + k);

#pragma unroll
        for (int k = 0; k < 9; k++) {
            const float4* sp = reinterpret_cast<const float4*>(s_t + k * 64 + pbase);
#pragma unroll
            for (int j4 = 0; j4 < 4; j4++) {
                float4 sv = sp[j4];
                acc[j4 * 4 + 0] += wv[k] * sv.x;
                acc[j4 * 4 + 1] += wv[k] * sv.y;
                acc[j4 * 4 + 2] += wv[k] * sv.z;
                acc[j4 * 4 + 3] += wv[k] * sv.w;
            }
        }
        __syncthreads();
    }

    float bb = __ldg(e_b + o), ssc = __ldg(e_s + o), oof = __ldg(e_o + o);
    float* op = out + ((size_t)b * 64 + o) * HW + tile * 64 + pbase;
#pragma unroll
    for (int j = 0; j < 16; j++)
        op[j] = fmaxf((acc[j] + bb) * ssc + oof, 0.0f);
}

// ---------------- plain conv3x3 via shifted-window mma (CIN=64, M=64 pad, N=64) ------
// Raw channel tile in SMEM (no tap materialization); 9 mma passes with offset B ptrs.
// EPI: 1=relu((acc+b)*s+o), 2=acc+b
template <int EPI>
__global__ void __launch_bounds__(256)
conv_shift(const float* __restrict__ inp,
           const unsigned* __restrict__ Ahi, const unsigned* __restrict__ Alo,
           const float* __restrict__ e_b, const float* __restrict__ e_s,
           const float* __restrict__ e_o, float* __restrict__ out, int Oact) {
    __shared__ unsigned s_bh[3 * 16 * 72], s_bl[3 * 16 * 72];

    const int b = blockIdx.y;
    const int tile = blockIdx.x;       // image row
    const int tid = threadIdx.x;
    const int warp = tid >> 5;
    const int lane = tid & 31;
    const int mt = warp >> 1;
    const int nh = warp & 1;

    float acc[4][4];
#pragma unroll
    for (int nt = 0; nt < 4; nt++)
#pragma unroll
        for (int r = 0; r < 4; r++) acc[nt][r] = 0.0f;

    const float* xb = inp + (size_t)b * 64 * HW;

    for (int slab = 0; slab < 2; slab++) {
        if (slab) __syncthreads();
        // fill raw tile: 3 rows x 16 channel-pairs x 66 cols (col = px+1)
        for (int e = tid; e < 3168; e += 256) {
            int r = e / 1056;
            int rem = e - r * 1056;
            int cp = rem / 66;
            int col = rem - cp * 66;
            int yy = tile - 1 + r;
            int px = col - 1;
            bool ok = ((unsigned)yy < 64u) && ((unsigned)px < 64u);
            const float* p0 = xb + (size_t)(slab * 32 + cp * 2) * HW + yy * 64 + px;
            float v0 = ok ? __ldg(p0) : 0.0f;
            float v1 = ok ? __ldg(p0 + HW) : 0.0f;
            __half h0 = __float2half(v0), h1 = __float2half(v1);
            __half l0 = __float2half(v0 - __half2float(h0));
            __half l1 = __float2half(v1 - __half2float(h1));
            int idx = (r * 16 + cp) * 72 + col;
            s_bh[idx] = pack_h2(h0, h1);
            s_bl[idx] = pack_h2(l0, l1);
        }
        __syncthreads();

#pragma unroll
        for (int t = 0; t < 9; t++) {
            const int dy = t / 3, dx = t % 3;
            const unsigned* rbh = s_bh + dy * 16 * 72;
            const unsigned* rbl = s_bl + dy * 16 * 72;
#pragma unroll
            for (int kcl = 0; kcl < 2; kcl++) {
                int kcg = (slab * 9 + t) * 2 + kcl;
                uint4 Ah = __ldg((const uint4*)(Ahi + (((size_t)kcg * 4 + mt) * 32 + lane) * 4));
                uint4 Al = __ldg((const uint4*)(Alo + (((size_t)kcg * 4 + mt) * 32 + lane) * 4));
                int boff = (kcl * 8 + (lane & 3)) * 72 + (lane >> 2) + nh * 32 + dx;
                const unsigned* bh = rbh + boff;
                const unsigned* bl = rbl + boff;
#pragma unroll
                for (int nt = 0; nt < 4; nt++) {
                    unsigned b0h = bh[nt * 8], b1h = bh[nt * 8 + 4 * 72];
                    unsigned b0l = bl[nt * 8], b1l = bl[nt * 8 + 4 * 72];
                    mma_f16(acc[nt], Ah.x, Ah.y, Ah.z, Ah.w, b0h, b1h);
                    mma_f16(acc[nt], Ah.x, Ah.y, Ah.z, Ah.w, b0l, b1l);
                    mma_f16(acc[nt], Al.x, Al.y, Al.z, Al.w, b0h, b1h);
                }
            }
        }
    }

    // epilogue
    int o = mt * 16 + (lane >> 2);
    float b0 = 0, s0 = 1, f0 = 0, b1 = 0, s1 = 1, f1 = 0;
    if (EPI == 1) {
        if (o < Oact)     { b0 = __ldg(e_b + o);     s0 = __ldg(e_s + o);     f0 = __ldg(e_o + o); }
        if (o + 8 < Oact) { b1 = __ldg(e_b + o + 8); s1 = __ldg(e_s + o + 8); f1 = __ldg(e_o + o + 8); }
    } else if (EPI == 2) {
        if (o < Oact)     b0 = __ldg(e_b + o);
        if (o + 8 < Oact) b1 = __ldg(e_b + o + 8);
    }
    int colb = tile * 64 + nh * 32 + (lane & 3) * 2;
    float* o0 = out + ((size_t)b * Oact + o) * HW + colb;
    float* o1 = o0 + 8 * HW;
#pragma unroll
    for (int nt = 0; nt < 4; nt++) {
        float v0a = acc[nt][0], v0b = acc[nt][1];
        float v1a = acc[nt][2], v1b = acc[nt][3];
        if (EPI == 1) {
            v0a = fmaxf((v0a + b0) * s0 + f0, 0.0f);
            v0b = fmaxf((v0b + b0) * s0 + f0, 0.0f);
            v1a = fmaxf((v1a + b1) * s1 + f1, 0.0f);
            v1b = fmaxf((v1b + b1) * s1 + f1, 0.0f);
        } else if (EPI == 2) {
            v0a += b0; v0b += b0; v1a += b1; v1b += b1;
        }
        if (o < Oact)
            *reinterpret_cast<float2*>(o0 + nt * 8) = make_float2(v0a, v0b);
        if (o + 8 < Oact)
            *reinterpret_cast<float2*>(o1 + nt * 8) = make_float2(v1a, v1b);
    }
}

// ---------------- DCNv1 mid conv (deform gather), 3-term f16 -------------------------
__global__ void __launch_bounds__(256)
dcn_mid(const float* __restrict__ inp,
        const unsigned* __restrict__ Ahi, const unsigned* __restrict__ Alo,
        const float* __restrict__ offs, int offBS, float* __restrict__ out) {
    __shared__ unsigned s_bh[32 * 72], s_bl[32 * 72];
    __shared__ int2 s_ii[576];
    __shared__ float4 s_ww[576];

    const int b = blockIdx.y;
    const int tile = blockIdx.x;
    const int tid = threadIdx.x;
    const int warp = tid >> 5;
    const int lane = tid & 31;
    const int mt = warp >> 1;
    const int nh = warp & 1;

    for (int e = tid; e < 576; e += 256) {
        int k = e >> 6, p = e & 63;
        int pix = tile * 64 + p;
        float py = (float)(tile - 1 + k / 3)
                 + offs[(size_t)b * offBS + (2 * k) * HW + pix];
        float px = (float)(p - 1 + k % 3)
                 + offs[(size_t)b * offBS + (2 * k + 1) * HW + pix];
        float fy = floorf(py), fx = floorf(px);
        int iy = (int)fy, ix = (int)fx;
        float ay = py - fy, ax = px - fx;
        bool vy0 = (iy >= 0) && (iy < 64);
        bool vy1 = (iy >= -1) && (iy < 63);
        bool vx0 = (ix >= 0) && (ix < 64);
        bool vx1 = (ix >= -1) && (ix < 63);
        int cy0 = min(max(iy, 0), 63), cy1 = min(max(iy + 1, 0), 63);
        int cx0 = min(max(ix, 0), 63), cx1 = min(max(ix + 1, 0), 63);
        int xb = min(max(ix, 0), 62);
        float wAx = 0.0f, wBx = 0.0f;
        if (vx0) { if (cx0 == xb) wAx += 1.0f - ax; else wBx += 1.0f - ax; }
        if (vx1) { if (cx1 == xb) wAx += ax; else wBx += ax; }
        float w0 = vy0 ? (1.0f - ay) : 0.0f;
        float w1 = vy1 ? ay : 0.0f;
        s_ii[e] = make_int2(cy0 * 64 + xb, cy1 * 64 + xb);
        s_ww[e] = make_float4(w0 * wAx, w0 * wBx, w1 * wAx, w1 * wBx);
    }
    __syncthreads();

    float acc[4][4];
#pragma unroll
    for (int nt = 0; nt < 4; nt++)
#pragma unroll
        for (int r = 0; r < 4; r++) acc[nt][r] = 0.0f;

    const float* xb_ptr = inp + (size_t)b * 64 * HW;
    const int p = tid & 63;
    const int j0 = tid >> 6;
    const int jh0 = j0 >> 1, jpar = j0 & 1;
    int c0 = 0, kk0 = j0;              // K0 = slab*64 + j0, tracked incrementally

    for (int slab = 0; slab < 9; slab++) {
        const float* xc = xb_ptr + (size_t)c0 * HW;
        int kk = kk0;
#pragma unroll
        for (int i = 0; i < 16; i++) {
            int r = kk * 64 + p;
            int2 ii = s_ii[r];
            float4 w4 = s_ww[r];
            float v = w4.x * __ldg(xc + ii.x) + w4.y * __ldg(xc + ii.x + 1)
                    + w4.z * __ldg(xc + ii.y) + w4.w * __ldg(xc + ii.y + 1);
            __half vh = __float2half(v);
            __half vl = __float2half(v - __half2float(vh));
            int idx = ((jh0 + 2 * i) * 72 + p) * 2 + jpar;
            ((__half*)s_bh)[idx] = vh;
            ((__half*)s_bl)[idx] = vl;
            kk += 4;
            if (kk >= 9) { kk -= 9; xc += HW; }
        }
        kk0 += 1; c0 += 7;
        if (kk0 >= 9) { kk0 -= 9; c0++; }
        __syncthreads();

#pragma unroll
        for (int kc = 0; kc < 4; kc++) {
            int kcg = slab * 4 + kc;
            uint4 Ah = __ldg((const uint4*)(Ahi + (((size_t)kcg * 4 + mt) * 32 + lane) * 4));
            uint4 Al = __ldg((const uint4*)(Alo + (((size_t)kcg * 4 + mt) * 32 + lane) * 4));
            int boff = (kc * 8 + (lane & 3)) * 72 + (lane >> 2) + nh * 32;
            const unsigned* bhp = s_bh + boff;
            const unsigned* blp = s_bl + boff;
#pragma unroll
            for (int nt = 0; nt < 4; nt++) {
                unsigned b0h = bhp[nt * 8], b1h = bhp[nt * 8 + 4 * 72];
                unsigned b0l = blp[nt * 8], b1l = blp[nt * 8 + 4 * 72];
                mma_f16(acc[nt], Ah.x, Ah.y, Ah.z, Ah.w, b0h, b1h);
                mma_f16(acc[nt], Ah.x, Ah.y, Ah.z, Ah.w, b0l, b1l);
                mma_f16(acc[nt], Al.x, Al.y, Al.z, Al.w, b0h, b1h);
            }
        }
        __syncthreads();
    }

    int o = mt * 16 + (lane >> 2);
    int colb = tile * 64 + nh * 32 + (lane & 3) * 2;
    float* o0 = out + ((size_t)b * 64 + o) * HW + colb;
    float* o1 = o0 + 8 * HW;
#pragma unroll
    for (int nt = 0; nt < 4; nt++) {
        *reinterpret_cast<float2*>(o0 + nt * 8) = make_float2(acc[nt][0], acc[nt][1]);
        *reinterpret_cast<float2*>(o1 + nt * 8) = make_float2(acc[nt][2], acc[nt][3]);
    }
}

// ---------------- final modulated DCNv2 (256->256), single-pass f16 mma --------------
__global__ void __launch_bounds__(256)
dcn_final_f16(const float* __restrict__ x, const unsigned* __restrict__ Af,
              const float* __restrict__ offs, const float* __restrict__ msk,
              const float* __restrict__ bias, float* __restrict__ out) {
    __shared__ unsigned s_b[32 * 72];
    __shared__ int2 s_ii[576];
    __shared__ float4 s_ww[576];

    const int b = blockIdx.y;
    const int tile = blockIdx.x;
    const int tid = threadIdx.x;
    const int warp = tid >> 5;
    const int lane = tid & 31;

    for (int e = tid; e < 576; e += 256) {
        int k = e >> 6, p = e & 63;
        int pix = tile * 64 + p;
        float py = (float)(tile - 1 + k / 3) + offs[(size_t)b * 36 * HW + (2 * k) * HW + pix];
        float px = (float)(p - 1 + k % 3) + offs[(size_t)b * 36 * HW + (2 * k + 1) * HW + pix];
        float m = msk[(size_t)b * 9 * HW + k * HW + pix];
        float fy = floorf(py), fx = floorf(px);
        int iy = (int)fy, ix = (int)fx;
        float ay = py - fy, ax = px - fx;
        bool vy0 = (iy >= 0) && (iy < 64);
        bool vy1 = (iy >= -1) && (iy < 63);
        bool vx0 = (ix >= 0) && (ix < 64);
        bool vx1 = (ix >= -1) && (ix < 63);
        int cy0 = min(max(iy, 0), 63), cy1 = min(max(iy + 1, 0), 63);
        int cx0 = min(max(ix, 0), 63), cx1 = min(max(ix + 1, 0), 63);
        int xb = min(max(ix, 0), 62);
        float wAx = 0.0f, wBx = 0.0f;
        if (vx0) { if (cx0 == xb) wAx += 1.0f - ax; else wBx += 1.0f - ax; }
        if (vx1) { if (cx1 == xb) wAx += ax; else wBx += ax; }
        float w0 = vy0 ? (1.0f - ay) * m : 0.0f;
        float w1 = vy1 ? ay * m : 0.0f;
        s_ii[e] = make_int2(cy0 * 64 + xb, cy1 * 64 + xb);
        s_ww[e] = make_float4(w0 * wAx, w0 * wBx, w1 * wAx, w1 * wBx);
    }
    __syncthreads();

    float acc[2][8][4];
#pragma unroll
    for (int mtl = 0; mtl < 2; mtl++)
#pragma unroll
        for (int nt = 0; nt < 8; nt++)
#pragma unroll
            for (int r = 0; r < 4; r++) acc[mtl][nt][r] = 0.0f;

    const float* xb_ptr = x + (size_t)b * 256 * HW;
    const int p = tid & 63;
    const int j0 = tid >> 6;
    const int jh0 = j0 >> 1, jpar = j0 & 1;
    int c0 = 0, kk0 = j0;

    for (int slab = 0; slab < 36; slab++) {
        const float* xc = xb_ptr + (size_t)c0 * HW;
        int kk = kk0;
#pragma unroll
        for (int i = 0; i < 16; i++) {
            int r = kk * 64 + p;
            int2 ii = s_ii[r];
            float4 w4 = s_ww[r];
            float v = w4.x * __ldg(xc + ii.x) + w4.y * __ldg(xc + ii.x + 1)
                    + w4.z * __ldg(xc + ii.y) + w4.w * __ldg(xc + ii.y + 1);
            ((__half*)s_b)[((jh0 + 2 * i) * 72 + p) * 2 + jpar] = __float2half(v);
            kk += 4;
            if (kk >= 9) { kk -= 9; xc += HW; }
        }
        kk0 += 1; c0 += 7;
        if (kk0 >= 9) { kk0 -= 9; c0++; }
        __syncthreads();

#pragma unroll
        for (int kc = 0; kc < 4; kc++) {
            int kcg = slab * 4 + kc;
            const unsigned* ap = Af + (((size_t)kcg * 16 + warp * 2) * 32 + lane) * 4;
            uint4 A0 = __ldg((const uint4*)ap);
            uint4 A1 = __ldg((const uint4*)(ap + 128));

            const unsigned* bp = s_b + (kc * 8 + (lane & 3)) * 72 + (lane >> 2);
#pragma unroll
            for (int nt = 0; nt < 8; nt++) {
                unsigned b0 = bp[nt * 8], b1 = bp[nt * 8 + 4 * 72];
                mma_f16(acc[0][nt], A0.x, A0.y, A0.z, A0.w, b0, b1);
                mma_f16(acc[1][nt], A1.x, A1.y, A1.z, A1.w, b0, b1);
            }
        }
        __syncthreads();
    }

#pragma unroll
    for (int mtl = 0; mtl < 2; mtl++) {
        int o = warp * 32 + mtl * 16 + (lane >> 2);
        float b_lo = __ldg(bias + o);
        float b_hi = __ldg(bias + o + 8);
        float* o0 = out + ((size_t)b * 256 + o) * HW + tile * 64 + (lane & 3) * 2;
        float* o1 = o0 + 8 * HW;
#pragma unroll
        for (int nt = 0; nt < 8; nt++) {
            *reinterpret_cast<float2*>(o0 + nt * 8) =
                make_float2(acc[mtl][nt][0] + b_lo, acc[mtl][nt][1] + b_lo);
            *reinterpret_cast<float2*>(o1 + nt * 8) =
                make_float2(acc[mtl][nt][2] + b_hi, acc[mtl][nt][3] + b_hi);
        }
    }
}

// ---------------- host launcher ------------------------------------------------------
extern "C" void kernel_launch(void* const* d_in, const int* in_sizes, int n_in,
                              void* d_out, int out_size) {
    const float* x       = (const float*)d_in[0];
    const float* S       = (const float*)d_in[1];
    const float* sp_w1   = (const float*)d_in[2];
    const float* sp_b1   = (const float*)d_in[3];
    const float* sp_s1   = (const float*)d_in[4];
    const float* sp_o1   = (const float*)d_in[5];
    const float* sp_w2   = (const float*)d_in[6];
    const float* sp_b2   = (const float*)d_in[7];
    const float* sp_s2   = (const float*)d_in[8];
    const float* sp_o2   = (const float*)d_in[9];
    const float* sp_w3   = (const float*)d_in[10];
    const float* sp_b3   = (const float*)d_in[11];
    const float* sp_s3   = (const float*)d_in[12];
    const float* sp_o3   = (const float*)d_in[13];
    const float* off_w   = (const float*)d_in[14];
    const float* off_b   = (const float*)d_in[15];
    const float* dcoff_w = (const float*)d_in[16];
    const float* dcoff_b = (const float*)d_in[17];
    const float* dc_w    = (const float*)d_in[18];
    const float* m_w     = (const float*)d_in[19];
    const float* m_b     = (const float*)d_in[20];
    const float* weight  = (const float*)d_in[21];
    const float* bias    = (const float*)d_in[22];

    float *h1, *h2, *h3, *feat, *off, *mask, *b36;
    unsigned *Af, *Ah2, *Al2, *Ah3, *Al3, *Ahdc, *Aldc, *Ah36, *Al36;
    cudaGetSymbolAddress((void**)&h1,   g_h1);
    cudaGetSymbolAddress((void**)&h2,   g_h2);
    cudaGetSymbolAddress((void**)&h3,   g_h3);
    cudaGetSymbolAddress((void**)&feat, g_feat);
    cudaGetSymbolAddress((void**)&off,  g_off);
    cudaGetSymbolAddress((void**)&mask, g_mask);
    cudaGetSymbolAddress((void**)&b36,  g_b36);
    cudaGetSymbolAddress((void**)&Af,   g_Af);
    cudaGetSymbolAddress((void**)&Ah2,  g_Ah2);
    cudaGetSymbolAddress((void**)&Al2,  g_Al2);
    cudaGetSymbolAddress((void**)&Ah3,  g_Ah3);
    cudaGetSymbolAddress((void**)&Al3,  g_Al3);
    cudaGetSymbolAddress((void**)&Ahdc, g_Ahdc);
    cudaGetSymbolAddress((void**)&Aldc, g_Aldc);
    cudaGetSymbolAddress((void**)&Ah36, g_Ah36);
    cudaGetSymbolAddress((void**)&Al36, g_Al36);

    auto tgrid = [](int n) { return (n + 255) / 256; };
    dim3 grid(64, BATCH);

    prep_shift_f16<<<tgrid(64 * 576), 256>>>(sp_w2, Ah2, Al2, 64);               // 0
    prep_shift_f16<<<tgrid(64 * 576), 256>>>(sp_w3, Ah3, Al3, 64);               // 1
    sp1_kernel<<<grid, 256>>>(S, sp_w1, sp_b1, sp_s1, sp_o1, h1);                // 2
    conv_shift<1><<<grid, 256>>>(h1, Ah2, Al2, sp_b2, sp_s2, sp_o2, h2, 64);     // 3 <- ncu
    conv_shift<1><<<grid, 256>>>(h2, Ah3, Al3, sp_b3, sp_s3, sp_o3, h3, 64);     // 4
    prep_shift_w36<<<tgrid(64 * 576), 256>>>(off_w, dcoff_w, Ah36, Al36);        // 5
    concat_bias36<<<1, 36>>>(off_b, dcoff_b, b36);                               // 6
    prep_mid_f16<<<tgrid(64 * 576), 256>>>(dc_w, Ahdc, Aldc, 64);                // 7
    conv_shift<2><<<grid, 256>>>(h3, Ah36, Al36, b36, nullptr, nullptr, off, 36);// 8
    dcn_mid<<<grid, 256>>>(h3, Ahdc, Aldc, off + 18 * HW, 36 * HW, feat);        // 9
    mask_kernel<<<(BATCH * HW + 255) / 256, 256>>>(feat, m_w, m_b, mask);        // 10
    prep_final_f16<<<tgrid(256 * 2304), 256>>>(weight, Af);                      // 11
    dcn_final_f16<<<grid, 256>>>(x, Af, off, mask, bias, (float*)d_out);         // 12
}

// round 7
// speedup vs baseline: 3.8389x; 1.0230x over previous
#include <cuda_runtime.h>
#include <cuda_fp16.h>
#include <math.h>
#include <stdint.h>

#define HW 4096     // 64*64
#define BATCH 8

// ---------------- scratch (static device globals; no allocation) ----------------
__device__ float g_h1  [BATCH*64*HW];
__device__ float g_h2  [BATCH*64*HW];
__device__ float g_h3  [BATCH*64*HW];
__device__ float g_feat[BATCH*64*HW];
__device__ float g_off [BATCH*36*HW];   // ch 0..17 = offset, 18..35 = dc_off
__device__ float g_mask[BATCH*9*HW];
__device__ float g_b36 [36];

// f16 fragment-packed weights (each u32 = 2 f16 along K)
__device__ unsigned g_Af[144*16*32*4];
#define MIDA (36*4*32*4)
__device__ unsigned g_Ah2 [MIDA], g_Al2 [MIDA];   // shift-order
__device__ unsigned g_Ah3 [MIDA], g_Al3 [MIDA];   // shift-order
__device__ unsigned g_Ah36[MIDA], g_Al36[MIDA];   // shift-order
__device__ unsigned g_Ahdc[MIDA], g_Aldc[MIDA];   // gather-order (K=c*9+kk)

// ---------------- helpers ------------------------------------------------------------
__device__ __forceinline__ void mma_f16(float* acc, unsigned a0, unsigned a1,
                                        unsigned a2, unsigned a3,
                                        unsigned b0, unsigned b1) {
    asm volatile(
        "mma.sync.aligned.m16n8k16.row.col.f32.f16.f16.f32 "
        "{%0,%1,%2,%3}, {%4,%5,%6,%7}, {%8,%9}, {%0,%1,%2,%3};"
        : "+f"(acc[0]), "+f"(acc[1]), "+f"(acc[2]), "+f"(acc[3])
        : "r"(a0), "r"(a1), "r"(a2), "r"(a3), "r"(b0), "r"(b1));
}

__device__ __forceinline__ void frag_coords(int om, int kk, int& lane, int& reg, int& half) {
    int kpair = kk >> 1;
    half = kk & 1;
    lane = (om & 7) * 4 + (kpair & 3);
    reg = (om >> 3) + ((kpair >> 2) << 1);
}

__device__ __forceinline__ unsigned pack_h2(__half lo, __half hi) {
    return (unsigned)__half_as_ushort(lo) | ((unsigned)__half_as_ushort(hi) << 16);
}

// ---------------- weight prep kernels -------------------------------------------------
__global__ void prep_mid_f16(const float* __restrict__ w, unsigned* __restrict__ hi,
                             unsigned* __restrict__ lo, int O) {
    int i = blockIdx.x * blockDim.x + threadIdx.x;
    if (i >= 64 * 576) return;
    int K = i % 576;
    int o = i / 576;
    float v = (o < O) ? w[o * 576 + K] : 0.0f;
    __half vh = __float2half(v);
    __half vl = __float2half(v - __half2float(vh));
    int kc = K >> 4, kk = K & 15;
    int lane, reg, half;
    frag_coords(o & 15, kk, lane, reg, half);
    size_t base = ((((size_t)kc * 4 + (o >> 4)) * 32 + lane) * 4 + reg) * 2 + half;
    ((__half*)hi)[base] = vh;
    ((__half*)lo)[base] = vl;
}

__global__ void prep_shift_f16(const float* __restrict__ w, unsigned* __restrict__ hi,
                               unsigned* __restrict__ lo, int O) {
    int i = blockIdx.x * blockDim.x + threadIdx.x;
    if (i >= 64 * 576) return;
    int K = i % 576;
    int o = i / 576;
    float v = (o < O) ? w[o * 576 + K] : 0.0f;
    __half vh = __float2half(v);
    __half vl = __float2half(v - __half2float(vh));
    int c = K / 9, kk = K % 9;
    int slab = c >> 5, cl = c & 31;
    int kcg = (slab * 9 + kk) * 2 + (cl >> 4);
    int lane, reg, half;
    frag_coords(o & 15, cl & 15, lane, reg, half);
    size_t base = ((((size_t)kcg * 4 + (o >> 4)) * 32 + lane) * 4 + reg) * 2 + half;
    ((__half*)hi)[base] = vh;
    ((__half*)lo)[base] = vl;
}

__global__ void prep_shift_w36(const float* __restrict__ wa, const float* __restrict__ wb,
                               unsigned* __restrict__ hi, unsigned* __restrict__ lo) {
    int i = blockIdx.x * blockDim.x + threadIdx.x;
    if (i >= 64 * 576) return;
    int K = i % 576;
    int o = i / 576;
    float v = 0.0f;
    if (o < 18) v = wa[o * 576 + K];
    else if (o < 36) v = wb[(o - 18) * 576 + K];
    __half vh = __float2half(v);
    __half vl = __float2half(v - __half2float(vh));
    int c = K / 9, kk = K % 9;
    int slab = c >> 5, cl = c & 31;
    int kcg = (slab * 9 + kk) * 2 + (cl >> 4);
    int lane, reg, half;
    frag_coords(o & 15, cl & 15, lane, reg, half);
    size_t base = ((((size_t)kcg * 4 + (o >> 4)) * 32 + lane) * 4 + reg) * 2 + half;
    ((__half*)hi)[base] = vh;
    ((__half*)lo)[base] = vl;
}

__global__ void prep_final_f16(const float* __restrict__ w, unsigned* __restrict__ dst) {
    int i = blockIdx.x * blockDim.x + threadIdx.x;
    if (i >= 256 * 2304) return;
    int K = i % 2304;
    int o = i / 2304;
    int kc = K >> 4, kk = K & 15;
    int lane, reg, half;
    frag_coords(o & 15, kk, lane, reg, half);
    size_t base = ((((size_t)kc * 16 + (o >> 4)) * 32 + lane) * 4 + reg) * 2 + half;
    ((__half*)dst)[base] = __float2half(w[i]);
}

__global__ void concat_bias36(const float* __restrict__ a, const float* __restrict__ b,
                              float* __restrict__ dst) {
    int i = threadIdx.x;
    if (i < 18) dst[i] = a[i];
    else if (i < 36) dst[i] = b[i - 18];
}

// ---------------- 1x1 conv + sigmoid -------------------------------------------------
__global__ void mask_kernel(const float* __restrict__ feat, const float* __restrict__ mw,
                            const float* __restrict__ mb, float* __restrict__ mask) {
    int i = blockIdx.x * blockDim.x + threadIdx.x;
    if (i >= BATCH * HW) return;
    int b = i >> 12;
    int pix = i & (HW - 1);
    float acc[9];
#pragma unroll
    for (int o = 0; o < 9; o++) acc[o] = __ldg(mb + o);
    const float* fp = feat + (size_t)b * 64 * HW + pix;
    for (int c = 0; c < 64; c++) {
        float v = __ldg(fp + c * HW);
#pragma unroll
        for (int o = 0; o < 9; o++) acc[o] += v * __ldg(mw + o * 64 + c);
    }
#pragma unroll
    for (int o = 0; o < 9; o++)
        mask[((size_t)b * 9 + o) * HW + pix] = 1.0f / (1.0f + expf(-acc[o]));
}

// ---------------- sp1: fused resize + conv3x3 (CIN=3) + BN + ReLU, fp32 --------------
__device__ __forceinline__ float resize_at(const float* __restrict__ p, int y, int x) {
    const float scale = 127.0f / 63.0f;
    float ys = y * scale, xs = x * scale;
    float fy = floorf(ys), fx = floorf(xs);
    int y0 = (int)fy, x0 = (int)fx;
    int y1 = min(y0 + 1, 127), x1 = min(x0 + 1, 127);
    float wy = ys - fy, wx = xs - fx;
    return p[y0 * 128 + x0] * (1.0f - wy) * (1.0f - wx)
         + p[y0 * 128 + x1] * (1.0f - wy) * wx
         + p[y1 * 128 + x0] * wy * (1.0f - wx)
         + p[y1 * 128 + x1] * wy * wx;
}

__global__ void __launch_bounds__(256)
sp1_kernel(const float* __restrict__ S, const float* __restrict__ w1,
           const float* __restrict__ e_b, const float* __restrict__ e_s,
           const float* __restrict__ e_o, float* __restrict__ out) {
    __shared__ __align__(16) float s_t[576];
    const int b = blockIdx.y;
    const int tile = blockIdx.x;
    const int tid = threadIdx.x;
    const int o = tid & 63;
    const int pbase = (tid >> 6) * 16;

    float acc[16];
#pragma unroll
    for (int j = 0; j < 16; j++) acc[j] = 0.0f;

    for (int c = 0; c < 3; c++) {
        const float* Sc = S + (size_t)(b * 3 + c) * 128 * 128;
        for (int e = tid; e < 576; e += 256) {
            int k = e >> 6, p = e & 63;
            int yy = tile + k / 3 - 1;
            int xx = p + k % 3 - 1;
            s_t[e] = ((unsigned)yy < 64u && (unsigned)xx < 64u)
                         ? resize_at(Sc, yy, xx) : 0.0f;
        }
        __syncthreads();

        float wv[9];
#pragma unroll
        for (int k = 0; k < 9; k++) wv[k] = __ldg(w1 + o * 27 + c * 9 + k);

#pragma unroll
        for (int k = 0; k < 9; k++) {
            const float4* sp = reinterpret_cast<const float4*>(s_t + k * 64 + pbase);
#pragma unroll
            for (int j4 = 0; j4 < 4; j4++) {
                float4 sv = sp[j4];
                acc[j4 * 4 + 0] += wv[k] * sv.x;
                acc[j4 * 4 + 1] += wv[k] * sv.y;
                acc[j4 * 4 + 2] += wv[k] * sv.z;
                acc[j4 * 4 + 3] += wv[k] * sv.w;
            }
        }
        __syncthreads();
    }

    float bb = __ldg(e_b + o), ssc = __ldg(e_s + o), oof = __ldg(e_o + o);
    float* op = out + ((size_t)b * 64 + o) * HW + tile * 64 + pbase;
#pragma unroll
    for (int j = 0; j < 16; j++)
        op[j] = fmaxf((acc[j] + bb) * ssc + oof, 0.0f);
}

// ---------------- plain conv3x3 via shifted-window mma, double-buffered --------------
// EPI: 1=relu((acc+b)*s+o), 2=acc+b.  Dynamic SMEM: 2 bufs x (hi+lo) x 3456 u32 = 55296B
template <int EPI>
__global__ void __launch_bounds__(256)
conv_shift(const float* __restrict__ inp,
           const unsigned* __restrict__ Ahi, const unsigned* __restrict__ Alo,
           const float* __restrict__ e_b, const float* __restrict__ e_s,
           const float* __restrict__ e_o, float* __restrict__ out, int Oact) {
    extern __shared__ unsigned csm[];
    unsigned* s_bhA = csm;              // [2][3456]
    unsigned* s_blA = csm + 2 * 3456;   // [2][3456]

    const int b = blockIdx.y;
    const int tile = blockIdx.x;
    const int tid = threadIdx.x;
    const int warp = tid >> 5;
    const int lane = tid & 31;
    const int mt = warp >> 1;
    const int nh = warp & 1;

    float acc[4][4];
#pragma unroll
    for (int nt = 0; nt < 4; nt++)
#pragma unroll
        for (int r = 0; r < 4; r++) acc[nt][r] = 0.0f;

    const float* xb = inp + (size_t)b * 64 * HW;

    auto fill = [&](int slab, int buf) {
        unsigned* bh = s_bhA + buf * 3456;
        unsigned* bl = s_blA + buf * 3456;
        for (int e = tid; e < 3168; e += 256) {
            int r = e / 1056;
            int rem = e - r * 1056;
            int cp = rem / 66;
            int col = rem - cp * 66;
            int yy = tile - 1 + r;
            int px = col - 1;
            bool ok = ((unsigned)yy < 64u) && ((unsigned)px < 64u);
            const float* p0 = xb + (size_t)(slab * 32 + cp * 2) * HW + yy * 64 + px;
            float v0 = ok ? __ldg(p0) : 0.0f;
            float v1 = ok ? __ldg(p0 + HW) : 0.0f;
            __half h0 = __float2half(v0), h1 = __float2half(v1);
            __half l0 = __float2half(v0 - __half2float(h0));
            __half l1 = __float2half(v1 - __half2float(h1));
            int idx = (r * 16 + cp) * 72 + col;
            bh[idx] = pack_h2(h0, h1);
            bl[idx] = pack_h2(l0, l1);
        }
    };

    fill(0, 0);
    __syncthreads();

    for (int slab = 0; slab < 2; slab++) {
        if (slab == 0) fill(1, 1);     // overlap: gather next while mma current
        const unsigned* sbh = s_bhA + slab * 3456;
        const unsigned* sbl = s_blA + slab * 3456;
#pragma unroll
        for (int t = 0; t < 9; t++) {
            const int dy = t / 3, dx = t % 3;
            const unsigned* rbh = sbh + dy * 16 * 72;
            const unsigned* rbl = sbl + dy * 16 * 72;
#pragma unroll
            for (int kcl = 0; kcl < 2; kcl++) {
                int kcg = (slab * 9 + t) * 2 + kcl;
                uint4 Ah = __ldg((const uint4*)(Ahi + (((size_t)kcg * 4 + mt) * 32 + lane) * 4));
                uint4 Al = __ldg((const uint4*)(Alo + (((size_t)kcg * 4 + mt) * 32 + lane) * 4));
                int boff = (kcl * 8 + (lane & 3)) * 72 + (lane >> 2) + nh * 32 + dx;
                const unsigned* bh = rbh + boff;
                const unsigned* bl = rbl + boff;
#pragma unroll
                for (int nt = 0; nt < 4; nt++) {
                    unsigned b0h = bh[nt * 8], b1h = bh[nt * 8 + 4 * 72];
                    unsigned b0l = bl[nt * 8], b1l = bl[nt * 8 + 4 * 72];
                    mma_f16(acc[nt], Ah.x, Ah.y, Ah.z, Ah.w, b0h, b1h);
                    mma_f16(acc[nt], Ah.x, Ah.y, Ah.z, Ah.w, b0l, b1l);
                    mma_f16(acc[nt], Al.x, Al.y, Al.z, Al.w, b0h, b1h);
                }
            }
        }
        __syncthreads();
    }

    int o = mt * 16 + (lane >> 2);
    float b0 = 0, s0 = 1, f0 = 0, b1 = 0, s1 = 1, f1 = 0;
    if (EPI == 1) {
        if (o < Oact)     { b0 = __ldg(e_b + o);     s0 = __ldg(e_s + o);     f0 = __ldg(e_o + o); }
        if (o + 8 < Oact) { b1 = __ldg(e_b + o + 8); s1 = __ldg(e_s + o + 8); f1 = __ldg(e_o + o + 8); }
    } else if (EPI == 2) {
        if (o < Oact)     b0 = __ldg(e_b + o);
        if (o + 8 < Oact) b1 = __ldg(e_b + o + 8);
    }
    int colb = tile * 64 + nh * 32 + (lane & 3) * 2;
    float* o0 = out + ((size_t)b * Oact + o) * HW + colb;
    float* o1 = o0 + 8 * HW;
#pragma unroll
    for (int nt = 0; nt < 4; nt++) {
        float v0a = acc[nt][0], v0b = acc[nt][1];
        float v1a = acc[nt][2], v1b = acc[nt][3];
        if (EPI == 1) {
            v0a = fmaxf((v0a + b0) * s0 + f0, 0.0f);
            v0b = fmaxf((v0b + b0) * s0 + f0, 0.0f);
            v1a = fmaxf((v1a + b1) * s1 + f1, 0.0f);
            v1b = fmaxf((v1b + b1) * s1 + f1, 0.0f);
        } else if (EPI == 2) {
            v0a += b0; v0b += b0; v1a += b1; v1b += b1;
        }
        if (o < Oact)
            *reinterpret_cast<float2*>(o0 + nt * 8) = make_float2(v0a, v0b);
        if (o + 8 < Oact)
            *reinterpret_cast<float2*>(o1 + nt * 8) = make_float2(v1a, v1b);
    }
}

// ---------------- DCNv1 mid conv (deform gather), double-buffered --------------------
// Dynamic SMEM: 2 bufs x (hi+lo) x 2304 u32 = 36864 B; tables static.
__global__ void __launch_bounds__(256)
dcn_mid(const float* __restrict__ inp,
        const unsigned* __restrict__ Ahi, const unsigned* __restrict__ Alo,
        const float* __restrict__ offs, int offBS, float* __restrict__ out) {
    extern __shared__ unsigned msm[];
    unsigned* s_bhA = msm;               // [2][2304]
    unsigned* s_blA = msm + 2 * 2304;    // [2][2304]
    __shared__ int2 s_ii[576];
    __shared__ float4 s_ww[576];

    const int b = blockIdx.y;
    const int tile = blockIdx.x;
    const int tid = threadIdx.x;
    const int warp = tid >> 5;
    const int lane = tid & 31;
    const int mt = warp >> 1;
    const int nh = warp & 1;

    for (int e = tid; e < 576; e += 256) {
        int k = e >> 6, p = e & 63;
        int pix = tile * 64 + p;
        float py = (float)(tile - 1 + k / 3)
                 + offs[(size_t)b * offBS + (2 * k) * HW + pix];
        float px = (float)(p - 1 + k % 3)
                 + offs[(size_t)b * offBS + (2 * k + 1) * HW + pix];
        float fy = floorf(py), fx = floorf(px);
        int iy = (int)fy, ix = (int)fx;
        float ay = py - fy, ax = px - fx;
        bool vy0 = (iy >= 0) && (iy < 64);
        bool vy1 = (iy >= -1) && (iy < 63);
        bool vx0 = (ix >= 0) && (ix < 64);
        bool vx1 = (ix >= -1) && (ix < 63);
        int cy0 = min(max(iy, 0), 63), cy1 = min(max(iy + 1, 0), 63);
        int cx0 = min(max(ix, 0), 63), cx1 = min(max(ix + 1, 0), 63);
        int xb = min(max(ix, 0), 62);
        float wAx = 0.0f, wBx = 0.0f;
        if (vx0) { if (cx0 == xb) wAx += 1.0f - ax; else wBx += 1.0f - ax; }
        if (vx1) { if (cx1 == xb) wAx += ax; else wBx += ax; }
        float w0 = vy0 ? (1.0f - ay) : 0.0f;
        float w1 = vy1 ? ay : 0.0f;
        s_ii[e] = make_int2(cy0 * 64 + xb, cy1 * 64 + xb);
        s_ww[e] = make_float4(w0 * wAx, w0 * wBx, w1 * wAx, w1 * wBx);
    }
    __syncthreads();

    float acc[4][4];
#pragma unroll
    for (int nt = 0; nt < 4; nt++)
#pragma unroll
        for (int r = 0; r < 4; r++) acc[nt][r] = 0.0f;

    const float* xb_ptr = inp + (size_t)b * 64 * HW;
    const int p = tid & 63;
    const int j0 = tid >> 6;
    const int jh0 = j0 >> 1, jpar = j0 & 1;
    int c0 = 0, kk0 = j0;     // sequential slab-gather state

    auto gather = [&](int buf) {
        unsigned* bh = s_bhA + buf * 2304;
        unsigned* bl = s_blA + buf * 2304;
        const float* xc = xb_ptr + (size_t)c0 * HW;
        int kk = kk0;
#pragma unroll
        for (int i = 0; i < 16; i++) {
            int r = kk * 64 + p;
            int2 ii = s_ii[r];
            float4 w4 = s_ww[r];
            float v = w4.x * __ldg(xc + ii.x) + w4.y * __ldg(xc + ii.x + 1)
                    + w4.z * __ldg(xc + ii.y) + w4.w * __ldg(xc + ii.y + 1);
            __half vh = __float2half(v);
            __half vl = __float2half(v - __half2float(vh));
            int idx = ((jh0 + 2 * i) * 72 + p) * 2 + jpar;
            ((__half*)bh)[idx] = vh;
            ((__half*)bl)[idx] = vl;
            kk += 4;
            if (kk >= 9) { kk -= 9; xc += HW; }
        }
        kk0 += 1; c0 += 7;
        if (kk0 >= 9) { kk0 -= 9; c0++; }
    };

    gather(0);
    __syncthreads();

    for (int slab = 0; slab < 9; slab++) {
        if (slab < 8) gather((slab + 1) & 1);
        const unsigned* sbh = s_bhA + (slab & 1) * 2304;
        const unsigned* sbl = s_blA + (slab & 1) * 2304;
#pragma unroll
        for (int kc = 0; kc < 4; kc++) {
            int kcg = slab * 4 + kc;
            uint4 Ah = __ldg((const uint4*)(Ahi + (((size_t)kcg * 4 + mt) * 32 + lane) * 4));
            uint4 Al = __ldg((const uint4*)(Alo + (((size_t)kcg * 4 + mt) * 32 + lane) * 4));
            int boff = (kc * 8 + (lane & 3)) * 72 + (lane >> 2) + nh * 32;
            const unsigned* bhp = sbh + boff;
            const unsigned* blp = sbl + boff;
#pragma unroll
            for (int nt = 0; nt < 4; nt++) {
                unsigned b0h = bhp[nt * 8], b1h = bhp[nt * 8 + 4 * 72];
                unsigned b0l = blp[nt * 8], b1l = blp[nt * 8 + 4 * 72];
                mma_f16(acc[nt], Ah.x, Ah.y, Ah.z, Ah.w, b0h, b1h);
                mma_f16(acc[nt], Ah.x, Ah.y, Ah.z, Ah.w, b0l, b1l);
                mma_f16(acc[nt], Al.x, Al.y, Al.z, Al.w, b0h, b1h);
            }
        }
        __syncthreads();
    }

    int o = mt * 16 + (lane >> 2);
    int colb = tile * 64 + nh * 32 + (lane & 3) * 2;
    float* o0 = out + ((size_t)b * 64 + o) * HW + colb;
    float* o1 = o0 + 8 * HW;
#pragma unroll
    for (int nt = 0; nt < 4; nt++) {
        *reinterpret_cast<float2*>(o0 + nt * 8) = make_float2(acc[nt][0], acc[nt][1]);
        *reinterpret_cast<float2*>(o1 + nt * 8) = make_float2(acc[nt][2], acc[nt][3]);
    }
}

// ---------------- final modulated DCNv2 (256->256), double-buffered ------------------
__global__ void __launch_bounds__(256)
dcn_final_f16(const float* __restrict__ x, const unsigned* __restrict__ Af,
              const float* __restrict__ offs, const float* __restrict__ msk,
              const float* __restrict__ bias, float* __restrict__ out) {
    __shared__ unsigned s_bA[2][32 * 72];
    __shared__ int2 s_ii[576];
    __shared__ float4 s_ww[576];

    const int b = blockIdx.y;
    const int tile = blockIdx.x;
    const int tid = threadIdx.x;
    const int warp = tid >> 5;
    const int lane = tid & 31;

    for (int e = tid; e < 576; e += 256) {
        int k = e >> 6, p = e & 63;
        int pix = tile * 64 + p;
        float py = (float)(tile - 1 + k / 3) + offs[(size_t)b * 36 * HW + (2 * k) * HW + pix];
        float px = (float)(p - 1 + k % 3) + offs[(size_t)b * 36 * HW + (2 * k + 1) * HW + pix];
        float m = msk[(size_t)b * 9 * HW + k * HW + pix];
        float fy = floorf(py), fx = floorf(px);
        int iy = (int)fy, ix = (int)fx;
        float ay = py - fy, ax = px - fx;
        bool vy0 = (iy >= 0) && (iy < 64);
        bool vy1 = (iy >= -1) && (iy < 63);
        bool vx0 = (ix >= 0) && (ix < 64);
        bool vx1 = (ix >= -1) && (ix < 63);
        int cy0 = min(max(iy, 0), 63), cy1 = min(max(iy + 1, 0), 63);
        int cx0 = min(max(ix, 0), 63), cx1 = min(max(ix + 1, 0), 63);
        int xb = min(max(ix, 0), 62);
        float wAx = 0.0f, wBx = 0.0f;
        if (vx0) { if (cx0 == xb) wAx += 1.0f - ax; else wBx += 1.0f - ax; }
        if (vx1) { if (cx1 == xb) wAx += ax; else wBx += ax; }
        float w0 = vy0 ? (1.0f - ay) * m : 0.0f;
        float w1 = vy1 ? ay * m : 0.0f;
        s_ii[e] = make_int2(cy0 * 64 + xb, cy1 * 64 + xb);
        s_ww[e] = make_float4(w0 * wAx, w0 * wBx, w1 * wAx, w1 * wBx);
    }
    __syncthreads();

    float acc[2][8][4];
#pragma unroll
    for (int mtl = 0; mtl < 2; mtl++)
#pragma unroll
        for (int nt = 0; nt < 8; nt++)
#pragma unroll
            for (int r = 0; r < 4; r++) acc[mtl][nt][r] = 0.0f;

    const float* xb_ptr = x + (size_t)b * 256 * HW;
    const int p = tid & 63;
    const int j0 = tid >> 6;
    const int jh0 = j0 >> 1, jpar = j0 & 1;
    int c0 = 0, kk0 = j0;

    auto gather = [&](int buf) {
        unsigned* bdst = s_bA[buf];
        const float* xc = xb_ptr + (size_t)c0 * HW;
        int kk = kk0;
#pragma unroll
        for (int i = 0; i < 16; i++) {
            int r = kk * 64 + p;
            int2 ii = s_ii[r];
            float4 w4 = s_ww[r];
            float v = w4.x * __ldg(xc + ii.x) + w4.y * __ldg(xc + ii.x + 1)
                    + w4.z * __ldg(xc + ii.y) + w4.w * __ldg(xc + ii.y + 1);
            ((__half*)bdst)[((jh0 + 2 * i) * 72 + p) * 2 + jpar] = __float2half(v);
            kk += 4;
            if (kk >= 9) { kk -= 9; xc += HW; }
        }
        kk0 += 1; c0 += 7;
        if (kk0 >= 9) { kk0 -= 9; c0++; }
    };

    gather(0);
    __syncthreads();

    for (int slab = 0; slab < 36; slab++) {
        if (slab < 35) gather((slab + 1) & 1);
        const unsigned* sb = s_bA[slab & 1];
#pragma unroll
        for (int kc = 0; kc < 4; kc++) {
            int kcg = slab * 4 + kc;
            const unsigned* ap = Af + (((size_t)kcg * 16 + warp * 2) * 32 + lane) * 4;
            uint4 A0 = __ldg((const uint4*)ap);
            uint4 A1 = __ldg((const uint4*)(ap + 128));

            const unsigned* bp = sb + (kc * 8 + (lane & 3)) * 72 + (lane >> 2);
#pragma unroll
            for (int nt = 0; nt < 8; nt++) {
                unsigned b0 = bp[nt * 8], b1 = bp[nt * 8 + 4 * 72];
                mma_f16(acc[0][nt], A0.x, A0.y, A0.z, A0.w, b0, b1);
                mma_f16(acc[1][nt], A1.x, A1.y, A1.z, A1.w, b0, b1);
            }
        }
        __syncthreads();
    }

#pragma unroll
    for (int mtl = 0; mtl < 2; mtl++) {
        int o = warp * 32 + mtl * 16 + (lane >> 2);
        float b_lo = __ldg(bias + o);
        float b_hi = __ldg(bias + o + 8);
        float* o0 = out + ((size_t)b * 256 + o) * HW + tile * 64 + (lane & 3) * 2;
        float* o1 = o0 + 8 * HW;
#pragma unroll
        for (int nt = 0; nt < 8; nt++) {
            *reinterpret_cast<float2*>(o0 + nt * 8) =
                make_float2(acc[mtl][nt][0] + b_lo, acc[mtl][nt][1] + b_lo);
            *reinterpret_cast<float2*>(o1 + nt * 8) =
                make_float2(acc[mtl][nt][2] + b_hi, acc[mtl][nt][3] + b_hi);
        }
    }
}

// ---------------- host launcher ------------------------------------------------------
extern "C" void kernel_launch(void* const* d_in, const int* in_sizes, int n_in,
                              void* d_out, int out_size) {
    const float* x       = (const float*)d_in[0];
    const float* S       = (const float*)d_in[1];
    const float* sp_w1   = (const float*)d_in[2];
    const float* sp_b1   = (const float*)d_in[3];
    const float* sp_s1   = (const float*)d_in[4];
    const float* sp_o1   = (const float*)d_in[5];
    const float* sp_w2   = (const float*)d_in[6];
    const float* sp_b2   = (const float*)d_in[7];
    const float* sp_s2   = (const float*)d_in[8];
    const float* sp_o2   = (const float*)d_in[9];
    const float* sp_w3   = (const float*)d_in[10];
    const float* sp_b3   = (const float*)d_in[11];
    const float* sp_s3   = (const float*)d_in[12];
    const float* sp_o3   = (const float*)d_in[13];
    const float* off_w   = (const float*)d_in[14];
    const float* off_b   = (const float*)d_in[15];
    const float* dcoff_w = (const float*)d_in[16];
    const float* dcoff_b = (const float*)d_in[17];
    const float* dc_w    = (const float*)d_in[18];
    const float* m_w     = (const float*)d_in[19];
    const float* m_b     = (const float*)d_in[20];
    const float* weight  = (const float*)d_in[21];
    const float* bias    = (const float*)d_in[22];

    float *h1, *h2, *h3, *feat, *off, *mask, *b36;
    unsigned *Af, *Ah2, *Al2, *Ah3, *Al3, *Ahdc, *Aldc, *Ah36, *Al36;
    cudaGetSymbolAddress((void**)&h1,   g_h1);
    cudaGetSymbolAddress((void**)&h2,   g_h2);
    cudaGetSymbolAddress((void**)&h3,   g_h3);
    cudaGetSymbolAddress((void**)&feat, g_feat);
    cudaGetSymbolAddress((void**)&off,  g_off);
    cudaGetSymbolAddress((void**)&mask, g_mask);
    cudaGetSymbolAddress((void**)&b36,  g_b36);
    cudaGetSymbolAddress((void**)&Af,   g_Af);
    cudaGetSymbolAddress((void**)&Ah2,  g_Ah2);
    cudaGetSymbolAddress((void**)&Al2,  g_Al2);
    cudaGetSymbolAddress((void**)&Ah3,  g_Ah3);
    cudaGetSymbolAddress((void**)&Al3,  g_Al3);
    cudaGetSymbolAddress((void**)&Ahdc, g_Ahdc);
    cudaGetSymbolAddress((void**)&Aldc, g_Aldc);
    cudaGetSymbolAddress((void**)&Ah36, g_Ah36);
    cudaGetSymbolAddress((void**)&Al36, g_Al36);

    const int SMEM_SHIFT = 4 * 3456 * 4;   // 55296
    const int SMEM_MID   = 4 * 2304 * 4;   // 36864
    cudaFuncSetAttribute(conv_shift<1>,
                         cudaFuncAttributeMaxDynamicSharedMemorySize, SMEM_SHIFT);
    cudaFuncSetAttribute(conv_shift<2>,
                         cudaFuncAttributeMaxDynamicSharedMemorySize, SMEM_SHIFT);
    cudaFuncSetAttribute(dcn_mid,
                         cudaFuncAttributeMaxDynamicSharedMemorySize, SMEM_MID);

    auto tgrid = [](int n) { return (n + 255) / 256; };
    dim3 grid(64, BATCH);

    prep_shift_f16<<<tgrid(64 * 576), 256>>>(sp_w2, Ah2, Al2, 64);                // 0
    prep_shift_f16<<<tgrid(64 * 576), 256>>>(sp_w3, Ah3, Al3, 64);                // 1
    sp1_kernel<<<grid, 256>>>(S, sp_w1, sp_b1, sp_s1, sp_o1, h1);                 // 2
    conv_shift<1><<<grid, 256, SMEM_SHIFT>>>(h1, Ah2, Al2,
                                             sp_b2, sp_s2, sp_o2, h2, 64);        // 3 <- ncu
    conv_shift<1><<<grid, 256, SMEM_SHIFT>>>(h2, Ah3, Al3,
                                             sp_b3, sp_s3, sp_o3, h3, 64);        // 4
    prep_shift_w36<<<tgrid(64 * 576), 256>>>(off_w, dcoff_w, Ah36, Al36);         // 5
    concat_bias36<<<1, 36>>>(off_b, dcoff_b, b36);                                // 6
    prep_mid_f16<<<tgrid(64 * 576), 256>>>(dc_w, Ahdc, Aldc, 64);                 // 7
    conv_shift<2><<<grid, 256, SMEM_SHIFT>>>(h3, Ah36, Al36,
                                             b36, nullptr, nullptr, off, 36);     // 8
    dcn_mid<<<grid, 256, SMEM_MID>>>(h3, Ahdc, Aldc, off + 18 * HW, 36 * HW, feat); // 9
    mask_kernel<<<(BATCH * HW + 255) / 256, 256>>>(feat, m_w, m_b, mask);         // 10
    prep_final_f16<<<tgrid(256 * 2304), 256>>>(weight, Af);                       // 11
    dcn_final_f16<<<grid, 256>>>(x, Af, off, mask, bias, (float*)d_out);          // 12
}

// round 8
// speedup vs baseline: 4.0352x; 1.0511x over previous
#include <cuda_runtime.h>
#include <cuda_fp16.h>
#include <math.h>
#include <stdint.h>

#define HW 4096     // 64*64
#define BATCH 8

// ---------------- scratch (static device globals; no allocation) ----------------
__device__ float g_h1  [BATCH*64*HW];
__device__ float g_h2  [BATCH*64*HW];
__device__ float g_h3  [BATCH*64*HW];
__device__ float g_feat[BATCH*64*HW];
__device__ float g_off [BATCH*36*HW];   // ch 0..17 = offset, 18..35 = dc_off
__device__ float g_mask[BATCH*9*HW];
__device__ float g_b36 [36];

// f16 fragment-packed weights (each u32 = 2 f16 along K)
__device__ unsigned g_Af[144*16*32*4];
#define MIDA (36*4*32*4)
__device__ unsigned g_Ah2 [MIDA], g_Al2 [MIDA];   // shift-order
__device__ unsigned g_Ah3 [MIDA], g_Al3 [MIDA];   // shift-order
__device__ unsigned g_Ah36[MIDA], g_Al36[MIDA];   // shift-order
__device__ unsigned g_Ahdc[MIDA], g_Aldc[MIDA];   // gather-order (K=c*9+kk)

// ---------------- helpers ------------------------------------------------------------
__device__ __forceinline__ void mma_f16(float* acc, unsigned a0, unsigned a1,
                                        unsigned a2, unsigned a3,
                                        unsigned b0, unsigned b1) {
    asm volatile(
        "mma.sync.aligned.m16n8k16.row.col.f32.f16.f16.f32 "
        "{%0,%1,%2,%3}, {%4,%5,%6,%7}, {%8,%9}, {%0,%1,%2,%3};"
        : "+f"(acc[0]), "+f"(acc[1]), "+f"(acc[2]), "+f"(acc[3])
        : "r"(a0), "r"(a1), "r"(a2), "r"(a3), "r"(b0), "r"(b1));
}

__device__ __forceinline__ void frag_coords(int om, int kk, int& lane, int& reg, int& half) {
    int kpair = kk >> 1;
    half = kk & 1;
    lane = (om & 7) * 4 + (kpair & 3);
    reg = (om >> 3) + ((kpair >> 2) << 1);
}

__device__ __forceinline__ unsigned pack_h2(__half lo, __half hi) {
    return (unsigned)__half_as_ushort(lo) | ((unsigned)__half_as_ushort(hi) << 16);
}

// ---------------- weight prep kernels -------------------------------------------------
__global__ void prep_mid_f16(const float* __restrict__ w, unsigned* __restrict__ hi,
                             unsigned* __restrict__ lo, int O) {
    int i = blockIdx.x * blockDim.x + threadIdx.x;
    if (i >= 64 * 576) return;
    int K = i % 576;
    int o = i / 576;
    float v = (o < O) ? w[o * 576 + K] : 0.0f;
    __half vh = __float2half(v);
    __half vl = __float2half(v - __half2float(vh));
    int kc = K >> 4, kk = K & 15;
    int lane, reg, half;
    frag_coords(o & 15, kk, lane, reg, half);
    size_t base = ((((size_t)kc * 4 + (o >> 4)) * 32 + lane) * 4 + reg) * 2 + half;
    ((__half*)hi)[base] = vh;
    ((__half*)lo)[base] = vl;
}

__global__ void prep_shift_f16(const float* __restrict__ w, unsigned* __restrict__ hi,
                               unsigned* __restrict__ lo, int O) {
    int i = blockIdx.x * blockDim.x + threadIdx.x;
    if (i >= 64 * 576) return;
    int K = i % 576;
    int o = i / 576;
    float v = (o < O) ? w[o * 576 + K] : 0.0f;
    __half vh = __float2half(v);
    __half vl = __float2half(v - __half2float(vh));
    int c = K / 9, kk = K % 9;
    int slab = c >> 5, cl = c & 31;
    int kcg = (slab * 9 + kk) * 2 + (cl >> 4);
    int lane, reg, half;
    frag_coords(o & 15, cl & 15, lane, reg, half);
    size_t base = ((((size_t)kcg * 4 + (o >> 4)) * 32 + lane) * 4 + reg) * 2 + half;
    ((__half*)hi)[base] = vh;
    ((__half*)lo)[base] = vl;
}

__global__ void prep_shift_w36(const float* __restrict__ wa, const float* __restrict__ wb,
                               unsigned* __restrict__ hi, unsigned* __restrict__ lo) {
    int i = blockIdx.x * blockDim.x + threadIdx.x;
    if (i >= 64 * 576) return;
    int K = i % 576;
    int o = i / 576;
    float v = 0.0f;
    if (o < 18) v = wa[o * 576 + K];
    else if (o < 36) v = wb[(o - 18) * 576 + K];
    __half vh = __float2half(v);
    __half vl = __float2half(v - __half2float(vh));
    int c = K / 9, kk = K % 9;
    int slab = c >> 5, cl = c & 31;
    int kcg = (slab * 9 + kk) * 2 + (cl >> 4);
    int lane, reg, half;
    frag_coords(o & 15, cl & 15, lane, reg, half);
    size_t base = ((((size_t)kcg * 4 + (o >> 4)) * 32 + lane) * 4 + reg) * 2 + half;
    ((__half*)hi)[base] = vh;
    ((__half*)lo)[base] = vl;
}

__global__ void prep_final_f16(const float* __restrict__ w, unsigned* __restrict__ dst) {
    int i = blockIdx.x * blockDim.x + threadIdx.x;
    if (i >= 256 * 2304) return;
    int K = i % 2304;
    int o = i / 2304;
    int kc = K >> 4, kk = K & 15;
    int lane, reg, half;
    frag_coords(o & 15, kk, lane, reg, half);
    size_t base = ((((size_t)kc * 16 + (o >> 4)) * 32 + lane) * 4 + reg) * 2 + half;
    ((__half*)dst)[base] = __float2half(w[i]);
}

__global__ void concat_bias36(const float* __restrict__ a, const float* __restrict__ b,
                              float* __restrict__ dst) {
    int i = threadIdx.x;
    if (i < 18) dst[i] = a[i];
    else if (i < 36) dst[i] = b[i - 18];
}

// ---------------- 1x1 conv + sigmoid -------------------------------------------------
__global__ void mask_kernel(const float* __restrict__ feat, const float* __restrict__ mw,
                            const float* __restrict__ mb, float* __restrict__ mask) {
    int i = blockIdx.x * blockDim.x + threadIdx.x;
    if (i >= BATCH * HW) return;
    int b = i >> 12;
    int pix = i & (HW - 1);
    float acc[9];
#pragma unroll
    for (int o = 0; o < 9; o++) acc[o] = __ldg(mb + o);
    const float* fp = feat + (size_t)b * 64 * HW + pix;
    for (int c = 0; c < 64; c++) {
        float v = __ldg(fp + c * HW);
#pragma unroll
        for (int o = 0; o < 9; o++) acc[o] += v * __ldg(mw + o * 64 + c);
    }
#pragma unroll
    for (int o = 0; o < 9; o++)
        mask[((size_t)b * 9 + o) * HW + pix] = 1.0f / (1.0f + expf(-acc[o]));
}

// ---------------- sp1: fused resize + conv3x3 (CIN=3) + BN + ReLU, fp32 --------------
__device__ __forceinline__ float resize_at(const float* __restrict__ p, int y, int x) {
    const float scale = 127.0f / 63.0f;
    float ys = y * scale, xs = x * scale;
    float fy = floorf(ys), fx = floorf(xs);
    int y0 = (int)fy, x0 = (int)fx;
    int y1 = min(y0 + 1, 127), x1 = min(x0 + 1, 127);
    float wy = ys - fy, wx = xs - fx;
    return p[y0 * 128 + x0] * (1.0f - wy) * (1.0f - wx)
         + p[y0 * 128 + x1] * (1.0f - wy) * wx
         + p[y1 * 128 + x0] * wy * (1.0f - wx)
         + p[y1 * 128 + x1] * wy * wx;
}

__global__ void __launch_bounds__(256)
sp1_kernel(const float* __restrict__ S, const float* __restrict__ w1,
           const float* __restrict__ e_b, const float* __restrict__ e_s,
           const float* __restrict__ e_o, float* __restrict__ out) {
    __shared__ __align__(16) float s_t[576];
    const int b = blockIdx.y;
    const int tile = blockIdx.x;
    const int tid = threadIdx.x;
    const int o = tid & 63;
    const int pbase = (tid >> 6) * 16;

    float acc[16];
#pragma unroll
    for (int j = 0; j < 16; j++) acc[j] = 0.0f;

    for (int c = 0; c < 3; c++) {
        const float* Sc = S + (size_t)(b * 3 + c) * 128 * 128;
        for (int e = tid; e < 576; e += 256) {
            int k = e >> 6, p = e & 63;
            int yy = tile + k / 3 - 1;
            int xx = p + k % 3 - 1;
            s_t[e] = ((unsigned)yy < 64u && (unsigned)xx < 64u)
                         ? resize_at(Sc, yy, xx) : 0.0f;
        }
        __syncthreads();

        float wv[9];
#pragma unroll
        for (int k = 0; k < 9; k++) wv[k] = __ldg(w1 + o * 27 + c * 9 + k);

#pragma unroll
        for (int k = 0; k < 9; k++) {
            const float4* sp = reinterpret_cast<const float4*>(s_t + k * 64 + pbase);
#pragma unroll
            for (int j4 = 0; j4 < 4; j4++) {
                float4 sv = sp[j4];
                acc[j4 * 4 + 0] += wv[k] * sv.x;
                acc[j4 * 4 + 1] += wv[k] * sv.y;
                acc[j4 * 4 + 2] += wv[k] * sv.z;
                acc[j4 * 4 + 3] += wv[k] * sv.w;
            }
        }
        __syncthreads();
    }

    float bb = __ldg(e_b + o), ssc = __ldg(e_s + o), oof = __ldg(e_o + o);
    float* op = out + ((size_t)b * 64 + o) * HW + tile * 64 + pbase;
#pragma unroll
    for (int j = 0; j < 16; j++)
        op[j] = fmaxf((acc[j] + bb) * ssc + oof, 0.0f);
}

// ---------------- plain conv3x3 via shifted-window mma, double-buffered --------------
template <int EPI>
__global__ void __launch_bounds__(256)
conv_shift(const float* __restrict__ inp,
           const unsigned* __restrict__ Ahi, const unsigned* __restrict__ Alo,
           const float* __restrict__ e_b, const float* __restrict__ e_s,
           const float* __restrict__ e_o, float* __restrict__ out, int Oact) {
    extern __shared__ unsigned csm[];
    unsigned* s_bhA = csm;              // [2][3456]
    unsigned* s_blA = csm + 2 * 3456;   // [2][3456]

    const int b = blockIdx.y;
    const int tile = blockIdx.x;
    const int tid = threadIdx.x;
    const int warp = tid >> 5;
    const int lane = tid & 31;
    const int mt = warp >> 1;
    const int nh = warp & 1;

    float acc[4][4];
#pragma unroll
    for (int nt = 0; nt < 4; nt++)
#pragma unroll
        for (int r = 0; r < 4; r++) acc[nt][r] = 0.0f;

    const float* xb = inp + (size_t)b * 64 * HW;

    auto fill = [&](int slab, int buf) {
        unsigned* bh = s_bhA + buf * 3456;
        unsigned* bl = s_blA + buf * 3456;
        for (int e = tid; e < 3168; e += 256) {
            int r = e / 1056;
            int rem = e - r * 1056;
            int cp = rem / 66;
            int col = rem - cp * 66;
            int yy = tile - 1 + r;
            int px = col - 1;
            bool ok = ((unsigned)yy < 64u) && ((unsigned)px < 64u);
            const float* p0 = xb + (size_t)(slab * 32 + cp * 2) * HW + yy * 64 + px;
            float v0 = ok ? __ldg(p0) : 0.0f;
            float v1 = ok ? __ldg(p0 + HW) : 0.0f;
            __half h0 = __float2half(v0), h1 = __float2half(v1);
            __half l0 = __float2half(v0 - __half2float(h0));
            __half l1 = __float2half(v1 - __half2float(h1));
            int idx = (r * 16 + cp) * 72 + col;
            bh[idx] = pack_h2(h0, h1);
            bl[idx] = pack_h2(l0, l1);
        }
    };

    fill(0, 0);
    __syncthreads();

    for (int slab = 0; slab < 2; slab++) {
        if (slab == 0) fill(1, 1);
        const unsigned* sbh = s_bhA + slab * 3456;
        const unsigned* sbl = s_blA + slab * 3456;
#pragma unroll
        for (int t = 0; t < 9; t++) {
            const int dy = t / 3, dx = t % 3;
            const unsigned* rbh = sbh + dy * 16 * 72;
            const unsigned* rbl = sbl + dy * 16 * 72;
#pragma unroll
            for (int kcl = 0; kcl < 2; kcl++) {
                int kcg = (slab * 9 + t) * 2 + kcl;
                uint4 Ah = __ldg((const uint4*)(Ahi + (((size_t)kcg * 4 + mt) * 32 + lane) * 4));
                uint4 Al = __ldg((const uint4*)(Alo + (((size_t)kcg * 4 + mt) * 32 + lane) * 4));
                int boff = (kcl * 8 + (lane & 3)) * 72 + (lane >> 2) + nh * 32 + dx;
                const unsigned* bh = rbh + boff;
                const unsigned* bl = rbl + boff;
#pragma unroll
                for (int nt = 0; nt < 4; nt++) {
                    unsigned b0h = bh[nt * 8], b1h = bh[nt * 8 + 4 * 72];
                    unsigned b0l = bl[nt * 8], b1l = bl[nt * 8 + 4 * 72];
                    mma_f16(acc[nt], Ah.x, Ah.y, Ah.z, Ah.w, b0h, b1h);
                    mma_f16(acc[nt], Ah.x, Ah.y, Ah.z, Ah.w, b0l, b1l);
                    mma_f16(acc[nt], Al.x, Al.y, Al.z, Al.w, b0h, b1h);
                }
            }
        }
        __syncthreads();
    }

    int o = mt * 16 + (lane >> 2);
    float b0 = 0, s0 = 1, f0 = 0, b1 = 0, s1 = 1, f1 = 0;
    if (EPI == 1) {
        if (o < Oact)     { b0 = __ldg(e_b + o);     s0 = __ldg(e_s + o);     f0 = __ldg(e_o + o); }
        if (o + 8 < Oact) { b1 = __ldg(e_b + o + 8); s1 = __ldg(e_s + o + 8); f1 = __ldg(e_o + o + 8); }
    } else if (EPI == 2) {
        if (o < Oact)     b0 = __ldg(e_b + o);
        if (o + 8 < Oact) b1 = __ldg(e_b + o + 8);
    }
    int colb = tile * 64 + nh * 32 + (lane & 3) * 2;
    float* o0 = out + ((size_t)b * Oact + o) * HW + colb;
    float* o1 = o0 + 8 * HW;
#pragma unroll
    for (int nt = 0; nt < 4; nt++) {
        float v0a = acc[nt][0], v0b = acc[nt][1];
        float v1a = acc[nt][2], v1b = acc[nt][3];
        if (EPI == 1) {
            v0a = fmaxf((v0a + b0) * s0 + f0, 0.0f);
            v0b = fmaxf((v0b + b0) * s0 + f0, 0.0f);
            v1a = fmaxf((v1a + b1) * s1 + f1, 0.0f);
            v1b = fmaxf((v1b + b1) * s1 + f1, 0.0f);
        } else if (EPI == 2) {
            v0a += b0; v0b += b0; v1a += b1; v1b += b1;
        }
        if (o < Oact)
            *reinterpret_cast<float2*>(o0 + nt * 8) = make_float2(v0a, v0b);
        if (o + 8 < Oact)
            *reinterpret_cast<float2*>(o1 + nt * 8) = make_float2(v1a, v1b);
    }
}

// ---------------- DCNv1 mid conv (deform gather), permuted-B + paired STS ------------
// B tile col = perm(p) = (p&7)*8 + (p>>3); thread gathers K-pairs -> 1 STS.32.
__global__ void __launch_bounds__(256)
dcn_mid(const float* __restrict__ inp,
        const unsigned* __restrict__ Ahi, const unsigned* __restrict__ Alo,
        const float* __restrict__ offs, int offBS, float* __restrict__ out) {
    extern __shared__ unsigned msm[];
    unsigned* s_bhA = msm;               // [2][2304]
    unsigned* s_blA = msm + 2 * 2304;    // [2][2304]
    __shared__ int2 s_ii[576];
    __shared__ float4 s_ww[576];

    const int b = blockIdx.y;
    const int tile = blockIdx.x;
    const int tid = threadIdx.x;
    const int warp = tid >> 5;
    const int lane = tid & 31;
    const int mt = warp >> 1;
    const int nh = warp & 1;
    const int q = lane >> 2;

    for (int e = tid; e < 576; e += 256) {
        int k = e >> 6, p = e & 63;
        int pix = tile * 64 + p;
        float py = (float)(tile - 1 + k / 3)
                 + offs[(size_t)b * offBS + (2 * k) * HW + pix];
        float px = (float)(p - 1 + k % 3)
                 + offs[(size_t)b * offBS + (2 * k + 1) * HW + pix];
        float fy = floorf(py), fx = floorf(px);
        int iy = (int)fy, ix = (int)fx;
        float ay = py - fy, ax = px - fx;
        bool vy0 = (iy >= 0) && (iy < 64);
        bool vy1 = (iy >= -1) && (iy < 63);
        bool vx0 = (ix >= 0) && (ix < 64);
        bool vx1 = (ix >= -1) && (ix < 63);
        int cy0 = min(max(iy, 0), 63), cy1 = min(max(iy + 1, 0), 63);
        int cx0 = min(max(ix, 0), 63), cx1 = min(max(ix + 1, 0), 63);
        int xb = min(max(ix, 0), 62);
        float wAx = 0.0f, wBx = 0.0f;
        if (vx0) { if (cx0 == xb) wAx += 1.0f - ax; else wBx += 1.0f - ax; }
        if (vx1) { if (cx1 == xb) wAx += ax; else wBx += ax; }
        float w0 = vy0 ? (1.0f - ay) : 0.0f;
        float w1 = vy1 ? ay : 0.0f;
        s_ii[e] = make_int2(cy0 * 64 + xb, cy1 * 64 + xb);
        s_ww[e] = make_float4(w0 * wAx, w0 * wBx, w1 * wAx, w1 * wBx);
    }
    __syncthreads();

    float acc[4][4];
#pragma unroll
    for (int nt = 0; nt < 4; nt++)
#pragma unroll
        for (int r = 0; r < 4; r++) acc[nt][r] = 0.0f;

    const float* xb_ptr = inp + (size_t)b * 64 * HW;
    const int p = tid & 63;
    const int jp0 = tid >> 6;                    // K-pair slot 0..3
    const int perm = (p & 7) * 8 + (p >> 3);     // permuted col
    int c0 = 0, kk0 = 2 * jp0;                   // (c,kk) of first sample of slab

    auto gather = [&](int buf) {
        unsigned* bh = s_bhA + buf * 2304;
        unsigned* bl = s_blA + buf * 2304;
        const float* xc = xb_ptr + (size_t)c0 * HW;
        int kk = kk0;
        int jp = jp0;
#pragma unroll
        for (int i = 0; i < 8; i++) {
            int ra = kk * 64 + p;
            int2 iia = s_ii[ra]; float4 wa4 = s_ww[ra];
            float va = wa4.x * __ldg(xc + iia.x) + wa4.y * __ldg(xc + iia.x + 1)
                     + wa4.z * __ldg(xc + iia.y) + wa4.w * __ldg(xc + iia.y + 1);
            const float* xcb = xc; int kkb = kk + 1;
            if (kkb == 9) { kkb = 0; xcb += HW; }
            int rb = kkb * 64 + p;
            int2 iib = s_ii[rb]; float4 wb4 = s_ww[rb];
            float vb = wb4.x * __ldg(xcb + iib.x) + wb4.y * __ldg(xcb + iib.x + 1)
                     + wb4.z * __ldg(xcb + iib.y) + wb4.w * __ldg(xcb + iib.y + 1);
            __half vah = __float2half(va), vbh = __float2half(vb);
            __half val = __float2half(va - __half2float(vah));
            __half vbl = __float2half(vb - __half2float(vbh));
            bh[jp * 72 + perm] = pack_h2(vah, vbh);
            bl[jp * 72 + perm] = pack_h2(val, vbl);
            jp += 4;
            kk += 8; if (kk >= 9) { kk -= 9; xc += HW; }
        }
        kk0 += 1; c0 += 7;
        if (kk0 >= 9) { kk0 -= 9; c0++; }
    };

    gather(0);
    __syncthreads();

    for (int slab = 0; slab < 9; slab++) {
        if (slab < 8) gather((slab + 1) & 1);
        const unsigned* sbh = s_bhA + (slab & 1) * 2304;
        const unsigned* sbl = s_blA + (slab & 1) * 2304;
#pragma unroll
        for (int kc = 0; kc < 4; kc++) {
            int kcg = slab * 4 + kc;
            uint4 Ah = __ldg((const uint4*)(Ahi + (((size_t)kcg * 4 + mt) * 32 + lane) * 4));
            uint4 Al = __ldg((const uint4*)(Alo + (((size_t)kcg * 4 + mt) * 32 + lane) * 4));
            int boff = (kc * 8 + (lane & 3)) * 72 + q * 8 + nh * 4;
            uint4 B0h = *(const uint4*)(sbh + boff);
            uint4 B1h = *(const uint4*)(sbh + boff + 4 * 72);
            uint4 B0l = *(const uint4*)(sbl + boff);
            uint4 B1l = *(const uint4*)(sbl + boff + 4 * 72);
            mma_f16(acc[0], Ah.x, Ah.y, Ah.z, Ah.w, B0h.x, B1h.x);
            mma_f16(acc[0], Ah.x, Ah.y, Ah.z, Ah.w, B0l.x, B1l.x);
            mma_f16(acc[0], Al.x, Al.y, Al.z, Al.w, B0h.x, B1h.x);
            mma_f16(acc[1], Ah.x, Ah.y, Ah.z, Ah.w, B0h.y, B1h.y);
            mma_f16(acc[1], Ah.x, Ah.y, Ah.z, Ah.w, B0l.y, B1l.y);
            mma_f16(acc[1], Al.x, Al.y, Al.z, Al.w, B0h.y, B1h.y);
            mma_f16(acc[2], Ah.x, Ah.y, Ah.z, Ah.w, B0h.z, B1h.z);
            mma_f16(acc[2], Ah.x, Ah.y, Ah.z, Ah.w, B0l.z, B1l.z);
            mma_f16(acc[2], Al.x, Al.y, Al.z, Al.w, B0h.z, B1h.z);
            mma_f16(acc[3], Ah.x, Ah.y, Ah.z, Ah.w, B0h.w, B1h.w);
            mma_f16(acc[3], Ah.x, Ah.y, Ah.z, Ah.w, B0l.w, B1l.w);
            mma_f16(acc[3], Al.x, Al.y, Al.z, Al.w, B0h.w, B1h.w);
        }
        __syncthreads();
    }

    int o = mt * 16 + (lane >> 2);
    int colb = tile * 64 + nh * 32 + (lane & 3) * 2;
    float* o0 = out + ((size_t)b * 64 + o) * HW + colb;
    float* o1 = o0 + 8 * HW;
#pragma unroll
    for (int nt = 0; nt < 4; nt++) {
        *reinterpret_cast<float2*>(o0 + nt * 8) = make_float2(acc[nt][0], acc[nt][1]);
        *reinterpret_cast<float2*>(o1 + nt * 8) = make_float2(acc[nt][2], acc[nt][3]);
    }
}

// ---------------- final modulated DCNv2 (256->256), permuted-B + paired STS ----------
__global__ void __launch_bounds__(256)
dcn_final_f16(const float* __restrict__ x, const unsigned* __restrict__ Af,
              const float* __restrict__ offs, const float* __restrict__ msk,
              const float* __restrict__ bias, float* __restrict__ out) {
    __shared__ unsigned s_bA[2][32 * 72];
    __shared__ int2 s_ii[576];
    __shared__ float4 s_ww[576];

    const int b = blockIdx.y;
    const int tile = blockIdx.x;
    const int tid = threadIdx.x;
    const int warp = tid >> 5;
    const int lane = tid & 31;
    const int q = lane >> 2;

    for (int e = tid; e < 576; e += 256) {
        int k = e >> 6, p = e & 63;
        int pix = tile * 64 + p;
        float py = (float)(tile - 1 + k / 3) + offs[(size_t)b * 36 * HW + (2 * k) * HW + pix];
        float px = (float)(p - 1 + k % 3) + offs[(size_t)b * 36 * HW + (2 * k + 1) * HW + pix];
        float m = msk[(size_t)b * 9 * HW + k * HW + pix];
        float fy = floorf(py), fx = floorf(px);
        int iy = (int)fy, ix = (int)fx;
        float ay = py - fy, ax = px - fx;
        bool vy0 = (iy >= 0) && (iy < 64);
        bool vy1 = (iy >= -1) && (iy < 63);
        bool vx0 = (ix >= 0) && (ix < 64);
        bool vx1 = (ix >= -1) && (ix < 63);
        int cy0 = min(max(iy, 0), 63), cy1 = min(max(iy + 1, 0), 63);
        int cx0 = min(max(ix, 0), 63), cx1 = min(max(ix + 1, 0), 63);
        int xb = min(max(ix, 0), 62);
        float wAx = 0.0f, wBx = 0.0f;
        if (vx0) { if (cx0 == xb) wAx += 1.0f - ax; else wBx += 1.0f - ax; }
        if (vx1) { if (cx1 == xb) wAx += ax; else wBx += ax; }
        float w0 = vy0 ? (1.0f - ay) * m : 0.0f;
        float w1 = vy1 ? ay * m : 0.0f;
        s_ii[e] = make_int2(cy0 * 64 + xb, cy1 * 64 + xb);
        s_ww[e] = make_float4(w0 * wAx, w0 * wBx, w1 * wAx, w1 * wBx);
    }
    __syncthreads();

    float acc[2][8][4];
#pragma unroll
    for (int mtl = 0; mtl < 2; mtl++)
#pragma unroll
        for (int nt = 0; nt < 8; nt++)
#pragma unroll
            for (int r = 0; r < 4; r++) acc[mtl][nt][r] = 0.0f;

    const float* xb_ptr = x + (size_t)b * 256 * HW;
    const int p = tid & 63;
    const int jp0 = tid >> 6;
    const int perm = (p & 7) * 8 + (p >> 3);
    int c0 = 0, kk0 = 2 * jp0;

    auto gather = [&](int buf) {
        unsigned* bdst = s_bA[buf];
        const float* xc = xb_ptr + (size_t)c0 * HW;
        int kk = kk0;
        int jp = jp0;
#pragma unroll
        for (int i = 0; i < 8; i++) {
            int ra = kk * 64 + p;
            int2 iia = s_ii[ra]; float4 wa4 = s_ww[ra];
            float va = wa4.x * __ldg(xc + iia.x) + wa4.y * __ldg(xc + iia.x + 1)
                     + wa4.z * __ldg(xc + iia.y) + wa4.w * __ldg(xc + iia.y + 1);
            const float* xcb = xc; int kkb = kk + 1;
            if (kkb == 9) { kkb = 0; xcb += HW; }
            int rb = kkb * 64 + p;
            int2 iib = s_ii[rb]; float4 wb4 = s_ww[rb];
            float vb = wb4.x * __ldg(xcb + iib.x) + wb4.y * __ldg(xcb + iib.x + 1)
                     + wb4.z * __ldg(xcb + iib.y) + wb4.w * __ldg(xcb + iib.y + 1);
            bdst[jp * 72 + perm] = pack_h2(__float2half(va), __float2half(vb));
            jp += 4;
            kk += 8; if (kk >= 9) { kk -= 9; xc += HW; }
        }
        kk0 += 1; c0 += 7;
        if (kk0 >= 9) { kk0 -= 9; c0++; }
    };

    gather(0);
    __syncthreads();

    for (int slab = 0; slab < 36; slab++) {
        if (slab < 35) gather((slab + 1) & 1);
        const unsigned* sb = s_bA[slab & 1];
#pragma unroll
        for (int kc = 0; kc < 4; kc++) {
            int kcg = slab * 4 + kc;
            const unsigned* ap = Af + (((size_t)kcg * 16 + warp * 2) * 32 + lane) * 4;
            uint4 A0 = __ldg((const uint4*)ap);
            uint4 A1 = __ldg((const uint4*)(ap + 128));

            int boff = (kc * 8 + (lane & 3)) * 72 + q * 8;
            uint4 B0a = *(const uint4*)(sb + boff);            // b0, nt 0..3
            uint4 B0b = *(const uint4*)(sb + boff + 4);        // b0, nt 4..7
            uint4 B1a = *(const uint4*)(sb + boff + 4 * 72);   // b1, nt 0..3
            uint4 B1b = *(const uint4*)(sb + boff + 4 * 72 + 4);
            mma_f16(acc[0][0], A0.x, A0.y, A0.z, A0.w, B0a.x, B1a.x);
            mma_f16(acc[1][0], A1.x, A1.y, A1.z, A1.w, B0a.x, B1a.x);
            mma_f16(acc[0][1], A0.x, A0.y, A0.z, A0.w, B0a.y, B1a.y);
            mma_f16(acc[1][1], A1.x, A1.y, A1.z, A1.w, B0a.y, B1a.y);
            mma_f16(acc[0][2], A0.x, A0.y, A0.z, A0.w, B0a.z, B1a.z);
            mma_f16(acc[1][2], A1.x, A1.y, A1.z, A1.w, B0a.z, B1a.z);
            mma_f16(acc[0][3], A0.x, A0.y, A0.z, A0.w, B0a.w, B1a.w);
            mma_f16(acc[1][3], A1.x, A1.y, A1.z, A1.w, B0a.w, B1a.w);
            mma_f16(acc[0][4], A0.x, A0.y, A0.z, A0.w, B0b.x, B1b.x);
            mma_f16(acc[1][4], A1.x, A1.y, A1.z, A1.w, B0b.x, B1b.x);
            mma_f16(acc[0][5], A0.x, A0.y, A0.z, A0.w, B0b.y, B1b.y);
            mma_f16(acc[1][5], A1.x, A1.y, A1.z, A1.w, B0b.y, B1b.y);
            mma_f16(acc[0][6], A0.x, A0.y, A0.z, A0.w, B0b.z, B1b.z);
            mma_f16(acc[1][6], A1.x, A1.y, A1.z, A1.w, B0b.z, B1b.z);
            mma_f16(acc[0][7], A0.x, A0.y, A0.z, A0.w, B0b.w, B1b.w);
            mma_f16(acc[1][7], A1.x, A1.y, A1.z, A1.w, B0b.w, B1b.w);
        }
        __syncthreads();
    }

#pragma unroll
    for (int mtl = 0; mtl < 2; mtl++) {
        int o = warp * 32 + mtl * 16 + (lane >> 2);
        float b_lo = __ldg(bias + o);
        float b_hi = __ldg(bias + o + 8);
        float* o0 = out + ((size_t)b * 256 + o) * HW + tile * 64 + (lane & 3) * 2;
        float* o1 = o0 + 8 * HW;
#pragma unroll
        for (int nt = 0; nt < 8; nt++) {
            *reinterpret_cast<float2*>(o0 + nt * 8) =
                make_float2(acc[mtl][nt][0] + b_lo, acc[mtl][nt][1] + b_lo);
            *reinterpret_cast<float2*>(o1 + nt * 8) =
                make_float2(acc[mtl][nt][2] + b_hi, acc[mtl][nt][3] + b_hi);
        }
    }
}

// ---------------- host launcher ------------------------------------------------------
extern "C" void kernel_launch(void* const* d_in, const int* in_sizes, int n_in,
                              void* d_out, int out_size) {
    const float* x       = (const float*)d_in[0];
    const float* S       = (const float*)d_in[1];
    const float* sp_w1   = (const float*)d_in[2];
    const float* sp_b1   = (const float*)d_in[3];
    const float* sp_s1   = (const float*)d_in[4];
    const float* sp_o1   = (const float*)d_in[5];
    const float* sp_w2   = (const float*)d_in[6];
    const float* sp_b2   = (const float*)d_in[7];
    const float* sp_s2   = (const float*)d_in[8];
    const float* sp_o2   = (const float*)d_in[9];
    const float* sp_w3   = (const float*)d_in[10];
    const float* sp_b3   = (const float*)d_in[11];
    const float* sp_s3   = (const float*)d_in[12];
    const float* sp_o3   = (const float*)d_in[13];
    const float* off_w   = (const float*)d_in[14];
    const float* off_b   = (const float*)d_in[15];
    const float* dcoff_w = (const float*)d_in[16];
    const float* dcoff_b = (const float*)d_in[17];
    const float* dc_w    = (const float*)d_in[18];
    const float* m_w     = (const float*)d_in[19];
    const float* m_b     = (const float*)d_in[20];
    const float* weight  = (const float*)d_in[21];
    const float* bias    = (const float*)d_in[22];

    float *h1, *h2, *h3, *feat, *off, *mask, *b36;
    unsigned *Af, *Ah2, *Al2, *Ah3, *Al3, *Ahdc, *Aldc, *Ah36, *Al36;
    cudaGetSymbolAddress((void**)&h1,   g_h1);
    cudaGetSymbolAddress((void**)&h2,   g_h2);
    cudaGetSymbolAddress((void**)&h3,   g_h3);
    cudaGetSymbolAddress((void**)&feat, g_feat);
    cudaGetSymbolAddress((void**)&off,  g_off);
    cudaGetSymbolAddress((void**)&mask, g_mask);
    cudaGetSymbolAddress((void**)&b36,  g_b36);
    cudaGetSymbolAddress((void**)&Af,   g_Af);
    cudaGetSymbolAddress((void**)&Ah2,  g_Ah2);
    cudaGetSymbolAddress((void**)&Al2,  g_Al2);
    cudaGetSymbolAddress((void**)&Ah3,  g_Ah3);
    cudaGetSymbolAddress((void**)&Al3,  g_Al3);
    cudaGetSymbolAddress((void**)&Ahdc, g_Ahdc);
    cudaGetSymbolAddress((void**)&Aldc, g_Aldc);
    cudaGetSymbolAddress((void**)&Ah36, g_Ah36);
    cudaGetSymbolAddress((void**)&Al36, g_Al36);

    const int SMEM_SHIFT = 4 * 3456 * 4;   // 55296
    const int SMEM_MID   = 4 * 2304 * 4;   // 36864
    cudaFuncSetAttribute(conv_shift<1>,
                         cudaFuncAttributeMaxDynamicSharedMemorySize, SMEM_SHIFT);
    cudaFuncSetAttribute(conv_shift<2>,
                         cudaFuncAttributeMaxDynamicSharedMemorySize, SMEM_SHIFT);
    cudaFuncSetAttribute(dcn_mid,
                         cudaFuncAttributeMaxDynamicSharedMemorySize, SMEM_MID);

    auto tgrid = [](int n) { return (n + 255) / 256; };
    dim3 grid(64, BATCH);

    prep_shift_f16<<<tgrid(64 * 576), 256>>>(sp_w2, Ah2, Al2, 64);                // 0
    prep_shift_f16<<<tgrid(64 * 576), 256>>>(sp_w3, Ah3, Al3, 64);                // 1
    sp1_kernel<<<grid, 256>>>(S, sp_w1, sp_b1, sp_s1, sp_o1, h1);                 // 2
    conv_shift<1><<<grid, 256, SMEM_SHIFT>>>(h1, Ah2, Al2,
                                             sp_b2, sp_s2, sp_o2, h2, 64);        // 3 <- ncu
    conv_shift<1><<<grid, 256, SMEM_SHIFT>>>(h2, Ah3, Al3,
                                             sp_b3, sp_s3, sp_o3, h3, 64);        // 4
    prep_shift_w36<<<tgrid(64 * 576), 256>>>(off_w, dcoff_w, Ah36, Al36);         // 5
    concat_bias36<<<1, 36>>>(off_b, dcoff_b, b36);                                // 6
    prep_mid_f16<<<tgrid(64 * 576), 256>>>(dc_w, Ahdc, Aldc, 64);                 // 7
    conv_shift<2><<<grid, 256, SMEM_SHIFT>>>(h3, Ah36, Al36,
                                             b36, nullptr, nullptr, off, 36);     // 8
    dcn_mid<<<grid, 256, SMEM_MID>>>(h3, Ahdc, Aldc, off + 18 * HW, 36 * HW, feat); // 9
    mask_kernel<<<(BATCH * HW + 255) / 256, 256>>>(feat, m_w, m_b, mask);         // 10
    prep_final_f16<<<tgrid(256 * 2304), 256>>>(weight, Af);                       // 11
    dcn_final_f16<<<grid, 256>>>(x, Af, off, mask, bias, (float*)d_out);          // 12
}

// round 9
// speedup vs baseline: 4.2217x; 1.0462x over previous
#include <cuda_runtime.h>
#include <cuda_fp16.h>
#include <math.h>
#include <stdint.h>

#define HW 4096     // 64*64
#define BATCH 8

// ---------------- scratch (static device globals; no allocation) ----------------
__device__ float g_h1  [BATCH*64*HW];
__device__ float g_h2  [BATCH*64*HW];
__device__ float g_h3  [BATCH*64*HW];
__device__ float g_feat[BATCH*64*HW];
__device__ float g_off [BATCH*36*HW];   // ch 0..17 = offset, 18..35 = dc_off
__device__ float g_mask[BATCH*9*HW];
__device__ float g_b36 [36];

// shingled copies: s[pos] = (v[pos], v[pos+1 within row])
__device__ float2 g_xs [BATCH*256*HW];  // 64MB
__device__ float2 g_hs3[BATCH*64*HW];   // 16MB

// f16 fragment-packed weights (each u32 = 2 f16 along K)
__device__ unsigned g_Af[144*16*32*4];
#define MIDA (36*4*32*4)
__device__ unsigned g_Ah2 [MIDA], g_Al2 [MIDA];   // shift-order
__device__ unsigned g_Ah3 [MIDA], g_Al3 [MIDA];   // shift-order
__device__ unsigned g_Ah36[MIDA], g_Al36[MIDA];   // shift-order
__device__ unsigned g_Ahdc[MIDA], g_Aldc[MIDA];   // tap-major (K=kk*64+c)

// ---------------- helpers ------------------------------------------------------------
__device__ __forceinline__ void mma_f16(float* acc, unsigned a0, unsigned a1,
                                        unsigned a2, unsigned a3,
                                        unsigned b0, unsigned b1) {
    asm volatile(
        "mma.sync.aligned.m16n8k16.row.col.f32.f16.f16.f32 "
        "{%0,%1,%2,%3}, {%4,%5,%6,%7}, {%8,%9}, {%0,%1,%2,%3};"
        : "+f"(acc[0]), "+f"(acc[1]), "+f"(acc[2]), "+f"(acc[3])
        : "r"(a0), "r"(a1), "r"(a2), "r"(a3), "r"(b0), "r"(b1));
}

__device__ __forceinline__ void frag_coords(int om, int kk, int& lane, int& reg, int& half) {
    int kpair = kk >> 1;
    half = kk & 1;
    lane = (om & 7) * 4 + (kpair & 3);
    reg = (om >> 3) + ((kpair >> 2) << 1);
}

__device__ __forceinline__ unsigned pack_h2(__half lo, __half hi) {
    return (unsigned)__half_as_ushort(lo) | ((unsigned)__half_as_ushort(hi) << 16);
}

// ---------------- weight prep kernels -------------------------------------------------
// tap-major mid (for dcn_mid): Kn = kk*64 + c
__global__ void prep_middc_tap(const float* __restrict__ w, unsigned* __restrict__ hi,
                               unsigned* __restrict__ lo) {
    int i = blockIdx.x * blockDim.x + threadIdx.x;
    if (i >= 64 * 576) return;
    int K = i % 576;
    int o = i / 576;
    float v = w[o * 576 + K];
    __half vh = __float2half(v);
    __half vl = __float2half(v - __half2float(vh));
    int c = K / 9, kk = K - c * 9;
    int Kn = kk * 64 + c;
    int kc = Kn >> 4, kwi = Kn & 15;
    int lane, reg, half;
    frag_coords(o & 15, kwi, lane, reg, half);
    size_t base = ((((size_t)kc * 4 + (o >> 4)) * 32 + lane) * 4 + reg) * 2 + half;
    ((__half*)hi)[base] = vh;
    ((__half*)lo)[base] = vl;
}

// shift-order (for conv_shift)
__global__ void prep_shift_f16(const float* __restrict__ w, unsigned* __restrict__ hi,
                               unsigned* __restrict__ lo, int O) {
    int i = blockIdx.x * blockDim.x + threadIdx.x;
    if (i >= 64 * 576) return;
    int K = i % 576;
    int o = i / 576;
    float v = (o < O) ? w[o * 576 + K] : 0.0f;
    __half vh = __float2half(v);
    __half vl = __float2half(v - __half2float(vh));
    int c = K / 9, kk = K % 9;
    int slab = c >> 5, cl = c & 31;
    int kcg = (slab * 9 + kk) * 2 + (cl >> 4);
    int lane, reg, half;
    frag_coords(o & 15, cl & 15, lane, reg, half);
    size_t base = ((((size_t)kcg * 4 + (o >> 4)) * 32 + lane) * 4 + reg) * 2 + half;
    ((__half*)hi)[base] = vh;
    ((__half*)lo)[base] = vl;
}

__global__ void prep_shift_w36(const float* __restrict__ wa, const float* __restrict__ wb,
                               unsigned* __restrict__ hi, unsigned* __restrict__ lo) {
    int i = blockIdx.x * blockDim.x + threadIdx.x;
    if (i >= 64 * 576) return;
    int K = i % 576;
    int o = i / 576;
    float v = 0.0f;
    if (o < 18) v = wa[o * 576 + K];
    else if (o < 36) v = wb[(o - 18) * 576 + K];
    __half vh = __float2half(v);
    __half vl = __float2half(v - __half2float(vh));
    int c = K / 9, kk = K % 9;
    int slab = c >> 5, cl = c & 31;
    int kcg = (slab * 9 + kk) * 2 + (cl >> 4);
    int lane, reg, half;
    frag_coords(o & 15, cl & 15, lane, reg, half);
    size_t base = ((((size_t)kcg * 4 + (o >> 4)) * 32 + lane) * 4 + reg) * 2 + half;
    ((__half*)hi)[base] = vh;
    ((__half*)lo)[base] = vl;
}

// final: tap-major Kn = kk*256 + c
__global__ void prep_final_f16(const float* __restrict__ w, unsigned* __restrict__ dst) {
    int i = blockIdx.x * blockDim.x + threadIdx.x;
    if (i >= 256 * 2304) return;
    int K = i % 2304;
    int o = i / 2304;
    int c = K / 9, kk = K - c * 9;
    int Kn = kk * 256 + c;
    int kc = Kn >> 4, kwi = Kn & 15;
    int lane, reg, half;
    frag_coords(o & 15, kwi, lane, reg, half);
    size_t base = ((((size_t)kc * 16 + (o >> 4)) * 32 + lane) * 4 + reg) * 2 + half;
    ((__half*)dst)[base] = __float2half(w[i]);
}

__global__ void concat_bias36(const float* __restrict__ a, const float* __restrict__ b,
                              float* __restrict__ dst) {
    int i = threadIdx.x;
    if (i < 18) dst[i] = a[i];
    else if (i < 36) dst[i] = b[i - 18];
}

// ---------------- shingle: dst[pos] = (src[pos], src[pos+1 same row]) -----------------
__global__ void shingle_k(const float* __restrict__ src, float2* __restrict__ dst,
                          int total) {
    int i = blockIdx.x * blockDim.x + threadIdx.x;
    if (i >= total) return;
    float a = src[i];
    float b = ((i & 63) < 63) ? src[i + 1] : 0.0f;
    dst[i] = make_float2(a, b);
}

// ---------------- 1x1 conv + sigmoid -------------------------------------------------
__global__ void mask_kernel(const float* __restrict__ feat, const float* __restrict__ mw,
                            const float* __restrict__ mb, float* __restrict__ mask) {
    int i = blockIdx.x * blockDim.x + threadIdx.x;
    if (i >= BATCH * HW) return;
    int b = i >> 12;
    int pix = i & (HW - 1);
    float acc[9];
#pragma unroll
    for (int o = 0; o < 9; o++) acc[o] = __ldg(mb + o);
    const float* fp = feat + (size_t)b * 64 * HW + pix;
    for (int c = 0; c < 64; c++) {
        float v = __ldg(fp + c * HW);
#pragma unroll
        for (int o = 0; o < 9; o++) acc[o] += v * __ldg(mw + o * 64 + c);
    }
#pragma unroll
    for (int o = 0; o < 9; o++)
        mask[((size_t)b * 9 + o) * HW + pix] = 1.0f / (1.0f + expf(-acc[o]));
}

// ---------------- sp1: fused resize + conv3x3 (CIN=3) + BN + ReLU, fp32 --------------
__device__ __forceinline__ float resize_at(const float* __restrict__ p, int y, int x) {
    const float scale = 127.0f / 63.0f;
    float ys = y * scale, xs = x * scale;
    float fy = floorf(ys), fx = floorf(xs);
    int y0 = (int)fy, x0 = (int)fx;
    int y1 = min(y0 + 1, 127), x1 = min(x0 + 1, 127);
    float wy = ys - fy, wx = xs - fx;
    return p[y0 * 128 + x0] * (1.0f - wy) * (1.0f - wx)
         + p[y0 * 128 + x1] * (1.0f - wy) * wx
         + p[y1 * 128 + x0] * wy * (1.0f - wx)
         + p[y1 * 128 + x1] * wy * wx;
}

__global__ void __launch_bounds__(256)
sp1_kernel(const float* __restrict__ S, const float* __restrict__ w1,
           const float* __restrict__ e_b, const float* __restrict__ e_s,
           const float* __restrict__ e_o, float* __restrict__ out) {
    __shared__ __align__(16) float s_t[576];
    const int b = blockIdx.y;
    const int tile = blockIdx.x;
    const int tid = threadIdx.x;
    const int o = tid & 63;
    const int pbase = (tid >> 6) * 16;

    float acc[16];
#pragma unroll
    for (int j = 0; j < 16; j++) acc[j] = 0.0f;

    for (int c = 0; c < 3; c++) {
        const float* Sc = S + (size_t)(b * 3 + c) * 128 * 128;
        for (int e = tid; e < 576; e += 256) {
            int k = e >> 6, p = e & 63;
            int yy = tile + k / 3 - 1;
            int xx = p + k % 3 - 1;
            s_t[e] = ((unsigned)yy < 64u && (unsigned)xx < 64u)
                         ? resize_at(Sc, yy, xx) : 0.0f;
        }
        __syncthreads();

        float wv[9];
#pragma unroll
        for (int k = 0; k < 9; k++) wv[k] = __ldg(w1 + o * 27 + c * 9 + k);

#pragma unroll
        for (int k = 0; k < 9; k++) {
            const float4* sp = reinterpret_cast<const float4*>(s_t + k * 64 + pbase);
#pragma unroll
            for (int j4 = 0; j4 < 4; j4++) {
                float4 sv = sp[j4];
                acc[j4 * 4 + 0] += wv[k] * sv.x;
                acc[j4 * 4 + 1] += wv[k] * sv.y;
                acc[j4 * 4 + 2] += wv[k] * sv.z;
                acc[j4 * 4 + 3] += wv[k] * sv.w;
            }
        }
        __syncthreads();
    }

    float bb = __ldg(e_b + o), ssc = __ldg(e_s + o), oof = __ldg(e_o + o);
    float* op = out + ((size_t)b * 64 + o) * HW + tile * 64 + pbase;
#pragma unroll
    for (int j = 0; j < 16; j++)
        op[j] = fmaxf((acc[j] + bb) * ssc + oof, 0.0f);
}

// ---------------- plain conv3x3 via shifted-window mma, double-buffered --------------
template <int EPI>
__global__ void __launch_bounds__(256)
conv_shift(const float* __restrict__ inp,
           const unsigned* __restrict__ Ahi, const unsigned* __restrict__ Alo,
           const float* __restrict__ e_b, const float* __restrict__ e_s,
           const float* __restrict__ e_o, float* __restrict__ out, int Oact) {
    extern __shared__ unsigned csm[];
    unsigned* s_bhA = csm;              // [2][3456]
    unsigned* s_blA = csm + 2 * 3456;   // [2][3456]

    const int b = blockIdx.y;
    const int tile = blockIdx.x;
    const int tid = threadIdx.x;
    const int warp = tid >> 5;
    const int lane = tid & 31;
    const int mt = warp >> 1;
    const int nh = warp & 1;

    float acc[4][4];
#pragma unroll
    for (int nt = 0; nt < 4; nt++)
#pragma unroll
        for (int r = 0; r < 4; r++) acc[nt][r] = 0.0f;

    const float* xb = inp + (size_t)b * 64 * HW;

    auto fill = [&](int slab, int buf) {
        unsigned* bh = s_bhA + buf * 3456;
        unsigned* bl = s_blA + buf * 3456;
        for (int e = tid; e < 3168; e += 256) {
            int r = e / 1056;
            int rem = e - r * 1056;
            int cp = rem / 66;
            int col = rem - cp * 66;
            int yy = tile - 1 + r;
            int px = col - 1;
            bool ok = ((unsigned)yy < 64u) && ((unsigned)px < 64u);
            const float* p0 = xb + (size_t)(slab * 32 + cp * 2) * HW + yy * 64 + px;
            float v0 = ok ? __ldg(p0) : 0.0f;
            float v1 = ok ? __ldg(p0 + HW) : 0.0f;
            __half h0 = __float2half(v0), h1 = __float2half(v1);
            __half l0 = __float2half(v0 - __half2float(h0));
            __half l1 = __float2half(v1 - __half2float(h1));
            int idx = (r * 16 + cp) * 72 + col;
            bh[idx] = pack_h2(h0, h1);
            bl[idx] = pack_h2(l0, l1);
        }
    };

    fill(0, 0);
    __syncthreads();

    for (int slab = 0; slab < 2; slab++) {
        if (slab == 0) fill(1, 1);
        const unsigned* sbh = s_bhA + slab * 3456;
        const unsigned* sbl = s_blA + slab * 3456;
#pragma unroll
        for (int t = 0; t < 9; t++) {
            const int dy = t / 3, dx = t % 3;
            const unsigned* rbh = sbh + dy * 16 * 72;
            const unsigned* rbl = sbl + dy * 16 * 72;
#pragma unroll
            for (int kcl = 0; kcl < 2; kcl++) {
                int kcg = (slab * 9 + t) * 2 + kcl;
                uint4 Ah = __ldg((const uint4*)(Ahi + (((size_t)kcg * 4 + mt) * 32 + lane) * 4));
                uint4 Al = __ldg((const uint4*)(Alo + (((size_t)kcg * 4 + mt) * 32 + lane) * 4));
                int boff = (kcl * 8 + (lane & 3)) * 72 + (lane >> 2) + nh * 32 + dx;
                const unsigned* bh = rbh + boff;
                const unsigned* bl = rbl + boff;
#pragma unroll
                for (int nt = 0; nt < 4; nt++) {
                    unsigned b0h = bh[nt * 8], b1h = bh[nt * 8 + 4 * 72];
                    unsigned b0l = bl[nt * 8], b1l = bl[nt * 8 + 4 * 72];
                    mma_f16(acc[nt], Ah.x, Ah.y, Ah.z, Ah.w, b0h, b1h);
                    mma_f16(acc[nt], Ah.x, Ah.y, Ah.z, Ah.w, b0l, b1l);
                    mma_f16(acc[nt], Al.x, Al.y, Al.z, Al.w, b0h, b1h);
                }
            }
        }
        __syncthreads();
    }

    int o = mt * 16 + (lane >> 2);
    float b0 = 0, s0 = 1, f0 = 0, b1 = 0, s1 = 1, f1 = 0;
    if (EPI == 1) {
        if (o < Oact)     { b0 = __ldg(e_b + o);     s0 = __ldg(e_s + o);     f0 = __ldg(e_o + o); }
        if (o + 8 < Oact) { b1 = __ldg(e_b + o + 8); s1 = __ldg(e_s + o + 8); f1 = __ldg(e_o + o + 8); }
    } else if (EPI == 2) {
        if (o < Oact)     b0 = __ldg(e_b + o);
        if (o + 8 < Oact) b1 = __ldg(e_b + o + 8);
    }
    int colb = tile * 64 + nh * 32 + (lane & 3) * 2;
    float* o0 = out + ((size_t)b * Oact + o) * HW + colb;
    float* o1 = o0 + 8 * HW;
#pragma unroll
    for (int nt = 0; nt < 4; nt++) {
        float v0a = acc[nt][0], v0b = acc[nt][1];
        float v1a = acc[nt][2], v1b = acc[nt][3];
        if (EPI == 1) {
            v0a = fmaxf((v0a + b0) * s0 + f0, 0.0f);
            v0b = fmaxf((v0b + b0) * s0 + f0, 0.0f);
            v1a = fmaxf((v1a + b1) * s1 + f1, 0.0f);
            v1b = fmaxf((v1b + b1) * s1 + f1, 0.0f);
        } else if (EPI == 2) {
            v0a += b0; v0b += b0; v1a += b1; v1b += b1;
        }
        if (o < Oact)
            *reinterpret_cast<float2*>(o0 + nt * 8) = make_float2(v0a, v0b);
        if (o + 8 < Oact)
            *reinterpret_cast<float2*>(o1 + nt * 8) = make_float2(v1a, v1b);
    }
}

// ---------------- DCNv1 mid conv: tap-major + shingled LDG.64 + permuted B -----------
// slab == tap kk (9 slabs of 64 channels); table loaded once per slab.
__global__ void __launch_bounds__(256)
dcn_mid(const float2* __restrict__ hs,
        const unsigned* __restrict__ Ahi, const unsigned* __restrict__ Alo,
        const float* __restrict__ offs, int offBS, float* __restrict__ out) {
    extern __shared__ unsigned msm[];
    unsigned* s_bhA = msm;               // [2][2304]
    unsigned* s_blA = msm + 2 * 2304;    // [2][2304]
    __shared__ int2 s_ii[576];
    __shared__ float4 s_ww[576];

    const int b = blockIdx.y;
    const int tile = blockIdx.x;
    const int tid = threadIdx.x;
    const int warp = tid >> 5;
    const int lane = tid & 31;
    const int mt = warp >> 1;
    const int nh = warp & 1;
    const int q = lane >> 2;

    for (int e = tid; e < 576; e += 256) {
        int k = e >> 6, p = e & 63;
        int pix = tile * 64 + p;
        float py = (float)(tile - 1 + k / 3)
                 + offs[(size_t)b * offBS + (2 * k) * HW + pix];
        float px = (float)(p - 1 + k % 3)
                 + offs[(size_t)b * offBS + (2 * k + 1) * HW + pix];
        float fy = floorf(py), fx = floorf(px);
        int iy = (int)fy, ix = (int)fx;
        float ay = py - fy, ax = px - fx;
        bool vy0 = (iy >= 0) && (iy < 64);
        bool vy1 = (iy >= -1) && (iy < 63);
        bool vx0 = (ix >= 0) && (ix < 64);
        bool vx1 = (ix >= -1) && (ix < 63);
        int cy0 = min(max(iy, 0), 63), cy1 = min(max(iy + 1, 0), 63);
        int cx0 = min(max(ix, 0), 63), cx1 = min(max(ix + 1, 0), 63);
        int xb = min(max(ix, 0), 62);
        float wAx = 0.0f, wBx = 0.0f;
        if (vx0) { if (cx0 == xb) wAx += 1.0f - ax; else wBx += 1.0f - ax; }
        if (vx1) { if (cx1 == xb) wAx += ax; else wBx += ax; }
        float w0 = vy0 ? (1.0f - ay) : 0.0f;
        float w1 = vy1 ? ay : 0.0f;
        s_ii[e] = make_int2(cy0 * 64 + xb, cy1 * 64 + xb);
        s_ww[e] = make_float4(w0 * wAx, w0 * wBx, w1 * wAx, w1 * wBx);
    }
    __syncthreads();

    float acc[4][4];
#pragma unroll
    for (int nt = 0; nt < 4; nt++)
#pragma unroll
        for (int r = 0; r < 4; r++) acc[nt][r] = 0.0f;

    const float2* hb = hs + (size_t)b * 64 * HW;
    const int p = tid & 63;
    const int jp0 = tid >> 6;
    const int perm = (p & 7) * 8 + (p >> 3);

    auto gather = [&](int slab, int buf) {
        unsigned* bh = s_bhA + buf * 2304;
        unsigned* bl = s_blA + buf * 2304;
        int r = slab * 64 + p;              // slab == tap
        int2 ii = s_ii[r];
        float4 w4 = s_ww[r];
        const float2* xc = hb + (size_t)(jp0 * 2) * HW;   // channel c = jp*2
        int jp = jp0;
#pragma unroll
        for (int i = 0; i < 8; i++) {
            float2 a0 = __ldg(xc + ii.x), a1 = __ldg(xc + ii.y);
            float va = w4.x * a0.x + w4.y * a0.y + w4.z * a1.x + w4.w * a1.y;
            float2 b0 = __ldg(xc + HW + ii.x), b1 = __ldg(xc + HW + ii.y);
            float vb = w4.x * b0.x + w4.y * b0.y + w4.z * b1.x + w4.w * b1.y;
            __half vah = __float2half(va), vbh = __float2half(vb);
            __half val = __float2half(va - __half2float(vah));
            __half vbl = __float2half(vb - __half2float(vbh));
            bh[jp * 72 + perm] = pack_h2(vah, vbh);
            bl[jp * 72 + perm] = pack_h2(val, vbl);
            jp += 4;
            xc += 8 * HW;
        }
    };

    gather(0, 0);
    __syncthreads();

    for (int slab = 0; slab < 9; slab++) {
        if (slab < 8) gather(slab + 1, (slab + 1) & 1);
        const unsigned* sbh = s_bhA + (slab & 1) * 2304;
        const unsigned* sbl = s_blA + (slab & 1) * 2304;
#pragma unroll
        for (int kc = 0; kc < 4; kc++) {
            int kcg = slab * 4 + kc;
            uint4 Ah = __ldg((const uint4*)(Ahi + (((size_t)kcg * 4 + mt) * 32 + lane) * 4));
            uint4 Al = __ldg((const uint4*)(Alo + (((size_t)kcg * 4 + mt) * 32 + lane) * 4));
            int boff = (kc * 8 + (lane & 3)) * 72 + q * 8 + nh * 4;
            uint4 B0h = *(const uint4*)(sbh + boff);
            uint4 B1h = *(const uint4*)(sbh + boff + 4 * 72);
            uint4 B0l = *(const uint4*)(sbl + boff);
            uint4 B1l = *(const uint4*)(sbl + boff + 4 * 72);
            mma_f16(acc[0], Ah.x, Ah.y, Ah.z, Ah.w, B0h.x, B1h.x);
            mma_f16(acc[0], Ah.x, Ah.y, Ah.z, Ah.w, B0l.x, B1l.x);
            mma_f16(acc[0], Al.x, Al.y, Al.z, Al.w, B0h.x, B1h.x);
            mma_f16(acc[1], Ah.x, Ah.y, Ah.z, Ah.w, B0h.y, B1h.y);
            mma_f16(acc[1], Ah.x, Ah.y, Ah.z, Ah.w, B0l.y, B1l.y);
            mma_f16(acc[1], Al.x, Al.y, Al.z, Al.w, B0h.y, B1h.y);
            mma_f16(acc[2], Ah.x, Ah.y, Ah.z, Ah.w, B0h.z, B1h.z);
            mma_f16(acc[2], Ah.x, Ah.y, Ah.z, Ah.w, B0l.z, B1l.z);
            mma_f16(acc[2], Al.x, Al.y, Al.z, Al.w, B0h.z, B1h.z);
            mma_f16(acc[3], Ah.x, Ah.y, Ah.z, Ah.w, B0h.w, B1h.w);
            mma_f16(acc[3], Ah.x, Ah.y, Ah.z, Ah.w, B0l.w, B1l.w);
            mma_f16(acc[3], Al.x, Al.y, Al.z, Al.w, B0h.w, B1h.w);
        }
        __syncthreads();
    }

    int o = mt * 16 + (lane >> 2);
    int colb = tile * 64 + nh * 32 + (lane & 3) * 2;
    float* o0 = out + ((size_t)b * 64 + o) * HW + colb;
    float* o1 = o0 + 8 * HW;
#pragma unroll
    for (int nt = 0; nt < 4; nt++) {
        *reinterpret_cast<float2*>(o0 + nt * 8) = make_float2(acc[nt][0], acc[nt][1]);
        *reinterpret_cast<float2*>(o1 + nt * 8) = make_float2(acc[nt][2], acc[nt][3]);
    }
}

// ---------------- final modulated DCNv2: tap-major + shingled LDG.64 -----------------
// 36 slabs of 64 K; tap kk = slab>>2, channels (slab&3)*64 .. +64.
__global__ void __launch_bounds__(256)
dcn_final_f16(const float2* __restrict__ xs, const unsigned* __restrict__ Af,
              const float* __restrict__ offs, const float* __restrict__ msk,
              const float* __restrict__ bias, float* __restrict__ out) {
    __shared__ unsigned s_bA[2][32 * 72];
    __shared__ int2 s_ii[576];
    __shared__ float4 s_ww[576];

    const int b = blockIdx.y;
    const int tile = blockIdx.x;
    const int tid = threadIdx.x;
    const int warp = tid >> 5;
    const int lane = tid & 31;
    const int q = lane >> 2;

    for (int e = tid; e < 576; e += 256) {
        int k = e >> 6, p = e & 63;
        int pix = tile * 64 + p;
        float py = (float)(tile - 1 + k / 3) + offs[(size_t)b * 36 * HW + (2 * k) * HW + pix];
        float px = (float)(p - 1 + k % 3) + offs[(size_t)b * 36 * HW + (2 * k + 1) * HW + pix];
        float m = msk[(size_t)b * 9 * HW + k * HW + pix];
        float fy = floorf(py), fx = floorf(px);
        int iy = (int)fy, ix = (int)fx;
        float ay = py - fy, ax = px - fx;
        bool vy0 = (iy >= 0) && (iy < 64);
        bool vy1 = (iy >= -1) && (iy < 63);
        bool vx0 = (ix >= 0) && (ix < 64);
        bool vx1 = (ix >= -1) && (ix < 63);
        int cy0 = min(max(iy, 0), 63), cy1 = min(max(iy + 1, 0), 63);
        int cx0 = min(max(ix, 0), 63), cx1 = min(max(ix + 1, 0), 63);
        int xb = min(max(ix, 0), 62);
        float wAx = 0.0f, wBx = 0.0f;
        if (vx0) { if (cx0 == xb) wAx += 1.0f - ax; else wBx += 1.0f - ax; }
        if (vx1) { if (cx1 == xb) wAx += ax; else wBx += ax; }
        float w0 = vy0 ? (1.0f - ay) * m : 0.0f;
        float w1 = vy1 ? ay * m : 0.0f;
        s_ii[e] = make_int2(cy0 * 64 + xb, cy1 * 64 + xb);
        s_ww[e] = make_float4(w0 * wAx, w0 * wBx, w1 * wAx, w1 * wBx);
    }
    __syncthreads();

    float acc[2][8][4];
#pragma unroll
    for (int mtl = 0; mtl < 2; mtl++)
#pragma unroll
        for (int nt = 0; nt < 8; nt++)
#pragma unroll
            for (int r = 0; r < 4; r++) acc[mtl][nt][r] = 0.0f;

    const float2* xsb = xs + (size_t)b * 256 * HW;
    const int p = tid & 63;
    const int jp0 = tid >> 6;
    const int perm = (p & 7) * 8 + (p >> 3);

    auto gather = [&](int slab, int buf) {
        unsigned* bdst = s_bA[buf];
        int kk = slab >> 2;
        int r = kk * 64 + p;
        int2 ii = s_ii[r];
        float4 w4 = s_ww[r];
        const float2* xc = xsb + (size_t)((slab & 3) * 64 + jp0 * 2) * HW;
        int jp = jp0;
#pragma unroll
        for (int i = 0; i < 8; i++) {
            float2 a0 = __ldg(xc + ii.x), a1 = __ldg(xc + ii.y);
            float va = w4.x * a0.x + w4.y * a0.y + w4.z * a1.x + w4.w * a1.y;
            float2 b0 = __ldg(xc + HW + ii.x), b1 = __ldg(xc + HW + ii.y);
            float vb = w4.x * b0.x + w4.y * b0.y + w4.z * b1.x + w4.w * b1.y;
            bdst[jp * 72 + perm] = pack_h2(__float2half(va), __float2half(vb));
            jp += 4;
            xc += 8 * HW;
        }
    };

    gather(0, 0);
    __syncthreads();

    for (int slab = 0; slab < 36; slab++) {
        if (slab < 35) gather(slab + 1, (slab + 1) & 1);
        const unsigned* sb = s_bA[slab & 1];
#pragma unroll
        for (int kc = 0; kc < 4; kc++) {
            int kcg = slab * 4 + kc;
            const unsigned* ap = Af + (((size_t)kcg * 16 + warp * 2) * 32 + lane) * 4;
            uint4 A0 = __ldg((const uint4*)ap);
            uint4 A1 = __ldg((const uint4*)(ap + 128));

            int boff = (kc * 8 + (lane & 3)) * 72 + q * 8;
            uint4 B0a = *(const uint4*)(sb + boff);
            uint4 B0b = *(const uint4*)(sb + boff + 4);
            uint4 B1a = *(const uint4*)(sb + boff + 4 * 72);
            uint4 B1b = *(const uint4*)(sb + boff + 4 * 72 + 4);
            mma_f16(acc[0][0], A0.x, A0.y, A0.z, A0.w, B0a.x, B1a.x);
            mma_f16(acc[1][0], A1.x, A1.y, A1.z, A1.w, B0a.x, B1a.x);
            mma_f16(acc[0][1], A0.x, A0.y, A0.z, A0.w, B0a.y, B1a.y);
            mma_f16(acc[1][1], A1.x, A1.y, A1.z, A1.w, B0a.y, B1a.y);
            mma_f16(acc[0][2], A0.x, A0.y, A0.z, A0.w, B0a.z, B1a.z);
            mma_f16(acc[1][2], A1.x, A1.y, A1.z, A1.w, B0a.z, B1a.z);
            mma_f16(acc[0][3], A0.x, A0.y, A0.z, A0.w, B0a.w, B1a.w);
            mma_f16(acc[1][3], A1.x, A1.y, A1.z, A1.w, B0a.w, B1a.w);
            mma_f16(acc[0][4], A0.x, A0.y, A0.z, A0.w, B0b.x, B1b.x);
            mma_f16(acc[1][4], A1.x, A1.y, A1.z, A1.w, B0b.x, B1b.x);
            mma_f16(acc[0][5], A0.x, A0.y, A0.z, A0.w, B0b.y, B1b.y);
            mma_f16(acc[1][5], A1.x, A1.y, A1.z, A1.w, B0b.y, B1b.y);
            mma_f16(acc[0][6], A0.x, A0.y, A0.z, A0.w, B0b.z, B1b.z);
            mma_f16(acc[1][6], A1.x, A1.y, A1.z, A1.w, B0b.z, B1b.z);
            mma_f16(acc[0][7], A0.x, A0.y, A0.z, A0.w, B0b.w, B1b.w);
            mma_f16(acc[1][7], A1.x, A1.y, A1.z, A1.w, B0b.w, B1b.w);
        }
        __syncthreads();
    }

#pragma unroll
    for (int mtl = 0; mtl < 2; mtl++) {
        int o = warp * 32 + mtl * 16 + (lane >> 2);
        float b_lo = __ldg(bias + o);
        float b_hi = __ldg(bias + o + 8);
        float* o0 = out + ((size_t)b * 256 + o) * HW + tile * 64 + (lane & 3) * 2;
        float* o1 = o0 + 8 * HW;
#pragma unroll
        for (int nt = 0; nt < 8; nt++) {
            *reinterpret_cast<float2*>(o0 + nt * 8) =
                make_float2(acc[mtl][nt][0] + b_lo, acc[mtl][nt][1] + b_lo);
            *reinterpret_cast<float2*>(o1 + nt * 8) =
                make_float2(acc[mtl][nt][2] + b_hi, acc[mtl][nt][3] + b_hi);
        }
    }
}

// ---------------- host launcher ------------------------------------------------------
extern "C" void kernel_launch(void* const* d_in, const int* in_sizes, int n_in,
                              void* d_out, int out_size) {
    const float* x       = (const float*)d_in[0];
    const float* S       = (const float*)d_in[1];
    const float* sp_w1   = (const float*)d_in[2];
    const float* sp_b1   = (const float*)d_in[3];
    const float* sp_s1   = (const float*)d_in[4];
    const float* sp_o1   = (const float*)d_in[5];
    const float* sp_w2   = (const float*)d_in[6];
    const float* sp_b2   = (const float*)d_in[7];
    const float* sp_s2   = (const float*)d_in[8];
    const float* sp_o2   = (const float*)d_in[9];
    const float* sp_w3   = (const float*)d_in[10];
    const float* sp_b3   = (const float*)d_in[11];
    const float* sp_s3   = (const float*)d_in[12];
    const float* sp_o3   = (const float*)d_in[13];
    const float* off_w   = (const float*)d_in[14];
    const float* off_b   = (const float*)d_in[15];
    const float* dcoff_w = (const float*)d_in[16];
    const float* dcoff_b = (const float*)d_in[17];
    const float* dc_w    = (const float*)d_in[18];
    const float* m_w     = (const float*)d_in[19];
    const float* m_b     = (const float*)d_in[20];
    const float* weight  = (const float*)d_in[21];
    const float* bias    = (const float*)d_in[22];

    float *h1, *h2, *h3, *feat, *off, *mask, *b36;
    float2 *xs, *hs3;
    unsigned *Af, *Ah2, *Al2, *Ah3, *Al3, *Ahdc, *Aldc, *Ah36, *Al36;
    cudaGetSymbolAddress((void**)&h1,   g_h1);
    cudaGetSymbolAddress((void**)&h2,   g_h2);
    cudaGetSymbolAddress((void**)&h3,   g_h3);
    cudaGetSymbolAddress((void**)&feat, g_feat);
    cudaGetSymbolAddress((void**)&off,  g_off);
    cudaGetSymbolAddress((void**)&mask, g_mask);
    cudaGetSymbolAddress((void**)&b36,  g_b36);
    cudaGetSymbolAddress((void**)&xs,   g_xs);
    cudaGetSymbolAddress((void**)&hs3,  g_hs3);
    cudaGetSymbolAddress((void**)&Af,   g_Af);
    cudaGetSymbolAddress((void**)&Ah2,  g_Ah2);
    cudaGetSymbolAddress((void**)&Al2,  g_Al2);
    cudaGetSymbolAddress((void**)&Ah3,  g_Ah3);
    cudaGetSymbolAddress((void**)&Al3,  g_Al3);
    cudaGetSymbolAddress((void**)&Ahdc, g_Ahdc);
    cudaGetSymbolAddress((void**)&Aldc, g_Aldc);
    cudaGetSymbolAddress((void**)&Ah36, g_Ah36);
    cudaGetSymbolAddress((void**)&Al36, g_Al36);

    const int SMEM_SHIFT = 4 * 3456 * 4;   // 55296
    const int SMEM_MID   = 4 * 2304 * 4;   // 36864
    cudaFuncSetAttribute(conv_shift<1>,
                         cudaFuncAttributeMaxDynamicSharedMemorySize, SMEM_SHIFT);
    cudaFuncSetAttribute(conv_shift<2>,
                         cudaFuncAttributeMaxDynamicSharedMemorySize, SMEM_SHIFT);
    cudaFuncSetAttribute(dcn_mid,
                         cudaFuncAttributeMaxDynamicSharedMemorySize, SMEM_MID);

    auto tgrid = [](int n) { return (n + 255) / 256; };
    dim3 grid(64, BATCH);

    prep_shift_f16<<<tgrid(64 * 576), 256>>>(sp_w2, Ah2, Al2, 64);                // 0
    prep_shift_f16<<<tgrid(64 * 576), 256>>>(sp_w3, Ah3, Al3, 64);                // 1
    sp1_kernel<<<grid, 256>>>(S, sp_w1, sp_b1, sp_s1, sp_o1, h1);                 // 2
    conv_shift<1><<<grid, 256, SMEM_SHIFT>>>(h1, Ah2, Al2,
                                             sp_b2, sp_s2, sp_o2, h2, 64);        // 3 <- ncu
    conv_shift<1><<<grid, 256, SMEM_SHIFT>>>(h2, Ah3, Al3,
                                             sp_b3, sp_s3, sp_o3, h3, 64);        // 4
    shingle_k<<<tgrid(BATCH * 256 * HW), 256>>>(x, xs, BATCH * 256 * HW);         // 5
    prep_shift_w36<<<tgrid(64 * 576), 256>>>(off_w, dcoff_w, Ah36, Al36);         // 6
    concat_bias36<<<1, 36>>>(off_b, dcoff_b, b36);                                // 7
    prep_middc_tap<<<tgrid(64 * 576), 256>>>(dc_w, Ahdc, Aldc);                   // 8
    conv_shift<2><<<grid, 256, SMEM_SHIFT>>>(h3, Ah36, Al36,
                                             b36, nullptr, nullptr, off, 36);     // 9
    shingle_k<<<tgrid(BATCH * 64 * HW), 256>>>(h3, hs3, BATCH * 64 * HW);         // 10
    dcn_mid<<<grid, 256, SMEM_MID>>>(hs3, Ahdc, Aldc, off + 18 * HW, 36 * HW, feat); // 11
    mask_kernel<<<(BATCH * HW + 255) / 256, 256>>>(feat, m_w, m_b, mask);         // 12
    prep_final_f16<<<tgrid(256 * 2304), 256>>>(weight, Af);                       // 13
    dcn_final_f16<<<grid, 256>>>(xs, Af, off, mask, bias, (float*)d_out);         // 14
}

// round 10
// speedup vs baseline: 4.4885x; 1.0632x over previous
#include <cuda_runtime.h>
#include <cuda_fp16.h>
#include <math.h>
#include <stdint.h>

#define HW 4096     // 64*64
#define BATCH 8

// ---------------- scratch (static device globals; no allocation) ----------------
__device__ float g_h1  [BATCH*64*HW];
__device__ float g_h2  [BATCH*64*HW];
__device__ float g_h3  [BATCH*64*HW];
__device__ float g_feat[BATCH*64*HW];
__device__ float g_off [BATCH*36*HW];   // ch 0..17 = offset, 18..35 = dc_off
__device__ float g_mask[BATCH*9*HW];
__device__ float g_b36 [36];

// quad-shingled copies: q[pos] = (v[y][x], v[y][x+1], v[y+1][x], v[y+1][x+1])
__device__ float4 g_xq [BATCH*256*HW];  // 128MB
__device__ float4 g_hq3[BATCH*64*HW];   // 32MB

// f16 fragment-packed weights (each u32 = 2 f16 along K)
__device__ unsigned g_Af[144*16*32*4];
#define MIDA (36*4*32*4)
__device__ unsigned g_Ah2 [MIDA], g_Al2 [MIDA];   // shift-order
__device__ unsigned g_Ah3 [MIDA], g_Al3 [MIDA];   // shift-order
__device__ unsigned g_Ah36[MIDA], g_Al36[MIDA];   // shift-order
__device__ unsigned g_Ahdc[MIDA], g_Aldc[MIDA];   // tap-major (K=kk*64+c)

// ---------------- helpers ------------------------------------------------------------
__device__ __forceinline__ void mma_f16(float* acc, unsigned a0, unsigned a1,
                                        unsigned a2, unsigned a3,
                                        unsigned b0, unsigned b1) {
    asm volatile(
        "mma.sync.aligned.m16n8k16.row.col.f32.f16.f16.f32 "
        "{%0,%1,%2,%3}, {%4,%5,%6,%7}, {%8,%9}, {%0,%1,%2,%3};"
        : "+f"(acc[0]), "+f"(acc[1]), "+f"(acc[2]), "+f"(acc[3])
        : "r"(a0), "r"(a1), "r"(a2), "r"(a3), "r"(b0), "r"(b1));
}

__device__ __forceinline__ void frag_coords(int om, int kk, int& lane, int& reg, int& half) {
    int kpair = kk >> 1;
    half = kk & 1;
    lane = (om & 7) * 4 + (kpair & 3);
    reg = (om >> 3) + ((kpair >> 2) << 1);
}

__device__ __forceinline__ unsigned pack_h2(__half lo, __half hi) {
    return (unsigned)__half_as_ushort(lo) | ((unsigned)__half_as_ushort(hi) << 16);
}

__device__ __forceinline__ float dot4(float4 w, float4 q) {
    return w.x * q.x + w.y * q.y + w.z * q.z + w.w * q.w;
}

// ---------------- weight prep kernels -------------------------------------------------
// tap-major mid (for dcn_mid): Kn = kk*64 + c
__global__ void prep_middc_tap(const float* __restrict__ w, unsigned* __restrict__ hi,
                               unsigned* __restrict__ lo) {
    int i = blockIdx.x * blockDim.x + threadIdx.x;
    if (i >= 64 * 576) return;
    int K = i % 576;
    int o = i / 576;
    float v = w[o * 576 + K];
    __half vh = __float2half(v);
    __half vl = __float2half(v - __half2float(vh));
    int c = K / 9, kk = K - c * 9;
    int Kn = kk * 64 + c;
    int kc = Kn >> 4, kwi = Kn & 15;
    int lane, reg, half;
    frag_coords(o & 15, kwi, lane, reg, half);
    size_t base = ((((size_t)kc * 4 + (o >> 4)) * 32 + lane) * 4 + reg) * 2 + half;
    ((__half*)hi)[base] = vh;
    ((__half*)lo)[base] = vl;
}

// shift-order (for conv_shift)
__global__ void prep_shift_f16(const float* __restrict__ w, unsigned* __restrict__ hi,
                               unsigned* __restrict__ lo, int O) {
    int i = blockIdx.x * blockDim.x + threadIdx.x;
    if (i >= 64 * 576) return;
    int K = i % 576;
    int o = i / 576;
    float v = (o < O) ? w[o * 576 + K] : 0.0f;
    __half vh = __float2half(v);
    __half vl = __float2half(v - __half2float(vh));
    int c = K / 9, kk = K % 9;
    int slab = c >> 5, cl = c & 31;
    int kcg = (slab * 9 + kk) * 2 + (cl >> 4);
    int lane, reg, half;
    frag_coords(o & 15, cl & 15, lane, reg, half);
    size_t base = ((((size_t)kcg * 4 + (o >> 4)) * 32 + lane) * 4 + reg) * 2 + half;
    ((__half*)hi)[base] = vh;
    ((__half*)lo)[base] = vl;
}

__global__ void prep_shift_w36(const float* __restrict__ wa, const float* __restrict__ wb,
                               unsigned* __restrict__ hi, unsigned* __restrict__ lo) {
    int i = blockIdx.x * blockDim.x + threadIdx.x;
    if (i >= 64 * 576) return;
    int K = i % 576;
    int o = i / 576;
    float v = 0.0f;
    if (o < 18) v = wa[o * 576 + K];
    else if (o < 36) v = wb[(o - 18) * 576 + K];
    __half vh = __float2half(v);
    __half vl = __float2half(v - __half2float(vh));
    int c = K / 9, kk = K % 9;
    int slab = c >> 5, cl = c & 31;
    int kcg = (slab * 9 + kk) * 2 + (cl >> 4);
    int lane, reg, half;
    frag_coords(o & 15, cl & 15, lane, reg, half);
    size_t base = ((((size_t)kcg * 4 + (o >> 4)) * 32 + lane) * 4 + reg) * 2 + half;
    ((__half*)hi)[base] = vh;
    ((__half*)lo)[base] = vl;
}

// final: tap-major Kn = kk*256 + c
__global__ void prep_final_f16(const float* __restrict__ w, unsigned* __restrict__ dst) {
    int i = blockIdx.x * blockDim.x + threadIdx.x;
    if (i >= 256 * 2304) return;
    int K = i % 2304;
    int o = i / 2304;
    int c = K / 9, kk = K - c * 9;
    int Kn = kk * 256 + c;
    int kc = Kn >> 4, kwi = Kn & 15;
    int lane, reg, half;
    frag_coords(o & 15, kwi, lane, reg, half);
    size_t base = ((((size_t)kc * 16 + (o >> 4)) * 32 + lane) * 4 + reg) * 2 + half;
    ((__half*)dst)[base] = __float2half(w[i]);
}

__global__ void concat_bias36(const float* __restrict__ a, const float* __restrict__ b,
                              float* __restrict__ dst) {
    int i = threadIdx.x;
    if (i < 18) dst[i] = a[i];
    else if (i < 36) dst[i] = b[i - 18];
}

// ---------------- quad shingle: dst[pos] = 2x2 window starting at pos -----------------
__global__ void quad_k(const float* __restrict__ src, float4* __restrict__ dst,
                       int total) {
    int i = blockIdx.x * blockDim.x + threadIdx.x;
    if (i >= total) return;
    int xx = i & 63, yy = (i >> 6) & 63;
    float a = src[i];
    float b = (xx < 63) ? src[i + 1] : 0.0f;
    float c = (yy < 63) ? src[i + 64] : 0.0f;
    float d = (xx < 63 && yy < 63) ? src[i + 65] : 0.0f;
    dst[i] = make_float4(a, b, c, d);
}

// ---------------- 1x1 conv + sigmoid -------------------------------------------------
__global__ void mask_kernel(const float* __restrict__ feat, const float* __restrict__ mw,
                            const float* __restrict__ mb, float* __restrict__ mask) {
    int i = blockIdx.x * blockDim.x + threadIdx.x;
    if (i >= BATCH * HW) return;
    int b = i >> 12;
    int pix = i & (HW - 1);
    float acc[9];
#pragma unroll
    for (int o = 0; o < 9; o++) acc[o] = __ldg(mb + o);
    const float* fp = feat + (size_t)b * 64 * HW + pix;
    for (int c = 0; c < 64; c++) {
        float v = __ldg(fp + c * HW);
#pragma unroll
        for (int o = 0; o < 9; o++) acc[o] += v * __ldg(mw + o * 64 + c);
    }
#pragma unroll
    for (int o = 0; o < 9; o++)
        mask[((size_t)b * 9 + o) * HW + pix] = 1.0f / (1.0f + expf(-acc[o]));
}

// ---------------- sp1: fused resize + conv3x3 (CIN=3) + BN + ReLU, fp32 --------------
__device__ __forceinline__ float resize_at(const float* __restrict__ p, int y, int x) {
    const float scale = 127.0f / 63.0f;
    float ys = y * scale, xs = x * scale;
    float fy = floorf(ys), fx = floorf(xs);
    int y0 = (int)fy, x0 = (int)fx;
    int y1 = min(y0 + 1, 127), x1 = min(x0 + 1, 127);
    float wy = ys - fy, wx = xs - fx;
    return p[y0 * 128 + x0] * (1.0f - wy) * (1.0f - wx)
         + p[y0 * 128 + x1] * (1.0f - wy) * wx
         + p[y1 * 128 + x0] * wy * (1.0f - wx)
         + p[y1 * 128 + x1] * wy * wx;
}

__global__ void __launch_bounds__(256)
sp1_kernel(const float* __restrict__ S, const float* __restrict__ w1,
           const float* __restrict__ e_b, const float* __restrict__ e_s,
           const float* __restrict__ e_o, float* __restrict__ out) {
    __shared__ __align__(16) float s_t[576];
    const int b = blockIdx.y;
    const int tile = blockIdx.x;
    const int tid = threadIdx.x;
    const int o = tid & 63;
    const int pbase = (tid >> 6) * 16;

    float acc[16];
#pragma unroll
    for (int j = 0; j < 16; j++) acc[j] = 0.0f;

    for (int c = 0; c < 3; c++) {
        const float* Sc = S + (size_t)(b * 3 + c) * 128 * 128;
        for (int e = tid; e < 576; e += 256) {
            int k = e >> 6, p = e & 63;
            int yy = tile + k / 3 - 1;
            int xx = p + k % 3 - 1;
            s_t[e] = ((unsigned)yy < 64u && (unsigned)xx < 64u)
                         ? resize_at(Sc, yy, xx) : 0.0f;
        }
        __syncthreads();

        float wv[9];
#pragma unroll
        for (int k = 0; k < 9; k++) wv[k] = __ldg(w1 + o * 27 + c * 9 + k);

#pragma unroll
        for (int k = 0; k < 9; k++) {
            const float4* sp = reinterpret_cast<const float4*>(s_t + k * 64 + pbase);
#pragma unroll
            for (int j4 = 0; j4 < 4; j4++) {
                float4 sv = sp[j4];
                acc[j4 * 4 + 0] += wv[k] * sv.x;
                acc[j4 * 4 + 1] += wv[k] * sv.y;
                acc[j4 * 4 + 2] += wv[k] * sv.z;
                acc[j4 * 4 + 3] += wv[k] * sv.w;
            }
        }
        __syncthreads();
    }

    float bb = __ldg(e_b + o), ssc = __ldg(e_s + o), oof = __ldg(e_o + o);
    float* op = out + ((size_t)b * 64 + o) * HW + tile * 64 + pbase;
#pragma unroll
    for (int j = 0; j < 16; j++)
        op[j] = fmaxf((acc[j] + bb) * ssc + oof, 0.0f);
}

// ---------------- plain conv3x3 via shifted-window mma, double-buffered --------------
template <int EPI>
__global__ void __launch_bounds__(256)
conv_shift(const float* __restrict__ inp,
           const unsigned* __restrict__ Ahi, const unsigned* __restrict__ Alo,
           const float* __restrict__ e_b, const float* __restrict__ e_s,
           const float* __restrict__ e_o, float* __restrict__ out, int Oact) {
    extern __shared__ unsigned csm[];
    unsigned* s_bhA = csm;              // [2][3456]
    unsigned* s_blA = csm + 2 * 3456;   // [2][3456]

    const int b = blockIdx.y;
    const int tile = blockIdx.x;
    const int tid = threadIdx.x;
    const int warp = tid >> 5;
    const int lane = tid & 31;
    const int mt = warp >> 1;
    const int nh = warp & 1;

    float acc[4][4];
#pragma unroll
    for (int nt = 0; nt < 4; nt++)
#pragma unroll
        for (int r = 0; r < 4; r++) acc[nt][r] = 0.0f;

    const float* xb = inp + (size_t)b * 64 * HW;

    auto fill = [&](int slab, int buf) {
        unsigned* bh = s_bhA + buf * 3456;
        unsigned* bl = s_blA + buf * 3456;
        for (int e = tid; e < 3168; e += 256) {
            int r = e / 1056;
            int rem = e - r * 1056;
            int cp = rem / 66;
            int col = rem - cp * 66;
            int yy = tile - 1 + r;
            int px = col - 1;
            bool ok = ((unsigned)yy < 64u) && ((unsigned)px < 64u);
            const float* p0 = xb + (size_t)(slab * 32 + cp * 2) * HW + yy * 64 + px;
            float v0 = ok ? __ldg(p0) : 0.0f;
            float v1 = ok ? __ldg(p0 + HW) : 0.0f;
            __half h0 = __float2half(v0), h1 = __float2half(v1);
            __half l0 = __float2half(v0 - __half2float(h0));
            __half l1 = __float2half(v1 - __half2float(h1));
            int idx = (r * 16 + cp) * 72 + col;
            bh[idx] = pack_h2(h0, h1);
            bl[idx] = pack_h2(l0, l1);
        }
    };

    fill(0, 0);
    __syncthreads();

    for (int slab = 0; slab < 2; slab++) {
        if (slab == 0) fill(1, 1);
        const unsigned* sbh = s_bhA + slab * 3456;
        const unsigned* sbl = s_blA + slab * 3456;
#pragma unroll
        for (int t = 0; t < 9; t++) {
            const int dy = t / 3, dx = t % 3;
            const unsigned* rbh = sbh + dy * 16 * 72;
            const unsigned* rbl = sbl + dy * 16 * 72;
#pragma unroll
            for (int kcl = 0; kcl < 2; kcl++) {
                int kcg = (slab * 9 + t) * 2 + kcl;
                uint4 Ah = __ldg((const uint4*)(Ahi + (((size_t)kcg * 4 + mt) * 32 + lane) * 4));
                uint4 Al = __ldg((const uint4*)(Alo + (((size_t)kcg * 4 + mt) * 32 + lane) * 4));
                int boff = (kcl * 8 + (lane & 3)) * 72 + (lane >> 2) + nh * 32 + dx;
                const unsigned* bh = rbh + boff;
                const unsigned* bl = rbl + boff;
#pragma unroll
                for (int nt = 0; nt < 4; nt++) {
                    unsigned b0h = bh[nt * 8], b1h = bh[nt * 8 + 4 * 72];
                    unsigned b0l = bl[nt * 8], b1l = bl[nt * 8 + 4 * 72];
                    mma_f16(acc[nt], Ah.x, Ah.y, Ah.z, Ah.w, b0h, b1h);
                    mma_f16(acc[nt], Ah.x, Ah.y, Ah.z, Ah.w, b0l, b1l);
                    mma_f16(acc[nt], Al.x, Al.y, Al.z, Al.w, b0h, b1h);
                }
            }
        }
        __syncthreads();
    }

    int o = mt * 16 + (lane >> 2);
    float b0 = 0, s0 = 1, f0 = 0, b1 = 0, s1 = 1, f1 = 0;
    if (EPI == 1) {
        if (o < Oact)     { b0 = __ldg(e_b + o);     s0 = __ldg(e_s + o);     f0 = __ldg(e_o + o); }
        if (o + 8 < Oact) { b1 = __ldg(e_b + o + 8); s1 = __ldg(e_s + o + 8); f1 = __ldg(e_o + o + 8); }
    } else if (EPI == 2) {
        if (o < Oact)     b0 = __ldg(e_b + o);
        if (o + 8 < Oact) b1 = __ldg(e_b + o + 8);
    }
    int colb = tile * 64 + nh * 32 + (lane & 3) * 2;
    float* o0 = out + ((size_t)b * Oact + o) * HW + colb;
    float* o1 = o0 + 8 * HW;
#pragma unroll
    for (int nt = 0; nt < 4; nt++) {
        float v0a = acc[nt][0], v0b = acc[nt][1];
        float v1a = acc[nt][2], v1b = acc[nt][3];
        if (EPI == 1) {
            v0a = fmaxf((v0a + b0) * s0 + f0, 0.0f);
            v0b = fmaxf((v0b + b0) * s0 + f0, 0.0f);
            v1a = fmaxf((v1a + b1) * s1 + f1, 0.0f);
            v1b = fmaxf((v1b + b1) * s1 + f1, 0.0f);
        } else if (EPI == 2) {
            v0a += b0; v0b += b0; v1a += b1; v1b += b1;
        }
        if (o < Oact)
            *reinterpret_cast<float2*>(o0 + nt * 8) = make_float2(v0a, v0b);
        if (o + 8 < Oact)
            *reinterpret_cast<float2*>(o1 + nt * 8) = make_float2(v1a, v1b);
    }
}

// ---------------- deform table build (quad version): 1 int + 1 float4 ----------------
// MASKED: fold mask channel into weights.
template <bool MASKED>
__device__ __forceinline__ void build_tables(
    int tid, int tile, int b, const float* __restrict__ offs, int offBS,
    const float* __restrict__ msk, int* s_ii, float4* s_ww) {
    for (int e = tid; e < 576; e += 256) {
        int k = e >> 6, p = e & 63;
        int pix = tile * 64 + p;
        float py = (float)(tile - 1 + k / 3)
                 + offs[(size_t)b * offBS + (2 * k) * HW + pix];
        float px = (float)(p - 1 + k % 3)
                 + offs[(size_t)b * offBS + (2 * k + 1) * HW + pix];
        float m = MASKED ? msk[(size_t)b * 9 * HW + k * HW + pix] : 1.0f;
        float fy = floorf(py), fx = floorf(px);
        int iy = (int)fy, ix = (int)fx;
        float ay = py - fy, ax = px - fx;
        bool vy0 = (iy >= 0) && (iy < 64);
        bool vy1 = (iy >= -1) && (iy < 63);
        bool vx0 = (ix >= 0) && (ix < 64);
        bool vx1 = (ix >= -1) && (ix < 63);
        int yb = min(max(iy, 0), 62), xb = min(max(ix, 0), 62);
        float wAx = 0.0f, wBx = 0.0f;
        if (vx0) { if (min(max(ix, 0), 63) == xb) wAx += 1.0f - ax; else wBx += 1.0f - ax; }
        if (vx1) { if (min(max(ix + 1, 0), 63) == xb) wAx += ax; else wBx += ax; }
        float wy0 = 0.0f, wy1 = 0.0f;
        if (vy0) { if (min(max(iy, 0), 63) == yb) wy0 += 1.0f - ay; else wy1 += 1.0f - ay; }
        if (vy1) { if (min(max(iy + 1, 0), 63) == yb) wy0 += ay; else wy1 += ay; }
        wy0 *= m; wy1 *= m;
        s_ii[e] = yb * 64 + xb;
        s_ww[e] = make_float4(wy0 * wAx, wy0 * wBx, wy1 * wAx, wy1 * wBx);
    }
}

// ---------------- DCNv1 mid conv: quad gather + tap-major + permuted B ---------------
__global__ void __launch_bounds__(256)
dcn_mid(const float4* __restrict__ hq,
        const unsigned* __restrict__ Ahi, const unsigned* __restrict__ Alo,
        const float* __restrict__ offs, int offBS, float* __restrict__ out) {
    extern __shared__ unsigned msm[];
    unsigned* s_bhA = msm;               // [2][2304]
    unsigned* s_blA = msm + 2 * 2304;    // [2][2304]
    __shared__ int s_ii[576];
    __shared__ float4 s_ww[576];

    const int b = blockIdx.y;
    const int tile = blockIdx.x;
    const int tid = threadIdx.x;
    const int warp = tid >> 5;
    const int lane = tid & 31;
    const int mt = warp >> 1;
    const int nh = warp & 1;
    const int q = lane >> 2;

    build_tables<false>(tid, tile, b, offs, offBS, nullptr, s_ii, s_ww);
    __syncthreads();

    float acc[4][4];
#pragma unroll
    for (int nt = 0; nt < 4; nt++)
#pragma unroll
        for (int r = 0; r < 4; r++) acc[nt][r] = 0.0f;

    const float4* hb = hq + (size_t)b * 64 * HW;
    const int p = tid & 63;
    const int jp0 = tid >> 6;
    const int perm = (p & 7) * 8 + (p >> 3);

    auto gather = [&](int slab, int buf) {
        unsigned* bh = s_bhA + buf * 2304;
        unsigned* bl = s_blA + buf * 2304;
        int r = slab * 64 + p;              // slab == tap
        int ib = s_ii[r];
        float4 w4 = s_ww[r];
        const float4* xc = hb + (size_t)(jp0 * 2) * HW;
        int jp = jp0;
#pragma unroll
        for (int i = 0; i < 8; i++) {
            float va = dot4(w4, __ldg(xc + ib));
            float vb = dot4(w4, __ldg(xc + HW + ib));
            __half vah = __float2half(va), vbh = __float2half(vb);
            __half val = __float2half(va - __half2float(vah));
            __half vbl = __float2half(vb - __half2float(vbh));
            bh[jp * 72 + perm] = pack_h2(vah, vbh);
            bl[jp * 72 + perm] = pack_h2(val, vbl);
            jp += 4;
            xc += 8 * HW;
        }
    };

    gather(0, 0);
    __syncthreads();

    for (int slab = 0; slab < 9; slab++) {
        if (slab < 8) gather(slab + 1, (slab + 1) & 1);
        const unsigned* sbh = s_bhA + (slab & 1) * 2304;
        const unsigned* sbl = s_blA + (slab & 1) * 2304;
#pragma unroll
        for (int kc = 0; kc < 4; kc++) {
            int kcg = slab * 4 + kc;
            uint4 Ah = __ldg((const uint4*)(Ahi + (((size_t)kcg * 4 + mt) * 32 + lane) * 4));
            uint4 Al = __ldg((const uint4*)(Alo + (((size_t)kcg * 4 + mt) * 32 + lane) * 4));
            int boff = (kc * 8 + (lane & 3)) * 72 + q * 8 + nh * 4;
            uint4 B0h = *(const uint4*)(sbh + boff);
            uint4 B1h = *(const uint4*)(sbh + boff + 4 * 72);
            uint4 B0l = *(const uint4*)(sbl + boff);
            uint4 B1l = *(const uint4*)(sbl + boff + 4 * 72);
            mma_f16(acc[0], Ah.x, Ah.y, Ah.z, Ah.w, B0h.x, B1h.x);
            mma_f16(acc[0], Ah.x, Ah.y, Ah.z, Ah.w, B0l.x, B1l.x);
            mma_f16(acc[0], Al.x, Al.y, Al.z, Al.w, B0h.x, B1h.x);
            mma_f16(acc[1], Ah.x, Ah.y, Ah.z, Ah.w, B0h.y, B1h.y);
            mma_f16(acc[1], Ah.x, Ah.y, Ah.z, Ah.w, B0l.y, B1l.y);
            mma_f16(acc[1], Al.x, Al.y, Al.z, Al.w, B0h.y, B1h.y);
            mma_f16(acc[2], Ah.x, Ah.y, Ah.z, Ah.w, B0h.z, B1h.z);
            mma_f16(acc[2], Ah.x, Ah.y, Ah.z, Ah.w, B0l.z, B1l.z);
            mma_f16(acc[2], Al.x, Al.y, Al.z, Al.w, B0h.z, B1h.z);
            mma_f16(acc[3], Ah.x, Ah.y, Ah.z, Ah.w, B0h.w, B1h.w);
            mma_f16(acc[3], Ah.x, Ah.y, Ah.z, Ah.w, B0l.w, B1l.w);
            mma_f16(acc[3], Al.x, Al.y, Al.z, Al.w, B0h.w, B1h.w);
        }
        __syncthreads();
    }

    int o = mt * 16 + (lane >> 2);
    int colb = tile * 64 + nh * 32 + (lane & 3) * 2;
    float* o0 = out + ((size_t)b * 64 + o) * HW + colb;
    float* o1 = o0 + 8 * HW;
#pragma unroll
    for (int nt = 0; nt < 4; nt++) {
        *reinterpret_cast<float2*>(o0 + nt * 8) = make_float2(acc[nt][0], acc[nt][1]);
        *reinterpret_cast<float2*>(o1 + nt * 8) = make_float2(acc[nt][2], acc[nt][3]);
    }
}

// ---------------- final modulated DCNv2: quad gather + tap-major ---------------------
__global__ void __launch_bounds__(256)
dcn_final_f16(const float4* __restrict__ xq, const unsigned* __restrict__ Af,
              const float* __restrict__ offs, const float* __restrict__ msk,
              const float* __restrict__ bias, float* __restrict__ out) {
    __shared__ unsigned s_bA[2][32 * 72];
    __shared__ int s_ii[576];
    __shared__ float4 s_ww[576];

    const int b = blockIdx.y;
    const int tile = blockIdx.x;
    const int tid = threadIdx.x;
    const int warp = tid >> 5;
    const int lane = tid & 31;
    const int q = lane >> 2;

    build_tables<true>(tid, tile, b, offs, 36 * HW, msk, s_ii, s_ww);
    __syncthreads();

    float acc[2][8][4];
#pragma unroll
    for (int mtl = 0; mtl < 2; mtl++)
#pragma unroll
        for (int nt = 0; nt < 8; nt++)
#pragma unroll
            for (int r = 0; r < 4; r++) acc[mtl][nt][r] = 0.0f;

    const float4* xsb = xq + (size_t)b * 256 * HW;
    const int p = tid & 63;
    const int jp0 = tid >> 6;
    const int perm = (p & 7) * 8 + (p >> 3);

    auto gather = [&](int slab, int buf) {
        unsigned* bdst = s_bA[buf];
        int kk = slab >> 2;
        int r = kk * 64 + p;
        int ib = s_ii[r];
        float4 w4 = s_ww[r];
        const float4* xc = xsb + (size_t)((slab & 3) * 64 + jp0 * 2) * HW;
        int jp = jp0;
#pragma unroll
        for (int i = 0; i < 8; i++) {
            float va = dot4(w4, __ldg(xc + ib));
            float vb = dot4(w4, __ldg(xc + HW + ib));
            bdst[jp * 72 + perm] = pack_h2(__float2half(va), __float2half(vb));
            jp += 4;
            xc += 8 * HW;
        }
    };

    gather(0, 0);
    __syncthreads();

    for (int slab = 0; slab < 36; slab++) {
        if (slab < 35) gather(slab + 1, (slab + 1) & 1);
        const unsigned* sb = s_bA[slab & 1];
#pragma unroll
        for (int kc = 0; kc < 4; kc++) {
            int kcg = slab * 4 + kc;
            const unsigned* ap = Af + (((size_t)kcg * 16 + warp * 2) * 32 + lane) * 4;
            uint4 A0 = __ldg((const uint4*)ap);
            uint4 A1 = __ldg((const uint4*)(ap + 128));

            int boff = (kc * 8 + (lane & 3)) * 72 + q * 8;
            uint4 B0a = *(const uint4*)(sb + boff);
            uint4 B0b = *(const uint4*)(sb + boff + 4);
            uint4 B1a = *(const uint4*)(sb + boff + 4 * 72);
            uint4 B1b = *(const uint4*)(sb + boff + 4 * 72 + 4);
            mma_f16(acc[0][0], A0.x, A0.y, A0.z, A0.w, B0a.x, B1a.x);
            mma_f16(acc[1][0], A1.x, A1.y, A1.z, A1.w, B0a.x, B1a.x);
            mma_f16(acc[0][1], A0.x, A0.y, A0.z, A0.w, B0a.y, B1a.y);
            mma_f16(acc[1][1], A1.x, A1.y, A1.z, A1.w, B0a.y, B1a.y);
            mma_f16(acc[0][2], A0.x, A0.y, A0.z, A0.w, B0a.z, B1a.z);
            mma_f16(acc[1][2], A1.x, A1.y, A1.z, A1.w, B0a.z, B1a.z);
            mma_f16(acc[0][3], A0.x, A0.y, A0.z, A0.w, B0a.w, B1a.w);
            mma_f16(acc[1][3], A1.x, A1.y, A1.z, A1.w, B0a.w, B1a.w);
            mma_f16(acc[0][4], A0.x, A0.y, A0.z, A0.w, B0b.x, B1b.x);
            mma_f16(acc[1][4], A1.x, A1.y, A1.z, A1.w, B0b.x, B1b.x);
            mma_f16(acc[0][5], A0.x, A0.y, A0.z, A0.w, B0b.y, B1b.y);
            mma_f16(acc[1][5], A1.x, A1.y, A1.z, A1.w, B0b.y, B1b.y);
            mma_f16(acc[0][6], A0.x, A0.y, A0.z, A0.w, B0b.z, B1b.z);
            mma_f16(acc[1][6], A1.x, A1.y, A1.z, A1.w, B0b.z, B1b.z);
            mma_f16(acc[0][7], A0.x, A0.y, A0.z, A0.w, B0b.w, B1b.w);
            mma_f16(acc[1][7], A1.x, A1.y, A1.z, A1.w, B0b.w, B1b.w);
        }
        __syncthreads();
    }

#pragma unroll
    for (int mtl = 0; mtl < 2; mtl++) {
        int o = warp * 32 + mtl * 16 + (lane >> 2);
        float b_lo = __ldg(bias + o);
        float b_hi = __ldg(bias + o + 8);
        float* o0 = out + ((size_t)b * 256 + o) * HW + tile * 64 + (lane & 3) * 2;
        float* o1 = o0 + 8 * HW;
#pragma unroll
        for (int nt = 0; nt < 8; nt++) {
            *reinterpret_cast<float2*>(o0 + nt * 8) =
                make_float2(acc[mtl][nt][0] + b_lo, acc[mtl][nt][1] + b_lo);
            *reinterpret_cast<float2*>(o1 + nt * 8) =
                make_float2(acc[mtl][nt][2] + b_hi, acc[mtl][nt][3] + b_hi);
        }
    }
}

// ---------------- host launcher ------------------------------------------------------
extern "C" void kernel_launch(void* const* d_in, const int* in_sizes, int n_in,
                              void* d_out, int out_size) {
    const float* x       = (const float*)d_in[0];
    const float* S       = (const float*)d_in[1];
    const float* sp_w1   = (const float*)d_in[2];
    const float* sp_b1   = (const float*)d_in[3];
    const float* sp_s1   = (const float*)d_in[4];
    const float* sp_o1   = (const float*)d_in[5];
    const float* sp_w2   = (const float*)d_in[6];
    const float* sp_b2   = (const float*)d_in[7];
    const float* sp_s2   = (const float*)d_in[8];
    const float* sp_o2   = (const float*)d_in[9];
    const float* sp_w3   = (const float*)d_in[10];
    const float* sp_b3   = (const float*)d_in[11];
    const float* sp_s3   = (const float*)d_in[12];
    const float* sp_o3   = (const float*)d_in[13];
    const float* off_w   = (const float*)d_in[14];
    const float* off_b   = (const float*)d_in[15];
    const float* dcoff_w = (const float*)d_in[16];
    const float* dcoff_b = (const float*)d_in[17];
    const float* dc_w    = (const float*)d_in[18];
    const float* m_w     = (const float*)d_in[19];
    const float* m_b     = (const float*)d_in[20];
    const float* weight  = (const float*)d_in[21];
    const float* bias    = (const float*)d_in[22];

    float *h1, *h2, *h3, *feat, *off, *mask, *b36;
    float4 *xq, *hq3;
    unsigned *Af, *Ah2, *Al2, *Ah3, *Al3, *Ahdc, *Aldc, *Ah36, *Al36;
    cudaGetSymbolAddress((void**)&h1,   g_h1);
    cudaGetSymbolAddress((void**)&h2,   g_h2);
    cudaGetSymbolAddress((void**)&h3,   g_h3);
    cudaGetSymbolAddress((void**)&feat, g_feat);
    cudaGetSymbolAddress((void**)&off,  g_off);
    cudaGetSymbolAddress((void**)&mask, g_mask);
    cudaGetSymbolAddress((void**)&b36,  g_b36);
    cudaGetSymbolAddress((void**)&xq,   g_xq);
    cudaGetSymbolAddress((void**)&hq3,  g_hq3);
    cudaGetSymbolAddress((void**)&Af,   g_Af);
    cudaGetSymbolAddress((void**)&Ah2,  g_Ah2);
    cudaGetSymbolAddress((void**)&Al2,  g_Al2);
    cudaGetSymbolAddress((void**)&Ah3,  g_Ah3);
    cudaGetSymbolAddress((void**)&Al3,  g_Al3);
    cudaGetSymbolAddress((void**)&Ahdc, g_Ahdc);
    cudaGetSymbolAddress((void**)&Aldc, g_Aldc);
    cudaGetSymbolAddress((void**)&Ah36, g_Ah36);
    cudaGetSymbolAddress((void**)&Al36, g_Al36);

    const int SMEM_SHIFT = 4 * 3456 * 4;   // 55296
    const int SMEM_MID   = 4 * 2304 * 4;   // 36864
    cudaFuncSetAttribute(conv_shift<1>,
                         cudaFuncAttributeMaxDynamicSharedMemorySize, SMEM_SHIFT);
    cudaFuncSetAttribute(conv_shift<2>,
                         cudaFuncAttributeMaxDynamicSharedMemorySize, SMEM_SHIFT);
    cudaFuncSetAttribute(dcn_mid,
                         cudaFuncAttributeMaxDynamicSharedMemorySize, SMEM_MID);

    auto tgrid = [](int n) { return (n + 255) / 256; };
    dim3 grid(64, BATCH);

    prep_shift_f16<<<tgrid(64 * 576), 256>>>(sp_w2, Ah2, Al2, 64);                // 0
    prep_shift_f16<<<tgrid(64 * 576), 256>>>(sp_w3, Ah3, Al3, 64);                // 1
    sp1_kernel<<<grid, 256>>>(S, sp_w1, sp_b1, sp_s1, sp_o1, h1);                 // 2
    conv_shift<1><<<grid, 256, SMEM_SHIFT>>>(h1, Ah2, Al2,
                                             sp_b2, sp_s2, sp_o2, h2, 64);        // 3 <- ncu
    conv_shift<1><<<grid, 256, SMEM_SHIFT>>>(h2, Ah3, Al3,
                                             sp_b3, sp_s3, sp_o3, h3, 64);        // 4
    quad_k<<<tgrid(BATCH * 256 * HW), 256>>>(x, xq, BATCH * 256 * HW);            // 5
    prep_shift_w36<<<tgrid(64 * 576), 256>>>(off_w, dcoff_w, Ah36, Al36);         // 6
    concat_bias36<<<1, 36>>>(off_b, dcoff_b, b36);                                // 7
    prep_middc_tap<<<tgrid(64 * 576), 256>>>(dc_w, Ahdc, Aldc);                   // 8
    conv_shift<2><<<grid, 256, SMEM_SHIFT>>>(h3, Ah36, Al36,
                                             b36, nullptr, nullptr, off, 36);     // 9
    quad_k<<<tgrid(BATCH * 64 * HW), 256>>>(h3, hq3, BATCH * 64 * HW);            // 10
    dcn_mid<<<grid, 256, SMEM_MID>>>(hq3, Ahdc, Aldc, off + 18 * HW, 36 * HW, feat); // 11
    mask_kernel<<<(BATCH * HW + 255) / 256, 256>>>(feat, m_w, m_b, mask);         // 12
    prep_final_f16<<<tgrid(256 * 2304), 256>>>(weight, Af);                       // 13
    dcn_final_f16<<<grid, 256>>>(xq, Af, off, mask, bias, (float*)d_out);         // 14
}